// round 5
// baseline (speedup 1.0000x reference)
#include <cuda_runtime.h>
#include <cuda_bf16.h>
#include <cstdint>
#include <cstddef>

// ---------------- problem constants ----------------
#define T_SEQ 2048
#define DIM   2048
#define NH    16
#define HD    128
#define FFN   8192
#define EPS_F 1.1920929e-07f
#define NEG_INF_F (-1e30f)

// ---------------- scratch (device globals; no runtime allocs) ----------------
__device__ float g_xn  [(size_t)T_SEQ * DIM];
__device__ float g_qkv [(size_t)T_SEQ * 3 * DIM];
__device__ float g_krot[(size_t)T_SEQ * NH * HD];
__device__ float g_y   [(size_t)T_SEQ * DIM];
__device__ float g_x1  [(size_t)T_SEQ * DIM];
__device__ float g_h   [(size_t)T_SEQ * FFN];
__device__ float g_agate[(size_t)T_SEQ * NH];
__device__ float g_vgate[(size_t)T_SEQ * NH];
__device__ float g_wqkv[(size_t)4 * DIM * DIM];   // tf32-rounded qkvo weights
__device__ float g_wfc [(size_t)FFN * DIM];       // tf32-rounded c_fc
__device__ float g_wpT [(size_t)DIM * FFN];       // tf32-rounded c_proj^T [DIM, FFN]

// ---------------- helpers ----------------
__device__ __forceinline__ float to_tf32(float x) {
    asm("cvt.rna.tf32.f32 %0, %1;" : "=f"(x) : "f"(x));
    return x;
}
__device__ __forceinline__ void cp_async16(uint32_t dst, const float* src) {
    asm volatile("cp.async.cg.shared.global [%0], [%1], 16;" :: "r"(dst), "l"(src));
}
__device__ __forceinline__ void cp_async_commit() {
    asm volatile("cp.async.commit_group;" ::: "memory");
}
template<int N>
__device__ __forceinline__ void cp_async_wait() {
    asm volatile("cp.async.wait_group %0;" :: "n"(N) : "memory");
}
__device__ __forceinline__ uint32_t smem_u32(const void* p) {
    uint32_t a;
    asm("{ .reg .u64 t; cvta.to.shared.u64 t, %1; cvt.u32.u64 %0, t; }" : "=r"(a) : "l"(p));
    return a;
}
__device__ __forceinline__ void mma_tf32(float& c0, float& c1, float& c2, float& c3,
                                         uint32_t a0, uint32_t a1, uint32_t a2, uint32_t a3,
                                         uint32_t b0, uint32_t b1) {
    asm volatile("mma.sync.aligned.m16n8k8.row.col.f32.tf32.tf32.f32 "
                 "{%0,%1,%2,%3}, {%4,%5,%6,%7}, {%8,%9}, {%0,%1,%2,%3};"
                 : "+f"(c0), "+f"(c1), "+f"(c2), "+f"(c3)
                 : "r"(a0), "r"(a1), "r"(a2), "r"(a3), "r"(b0), "r"(b1));
}

// ================= warp-MMA tf32 GEMM =================
// C[M,N] = epi(alpha * A[M,K] @ B[N,K]^T)
// BM=256 BN=256 BK=32, 512 threads (16 warps, 4x4 of 64x64 warp tiles), 3-stage cp.async.
#define GBM 256
#define GBN 256
#define GBK 32
#define GSTAGES 3
#define ROWF 36                               // padded row length in floats (144 B)
#define A_STAGE_F (GBM * ROWF)                // 9216 floats
#define B_STAGE_F (GBN * ROWF)                // 9216 floats
#define STAGE_F   (A_STAGE_F + B_STAGE_F)     // 18432 floats
#define GEMM_SMEM (GSTAGES * STAGE_F * 4)     // 221184 bytes

// EPI: 0=none, 1=relu^2 + tf32 round, 2=add residual
template<int EPI>
__global__ void __launch_bounds__(512, 1)
tf32_gemm_kernel(const float* __restrict__ A, const float* __restrict__ B,
                 float* __restrict__ C, const float* __restrict__ addsrc,
                 const float* __restrict__ alpha_ptr, int alpha_idx,
                 int N, int K)
{
    extern __shared__ float smf[];
    const int tid = threadIdx.x;
    const int wid = tid >> 5, lane = tid & 31;
    const int g = lane >> 2, tig = lane & 3;
    const int wm = (wid & 3) * 64, wn = (wid >> 2) * 64;
    const int bn = blockIdx.x, bm = blockIdx.y;
    const int nk = K / GBK;
    const uint32_t sb = smem_u32(smf);

    const float* Agm = A + (size_t)bm * GBM * K;
    const float* Bgm = B + (size_t)bn * GBN * K;

    auto load_tile = [&](int stage, int ktile) {
        uint32_t sa = sb + stage * (STAGE_F * 4);
        uint32_t sB = sa + A_STAGE_F * 4;
        int kt = ktile * GBK;
        #pragma unroll
        for (int i = 0; i < 4; i++) {                 // A: 2048 chunks of 16B
            int c = tid + i * 512;
            int row = c >> 3, co = (c & 7) * 4;
            cp_async16(sa + (uint32_t)row * 144 + (co << 2),
                       Agm + (size_t)row * K + kt + co);
        }
        #pragma unroll
        for (int i = 0; i < 4; i++) {                 // B: 2048 chunks
            int c = tid + i * 512;
            int row = c >> 3, co = (c & 7) * 4;
            cp_async16(sB + (uint32_t)row * 144 + (co << 2),
                       Bgm + (size_t)row * K + kt + co);
        }
    };

    float acc[4][8][4];
    #pragma unroll
    for (int mt = 0; mt < 4; mt++)
        #pragma unroll
        for (int nt = 0; nt < 8; nt++)
            #pragma unroll
            for (int q = 0; q < 4; q++) acc[mt][nt][q] = 0.f;

    #pragma unroll
    for (int s = 0; s < GSTAGES - 1; s++) { load_tile(s, s); cp_async_commit(); }

    for (int k = 0; k < nk; k++) {
        cp_async_wait<GSTAGES - 2>();
        __syncthreads();
        const float* As = smf + (k % GSTAGES) * STAGE_F;
        const float* Bs = As + A_STAGE_F;
        #pragma unroll
        for (int ks = 0; ks < 4; ks++) {
            const int k0 = ks * 8;
            uint32_t a[4][4];
            #pragma unroll
            for (int mt = 0; mt < 4; mt++) {
                int m = wm + mt * 16 + g;
                a[mt][0] = __float_as_uint(As[(size_t)m * ROWF + k0 + tig]);
                a[mt][1] = __float_as_uint(As[(size_t)(m + 8) * ROWF + k0 + tig]);
                a[mt][2] = __float_as_uint(As[(size_t)m * ROWF + k0 + tig + 4]);
                a[mt][3] = __float_as_uint(As[(size_t)(m + 8) * ROWF + k0 + tig + 4]);
            }
            #pragma unroll
            for (int nt = 0; nt < 8; nt++) {
                int n = wn + nt * 8 + g;
                uint32_t b0 = __float_as_uint(Bs[(size_t)n * ROWF + k0 + tig]);
                uint32_t b1 = __float_as_uint(Bs[(size_t)n * ROWF + k0 + tig + 4]);
                #pragma unroll
                for (int mt = 0; mt < 4; mt++)
                    mma_tf32(acc[mt][nt][0], acc[mt][nt][1], acc[mt][nt][2], acc[mt][nt][3],
                             a[mt][0], a[mt][1], a[mt][2], a[mt][3], b0, b1);
            }
        }
        __syncthreads();
        if (k + GSTAGES - 1 < nk) load_tile((k + GSTAGES - 1) % GSTAGES, k + GSTAGES - 1);
        cp_async_commit();
    }

    float alpha = alpha_ptr ? alpha_ptr[alpha_idx] : 1.0f;
    #pragma unroll
    for (int mt = 0; mt < 4; mt++) {
        #pragma unroll
        for (int half = 0; half < 2; half++) {
            int row = bm * GBM + wm + mt * 16 + g + half * 8;
            #pragma unroll
            for (int nt = 0; nt < 8; nt++) {
                int col = bn * GBN + wn + nt * 8 + tig * 2;
                float2 v;
                v.x = acc[mt][nt][half * 2 + 0] * alpha;
                v.y = acc[mt][nt][half * 2 + 1] * alpha;
                size_t idx = (size_t)row * N + col;
                if (EPI == 1) {
                    v.x = fmaxf(v.x, 0.f); v.x = to_tf32(v.x * v.x);
                    v.y = fmaxf(v.y, 0.f); v.y = to_tf32(v.y * v.y);
                } else if (EPI == 2) {
                    float2 a2 = *(const float2*)&addsrc[idx];
                    v.x += a2.x; v.y += a2.y;
                }
                *(float2*)&C[idx] = v;
            }
        }
    }
}

// ---------------- weight conversion kernels ----------------
__global__ void __launch_bounds__(256) round_tf32_kernel(const float* __restrict__ in,
                                                         float* __restrict__ outp, int n4) {
    int i = blockIdx.x * 256 + threadIdx.x;
    if (i < n4) {
        float4 v = ((const float4*)in)[i];
        v.x = to_tf32(v.x); v.y = to_tf32(v.y); v.z = to_tf32(v.z); v.w = to_tf32(v.w);
        ((float4*)outp)[i] = v;
    }
}
__global__ void __launch_bounds__(256) transpose_round_kernel(const float* __restrict__ in,
                                                              float* __restrict__ outp) {
    __shared__ float t[32][33];
    int bx = blockIdx.x;   // over DIM/32
    int by = blockIdx.y;   // over FFN/32
    int x = threadIdx.x, y = threadIdx.y;    // 32 x 8
    #pragma unroll
    for (int i = 0; i < 32; i += 8)
        t[y + i][x] = in[(size_t)(by * 32 + y + i) * DIM + bx * 32 + x];
    __syncthreads();
    #pragma unroll
    for (int i = 0; i < 32; i += 8)
        outp[(size_t)(bx * 32 + y + i) * FFN + by * 32 + x] = to_tf32(t[x][y + i]);
}

// ---------------- RMSNorm (tf32-rounded output) ----------------
__global__ void __launch_bounds__(256) rmsnorm_kernel(const float* __restrict__ in,
                                                      float* __restrict__ outp) {
    int t = blockIdx.x;
    const float* r = in + (size_t)t * DIM;
    float ss = 0.f;
    for (int i = threadIdx.x; i < DIM; i += 256) { float v = r[i]; ss += v * v; }
    __shared__ float sred[8];
    for (int o = 16; o; o >>= 1) ss += __shfl_xor_sync(0xffffffffu, ss, o);
    if ((threadIdx.x & 31) == 0) sred[threadIdx.x >> 5] = ss;
    __syncthreads();
    float tot = 0.f;
    #pragma unroll
    for (int i = 0; i < 8; i++) tot += sred[i];
    float scale = rsqrtf(tot / (float)DIM + EPS_F);
    for (int i = threadIdx.x; i < DIM; i += 256)
        outp[(size_t)t * DIM + i] = to_tf32(r[i] * scale);
}

// ---------------- per-(t, head-slot) QK rmsnorm + rotary (tf32-rounded out) ----------------
__global__ void __launch_bounds__(128) qkrot_kernel(
    float* __restrict__ qkv, float* __restrict__ krot,
    const float* __restrict__ cosb, const float* __restrict__ sinb)
{
    int hs = blockIdx.x;
    int t  = blockIdx.y;
    int d  = threadIdx.x;
    float v = qkv[((size_t)t * 48 + hs) * HD + d];
    __shared__ float sm[HD];
    __shared__ float red[4];
    float ss = v * v;
    for (int o = 16; o; o >>= 1) ss += __shfl_xor_sync(0xffffffffu, ss, o);
    if ((d & 31) == 0) red[d >> 5] = ss;
    __syncthreads();
    float tot = red[0] + red[1] + red[2] + red[3];
    float n = v * rsqrtf(tot / (float)HD + EPS_F);
    sm[d] = n;
    __syncthreads();
    float o;
    if (d < 64) {
        float c = cosb[t * 64 + d], s = sinb[t * 64 + d];
        o = sm[d] * c + sm[d + 64] * s;
    } else {
        float c = cosb[t * 64 + d - 64], s = sinb[t * 64 + d - 64];
        o = -sm[d - 64] * s + sm[d] * c;
    }
    o = to_tf32(o);
    if (hs < 16) qkv[((size_t)t * 48 + hs) * HD + d] = o;
    else         krot[((size_t)t * NH + (hs - 16)) * HD + d] = o;
}

// ---------------- key-offset shift ----------------
__global__ void __launch_bounds__(256) kshift_kernel(
    const float* __restrict__ krot, float* __restrict__ qkv,
    const int* __restrict__ key_offset)
{
    int idx = blockIdx.x * 256 + threadIdx.x;
    int d = idx & 127;
    int h = (idx >> 7) & 15;
    int t = idx >> 11;
    int ko = key_offset[0];
    bool up = (d >= 32 && d < 64) || (d >= 96);
    int st = (ko && up && t > 0) ? (t - 1) : t;
    qkv[((size_t)t * 48 + 16 + h) * HD + d] = krot[((size_t)st * NH + h) * HD + d];
}

// ---------------- gate logits ----------------
__global__ void __launch_bounds__(256) gates_kernel(
    const float* __restrict__ xn, const float* __restrict__ agw,
    const float* __restrict__ vgw, float* __restrict__ agate,
    float* __restrict__ vgate)
{
    int t = blockIdx.x;
    int w = threadIdx.x >> 5, lane = threadIdx.x & 31;
    const float* xr = xn + (size_t)t * DIM;
    float acc[4] = {};
    const float* wbase[4];
    #pragma unroll
    for (int q = 0; q < 4; q++) {
        int o = w * 4 + q;
        wbase[q] = (o < 16) ? (agw + (size_t)o * DIM) : (vgw + (size_t)(o - 16) * DIM);
    }
    for (int dd = lane; dd < DIM; dd += 32) {
        float xv = xr[dd];
        #pragma unroll
        for (int q = 0; q < 4; q++) acc[q] = fmaf(xv, wbase[q][dd], acc[q]);
    }
    #pragma unroll
    for (int q = 0; q < 4; q++)
        for (int o2 = 16; o2; o2 >>= 1) acc[q] += __shfl_xor_sync(0xffffffffu, acc[q], o2);
    if (lane == 0) {
        #pragma unroll
        for (int q = 0; q < 4; q++) {
            int o = w * 4 + q;
            float g = 1.f / (1.f + expf(-acc[q]));
            if (o < 16) agate[t * NH + o] = g;
            else        vgate[t * NH + (o - 16)] = g;
        }
    }
}

// ---------------- v = round_tf32(v + ve_gate * ve) ----------------
__global__ void __launch_bounds__(256) vupdate_kernel(
    float* __restrict__ qkv, const float* __restrict__ ve,
    const float* __restrict__ vgate)
{
    int idx = blockIdx.x * 256 + threadIdx.x;
    int d = idx & 127;
    int h = (idx >> 7) & 15;
    int t = idx >> 11;
    float g = vgate[t * NH + h];
    size_t o = ((size_t)t * 48 + 32 + h) * HD + d;
    qkv[o] = to_tf32(qkv[o] + g * ve[idx]);
}

// ================= MMA flash attention (tf32) =================
// 64 q-rows x 64 k-cols per tile, 4 warps (each warp: 16 q-rows).
// Doc-block tile skip: docs sorted, so skip tile if docs[kbase+63] < docs[qbase].
#define ROWP 132
#define FL_SMEM ((3 * 64 * ROWP + 64) * 4)

__global__ void __launch_bounds__(128) flash_mma_kernel(
    const float* __restrict__ qkv, const int* __restrict__ docs,
    const float* __restrict__ attn_scale, const float* __restrict__ agate,
    float* __restrict__ y)
{
    extern __shared__ float fs[];
    float* Qs = fs;
    float* Ks = fs + 64 * ROWP;
    float* Vs = fs + 2 * 64 * ROWP;
    int*   kd = (int*)(fs + 3 * 64 * ROWP);

    const int tid = threadIdx.x, wid = tid >> 5, lane = tid & 31;
    const int g = lane >> 2, tig = lane & 3;
    const int h = blockIdx.y;
    const int qi = (int)gridDim.x - 1 - (int)blockIdx.x;   // heavy tiles launch first
    const int qbase = qi * 64;
    const float scale = attn_scale[0];

    #pragma unroll
    for (int i = 0; i < 16; i++) {
        int c = tid + i * 128;
        int r = c >> 5, co = (c & 31) * 4;
        float4 f = *(const float4*)&qkv[((size_t)(qbase + r) * 48 + h) * HD + co];
        *(float4*)&Qs[r * ROWP + co] = f;
    }
    const int rg0 = qbase + wid * 16 + g;
    const int rg1 = rg0 + 8;
    const int qd0 = docs[rg0], qd1 = docs[rg1];
    const int qdmin = docs[qbase];

    float o[16][4] = {};
    float m0 = NEG_INF_F, m1 = NEG_INF_F, l0 = 0.f, l1 = 0.f;
    __syncthreads();

    for (int kb = 0; kb <= qi; kb++) {
        const int kbase = kb * 64;
        if (docs[kbase + 63] < qdmin) continue;     // doc-block skip (uniform)
        __syncthreads();
        #pragma unroll
        for (int i = 0; i < 16; i++) {
            int c = tid + i * 128;
            int r = c >> 5, co = (c & 31) * 4;
            float4 f = *(const float4*)&qkv[((size_t)(kbase + r) * 48 + 16 + h) * HD + co];
            *(float4*)&Ks[r * ROWP + co] = f;
            float4 v4 = *(const float4*)&qkv[((size_t)(kbase + r) * 48 + 32 + h) * HD + co];
            *(float4*)&Vs[r * ROWP + co] = v4;
        }
        if (tid < 64) kd[tid] = docs[kbase + tid];
        __syncthreads();

        float s[8][4] = {};
        #pragma unroll
        for (int ks = 0; ks < 16; ks++) {
            const int k0 = ks * 8;
            uint32_t a0 = __float_as_uint(Qs[(wid * 16 + g) * ROWP + k0 + tig]);
            uint32_t a1 = __float_as_uint(Qs[(wid * 16 + g + 8) * ROWP + k0 + tig]);
            uint32_t a2 = __float_as_uint(Qs[(wid * 16 + g) * ROWP + k0 + tig + 4]);
            uint32_t a3 = __float_as_uint(Qs[(wid * 16 + g + 8) * ROWP + k0 + tig + 4]);
            #pragma unroll
            for (int nt = 0; nt < 8; nt++) {
                uint32_t b0 = __float_as_uint(Ks[(nt * 8 + g) * ROWP + k0 + tig]);
                uint32_t b1 = __float_as_uint(Ks[(nt * 8 + g) * ROWP + k0 + tig + 4]);
                mma_tf32(s[nt][0], s[nt][1], s[nt][2], s[nt][3], a0, a1, a2, a3, b0, b1);
            }
        }

        float mx0 = m0, mx1 = m1;
        #pragma unroll
        for (int nt = 0; nt < 8; nt++) {
            int c0i = kbase + nt * 8 + 2 * tig;
            int d0 = kd[nt * 8 + 2 * tig], d1 = kd[nt * 8 + 2 * tig + 1];
            float v00 = (c0i     <= rg0 && d0 == qd0) ? s[nt][0] * scale : NEG_INF_F;
            float v01 = (c0i + 1 <= rg0 && d1 == qd0) ? s[nt][1] * scale : NEG_INF_F;
            float v10 = (c0i     <= rg1 && d0 == qd1) ? s[nt][2] * scale : NEG_INF_F;
            float v11 = (c0i + 1 <= rg1 && d1 == qd1) ? s[nt][3] * scale : NEG_INF_F;
            s[nt][0] = v00; s[nt][1] = v01; s[nt][2] = v10; s[nt][3] = v11;
            mx0 = fmaxf(mx0, fmaxf(v00, v01));
            mx1 = fmaxf(mx1, fmaxf(v10, v11));
        }
        mx0 = fmaxf(mx0, __shfl_xor_sync(0xffffffffu, mx0, 1));
        mx0 = fmaxf(mx0, __shfl_xor_sync(0xffffffffu, mx0, 2));
        mx1 = fmaxf(mx1, __shfl_xor_sync(0xffffffffu, mx1, 1));
        mx1 = fmaxf(mx1, __shfl_xor_sync(0xffffffffu, mx1, 2));
        float al0 = __expf(m0 - mx0), al1 = __expf(m1 - mx1);
        m0 = mx0; m1 = mx1;

        float sum0 = 0.f, sum1 = 0.f;
        #pragma unroll
        for (int nt = 0; nt < 8; nt++) {
            float p00 = __expf(s[nt][0] - m0);
            float p01 = __expf(s[nt][1] - m0);
            float p10 = __expf(s[nt][2] - m1);
            float p11 = __expf(s[nt][3] - m1);
            sum0 += p00 + p01; sum1 += p10 + p11;
            s[nt][0] = to_tf32(p00); s[nt][1] = to_tf32(p01);
            s[nt][2] = to_tf32(p10); s[nt][3] = to_tf32(p11);
        }
        sum0 += __shfl_xor_sync(0xffffffffu, sum0, 1);
        sum0 += __shfl_xor_sync(0xffffffffu, sum0, 2);
        sum1 += __shfl_xor_sync(0xffffffffu, sum1, 1);
        sum1 += __shfl_xor_sync(0xffffffffu, sum1, 2);
        l0 = l0 * al0 + sum0;
        l1 = l1 * al1 + sum1;
        #pragma unroll
        for (int nt = 0; nt < 16; nt++) {
            o[nt][0] *= al0; o[nt][1] *= al0;
            o[nt][2] *= al1; o[nt][3] *= al1;
        }

        #pragma unroll
        for (int kc = 0; kc < 8; kc++) {
            int src = (g << 2) | (tig >> 1);
            float x0 = __shfl_sync(0xffffffffu, s[kc][0], src);
            float x1 = __shfl_sync(0xffffffffu, s[kc][1], src);
            float x2 = __shfl_sync(0xffffffffu, s[kc][2], src);
            float x3 = __shfl_sync(0xffffffffu, s[kc][3], src);
            float z0 = __shfl_sync(0xffffffffu, s[kc][0], src + 2);
            float z1 = __shfl_sync(0xffffffffu, s[kc][1], src + 2);
            float z2 = __shfl_sync(0xffffffffu, s[kc][2], src + 2);
            float z3 = __shfl_sync(0xffffffffu, s[kc][3], src + 2);
            bool odd = (tig & 1) != 0;
            uint32_t a0 = __float_as_uint(odd ? x1 : x0);
            uint32_t a1 = __float_as_uint(odd ? x3 : x2);
            uint32_t a2 = __float_as_uint(odd ? z1 : z0);
            uint32_t a3 = __float_as_uint(odd ? z3 : z2);
            #pragma unroll
            for (int nt = 0; nt < 16; nt++) {
                uint32_t b0 = __float_as_uint(Vs[(kc * 8 + tig) * ROWP + nt * 8 + g]);
                uint32_t b1 = __float_as_uint(Vs[(kc * 8 + tig + 4) * ROWP + nt * 8 + g]);
                mma_tf32(o[nt][0], o[nt][1], o[nt][2], o[nt][3], a0, a1, a2, a3, b0, b1);
            }
        }
    }

    float f0 = (1.f / l0) * agate[rg0 * NH + h];
    float f1 = (1.f / l1) * agate[rg1 * NH + h];
    #pragma unroll
    for (int nt = 0; nt < 16; nt++) {
        float2 w0, w1;
        w0.x = to_tf32(o[nt][0] * f0); w0.y = to_tf32(o[nt][1] * f0);
        w1.x = to_tf32(o[nt][2] * f1); w1.y = to_tf32(o[nt][3] * f1);
        *(float2*)&y[(size_t)rg0 * DIM + h * HD + nt * 8 + 2 * tig] = w0;
        *(float2*)&y[(size_t)rg1 * DIM + h * HD + nt * 8 + 2 * tig] = w1;
    }
}

// ---------------- launch ----------------
extern "C" void kernel_launch(void* const* d_in, const int* in_sizes, int n_in,
                              void* d_out, int out_size) {
    const float* x           = (const float*)d_in[0];
    const float* ve          = (const float*)d_in[1];
    const float* qkvo_w      = (const float*)d_in[2];
    const float* attn_gate_w = (const float*)d_in[3];
    const float* ve_gate_w   = (const float*)d_in[4];
    const float* c_fc        = (const float*)d_in[5];
    const float* c_proj      = (const float*)d_in[6];
    const float* sa_lambdas  = (const float*)d_in[7];
    const float* cosb        = (const float*)d_in[8];
    const float* sinb        = (const float*)d_in[9];
    const float* attn_scale  = (const float*)d_in[10];
    const int*   docs        = (const int*)d_in[11];
    const int*   key_offset  = (const int*)d_in[12];
    float*       out         = (float*)d_out;

    float *xn, *qkv, *krot, *y, *x1, *hbuf, *agate, *vgate, *wqkv, *wfc, *wpT;
    cudaGetSymbolAddress((void**)&xn,    g_xn);
    cudaGetSymbolAddress((void**)&qkv,   g_qkv);
    cudaGetSymbolAddress((void**)&krot,  g_krot);
    cudaGetSymbolAddress((void**)&y,     g_y);
    cudaGetSymbolAddress((void**)&x1,    g_x1);
    cudaGetSymbolAddress((void**)&hbuf,  g_h);
    cudaGetSymbolAddress((void**)&agate, g_agate);
    cudaGetSymbolAddress((void**)&vgate, g_vgate);
    cudaGetSymbolAddress((void**)&wqkv,  g_wqkv);
    cudaGetSymbolAddress((void**)&wfc,   g_wfc);
    cudaGetSymbolAddress((void**)&wpT,   g_wpT);

    cudaFuncSetAttribute(flash_mma_kernel, cudaFuncAttributeMaxDynamicSharedMemorySize,
                         FL_SMEM);
    cudaFuncSetAttribute(tf32_gemm_kernel<0>, cudaFuncAttributeMaxDynamicSharedMemorySize,
                         GEMM_SMEM);
    cudaFuncSetAttribute(tf32_gemm_kernel<1>, cudaFuncAttributeMaxDynamicSharedMemorySize,
                         GEMM_SMEM);
    cudaFuncSetAttribute(tf32_gemm_kernel<2>, cudaFuncAttributeMaxDynamicSharedMemorySize,
                         GEMM_SMEM);

    // weight conversions (rounded tf32 copies; c_proj also transposed to [N,K])
    round_tf32_kernel<<<(4 * DIM * DIM / 4 + 255) / 256, 256>>>(qkvo_w, wqkv, 4 * DIM * DIM / 4);
    round_tf32_kernel<<<((size_t)FFN * DIM / 4 + 255) / 256, 256>>>(c_fc, wfc, FFN * DIM / 4);
    transpose_round_kernel<<<dim3(DIM / 32, FFN / 32), dim3(32, 8)>>>(c_proj, wpT);

    // 1. xn = round_tf32(rmsnorm(x))
    rmsnorm_kernel<<<T_SEQ, 256>>>(x, xn);
    // 2. qkv = lam0 * xn @ Wqkv^T
    tf32_gemm_kernel<0><<<dim3(3 * DIM / GBN, T_SEQ / GBM), 512, GEMM_SMEM>>>(
        xn, wqkv, qkv, nullptr, sa_lambdas, 0, 3 * DIM, DIM);
    // 3. per-head rmsnorm + rotary (tf32-rounded)
    qkrot_kernel<<<dim3(32, T_SEQ), 128>>>(qkv, krot, cosb, sinb);
    // 4. key-offset shift
    kshift_kernel<<<(T_SEQ * NH * HD) / 256, 256>>>(krot, qkv, key_offset);
    // 5. gates
    gates_kernel<<<T_SEQ, 256>>>(xn, attn_gate_w, ve_gate_w, agate, vgate);
    // 6. v update (tf32-rounded)
    vupdate_kernel<<<(T_SEQ * DIM) / 256, 256>>>(qkv, ve, vgate);
    // 7. MMA flash attention with doc-block skip
    flash_mma_kernel<<<dim3(T_SEQ / 64, NH), 128, FL_SMEM>>>(
        qkv, docs, attn_scale, agate, y);
    // 8. x1 = x + lam1 * y @ Wo^T
    tf32_gemm_kernel<2><<<dim3(DIM / GBN, T_SEQ / GBM), 512, GEMM_SMEM>>>(
        y, wqkv + (size_t)3 * DIM * DIM, x1, x, sa_lambdas, 1, DIM, DIM);
    // 9. xn = round_tf32(rmsnorm(x1))
    rmsnorm_kernel<<<T_SEQ, 256>>>(x1, xn);
    // 10. h = round_tf32(relu(xn @ c_fc^T)^2)
    tf32_gemm_kernel<1><<<dim3(FFN / GBN, T_SEQ / GBM), 512, GEMM_SMEM>>>(
        xn, wfc, hbuf, nullptr, nullptr, 0, FFN, DIM);
    // 11. out = x1 + h @ c_proj   (via c_proj^T, K=8192)
    tf32_gemm_kernel<2><<<dim3(DIM / GBN, T_SEQ / GBM), 512, GEMM_SMEM>>>(
        hbuf, wpT, out, x1, nullptr, 0, DIM, FFN);
}

// round 6
// speedup vs baseline: 7.3163x; 7.3163x over previous
#include <cuda_runtime.h>
#include <cuda_fp16.h>
#include <cstdint>
#include <cstddef>

// ---------------- problem constants ----------------
#define T_SEQ 2048
#define DIM   2048
#define NH    16
#define HD    128
#define FFN   8192
#define EPS_F 1.1920929e-07f
#define NEG_INF_F (-1e30f)

// ---------------- scratch (device globals; no runtime allocs) ----------------
__device__ __half g_xn  [(size_t)T_SEQ * DIM];     // fp16 rmsnorm output
__device__ float  g_qkv [(size_t)T_SEQ * 3 * DIM]; // [T, 48, 128] fp32
__device__ float  g_krot[(size_t)T_SEQ * NH * HD];
__device__ __half g_y   [(size_t)T_SEQ * DIM];     // fp16 attention output
__device__ float  g_x1  [(size_t)T_SEQ * DIM];
__device__ __half g_h   [(size_t)T_SEQ * FFN];     // fp16 MLP hidden
__device__ float  g_agate[(size_t)T_SEQ * NH];
__device__ float  g_vgate[(size_t)T_SEQ * NH];
__device__ __half g_wqkv[(size_t)4 * DIM * DIM];   // fp16 qkvo weights
__device__ __half g_wfc [(size_t)FFN * DIM];       // fp16 c_fc
__device__ __half g_wpT [(size_t)DIM * FFN];       // fp16 c_proj^T [DIM, FFN]

// ---------------- helpers ----------------
__device__ __forceinline__ float to_tf32(float x) {
    asm("cvt.rna.tf32.f32 %0, %1;" : "=f"(x) : "f"(x));
    return x;
}
__device__ __forceinline__ void cp_async16(uint32_t dst, const void* src) {
    asm volatile("cp.async.cg.shared.global [%0], [%1], 16;" :: "r"(dst), "l"(src));
}
__device__ __forceinline__ void cp_async_commit() {
    asm volatile("cp.async.commit_group;" ::: "memory");
}
template<int N>
__device__ __forceinline__ void cp_async_wait() {
    asm volatile("cp.async.wait_group %0;" :: "n"(N) : "memory");
}
__device__ __forceinline__ uint32_t smem_u32(const void* p) {
    uint32_t a;
    asm("{ .reg .u64 t; cvta.to.shared.u64 t, %1; cvt.u32.u64 %0, t; }" : "=r"(a) : "l"(p));
    return a;
}
__device__ __forceinline__ void ldsm_x4(uint32_t& r0, uint32_t& r1, uint32_t& r2, uint32_t& r3,
                                        uint32_t addr) {
    asm volatile("ldmatrix.sync.aligned.m8n8.x4.shared.b16 {%0,%1,%2,%3}, [%4];"
                 : "=r"(r0), "=r"(r1), "=r"(r2), "=r"(r3) : "r"(addr));
}
__device__ __forceinline__ void mma_f16(float& c0, float& c1, float& c2, float& c3,
                                        uint32_t a0, uint32_t a1, uint32_t a2, uint32_t a3,
                                        uint32_t b0, uint32_t b1) {
    asm volatile("mma.sync.aligned.m16n8k16.row.col.f32.f16.f16.f32 "
                 "{%0,%1,%2,%3}, {%4,%5,%6,%7}, {%8,%9}, {%0,%1,%2,%3};"
                 : "+f"(c0), "+f"(c1), "+f"(c2), "+f"(c3)
                 : "r"(a0), "r"(a1), "r"(a2), "r"(a3), "r"(b0), "r"(b1));
}
__device__ __forceinline__ void mma_tf32(float& c0, float& c1, float& c2, float& c3,
                                         uint32_t a0, uint32_t a1, uint32_t a2, uint32_t a3,
                                         uint32_t b0, uint32_t b1) {
    asm volatile("mma.sync.aligned.m16n8k8.row.col.f32.tf32.tf32.f32 "
                 "{%0,%1,%2,%3}, {%4,%5,%6,%7}, {%8,%9}, {%0,%1,%2,%3};"
                 : "+f"(c0), "+f"(c1), "+f"(c2), "+f"(c3)
                 : "r"(a0), "r"(a1), "r"(a2), "r"(a3), "r"(b0), "r"(b1));
}

// ================= fp16 warp-MMA GEMM =================
// C[M,N] = epi(alpha * A[M,K] @ B[N,K]^T), A/B fp16, accumulate fp32.
// BM=256 BN=128 BK=64, 256 threads (8 warps, 4x2 of 64x64 warp tiles), 3-stage cp.async.
#define GBM 256
#define GBN 128
#define GBK 64
#define GSTAGES 3
#define ROWH 72                               // halfs per smem row (144 B)
#define A_STAGE_B (GBM * ROWH * 2)            // 36864 bytes
#define B_STAGE_B (GBN * ROWH * 2)            // 18432 bytes
#define STAGE_B   (A_STAGE_B + B_STAGE_B)     // 55296 bytes
#define GEMM_SMEM (GSTAGES * STAGE_B)         // 165888 bytes

// EPI: 0=none->float, 1=relu^2->half, 2=add residual->float
template<int EPI>
__global__ void __launch_bounds__(256, 1)
f16_gemm_kernel(const __half* __restrict__ A, const __half* __restrict__ B,
                void* __restrict__ Cv, const float* __restrict__ addsrc,
                const float* __restrict__ alpha_ptr, int alpha_idx,
                int N, int K)
{
    extern __shared__ char smc[];
    const int tid = threadIdx.x;
    const int wid = tid >> 5, lane = tid & 31;
    const int g = lane >> 2, tig = lane & 3;
    const int wm = (wid & 3) * 64, wn = (wid >> 2) * 64;
    const int bn = blockIdx.x, bm = blockIdx.y;
    const int nk = K / GBK;
    const uint32_t sb = smem_u32(smc);

    const __half* Agm = A + (size_t)bm * GBM * K;
    const __half* Bgm = B + (size_t)bn * GBN * K;

    auto load_tile = [&](int stage, int ktile) {
        uint32_t sa = sb + stage * STAGE_B;
        uint32_t sB = sa + A_STAGE_B;
        int kt = ktile * GBK;
        #pragma unroll
        for (int i = 0; i < 8; i++) {                 // A: 256 rows x 8 chunks
            int c = tid + i * 256;
            int row = c >> 3, ch = c & 7;
            cp_async16(sa + (uint32_t)row * 144 + ch * 16,
                       Agm + (size_t)row * K + kt + ch * 8);
        }
        #pragma unroll
        for (int i = 0; i < 4; i++) {                 // B: 128 rows x 8 chunks
            int c = tid + i * 256;
            int row = c >> 3, ch = c & 7;
            cp_async16(sB + (uint32_t)row * 144 + ch * 16,
                       Bgm + (size_t)row * K + kt + ch * 8);
        }
    };

    // per-thread ldmatrix byte offsets (within a stage)
    uint32_t aoff[4], boff[4];
    #pragma unroll
    for (int mt = 0; mt < 4; mt++)
        aoff[mt] = (uint32_t)(wm + mt * 16 + (lane & 7) + ((lane >> 3) & 1) * 8) * 144
                 + ((lane >> 4) & 1) * 16;
    #pragma unroll
    for (int nb = 0; nb < 4; nb++)
        boff[nb] = (uint32_t)(wn + nb * 16 + (lane & 7) + ((lane >> 4) & 1) * 8) * 144
                 + ((lane >> 3) & 1) * 16;

    float acc[4][8][4];
    #pragma unroll
    for (int mt = 0; mt < 4; mt++)
        #pragma unroll
        for (int nt = 0; nt < 8; nt++)
            #pragma unroll
            for (int q = 0; q < 4; q++) acc[mt][nt][q] = 0.f;

    #pragma unroll
    for (int s = 0; s < GSTAGES - 1; s++) { load_tile(s, s); cp_async_commit(); }

    for (int k = 0; k < nk; k++) {
        cp_async_wait<GSTAGES - 2>();
        __syncthreads();
        uint32_t sa = sb + (k % GSTAGES) * STAGE_B;
        uint32_t sB = sa + A_STAGE_B;
        #pragma unroll
        for (int ks = 0; ks < 4; ks++) {              // 4 x k16 = BK 64
            const uint32_t kb = ks * 32;              // 16 halfs = 32 bytes
            uint32_t a[4][4];
            #pragma unroll
            for (int mt = 0; mt < 4; mt++)
                ldsm_x4(a[mt][0], a[mt][1], a[mt][2], a[mt][3], sa + aoff[mt] + kb);
            #pragma unroll
            for (int nb = 0; nb < 4; nb++) {
                uint32_t b0, b1, b2, b3;
                ldsm_x4(b0, b1, b2, b3, sB + boff[nb] + kb);
                #pragma unroll
                for (int mt = 0; mt < 4; mt++) {
                    mma_f16(acc[mt][2 * nb][0], acc[mt][2 * nb][1],
                            acc[mt][2 * nb][2], acc[mt][2 * nb][3],
                            a[mt][0], a[mt][1], a[mt][2], a[mt][3], b0, b1);
                    mma_f16(acc[mt][2 * nb + 1][0], acc[mt][2 * nb + 1][1],
                            acc[mt][2 * nb + 1][2], acc[mt][2 * nb + 1][3],
                            a[mt][0], a[mt][1], a[mt][2], a[mt][3], b2, b3);
                }
            }
        }
        __syncthreads();
        if (k + GSTAGES - 1 < nk) load_tile((k + GSTAGES - 1) % GSTAGES, k + GSTAGES - 1);
        cp_async_commit();
    }

    float alpha = alpha_ptr ? alpha_ptr[alpha_idx] : 1.0f;
    #pragma unroll
    for (int mt = 0; mt < 4; mt++) {
        #pragma unroll
        for (int half_i = 0; half_i < 2; half_i++) {
            int row = bm * GBM + wm + mt * 16 + g + half_i * 8;
            #pragma unroll
            for (int nt = 0; nt < 8; nt++) {
                int col = bn * GBN + wn + nt * 8 + tig * 2;
                float vx = acc[mt][nt][half_i * 2 + 0] * alpha;
                float vy = acc[mt][nt][half_i * 2 + 1] * alpha;
                size_t idx = (size_t)row * N + col;
                if (EPI == 1) {
                    vx = fmaxf(vx, 0.f); vx = vx * vx;
                    vy = fmaxf(vy, 0.f); vy = vy * vy;
                    *(__half2*)((__half*)Cv + idx) = __floats2half2_rn(vx, vy);
                } else if (EPI == 2) {
                    float2 a2 = *(const float2*)&addsrc[idx];
                    float2 v; v.x = vx + a2.x; v.y = vy + a2.y;
                    *(float2*)((float*)Cv + idx) = v;
                } else {
                    float2 v; v.x = vx; v.y = vy;
                    *(float2*)((float*)Cv + idx) = v;
                }
            }
        }
    }
}

// ---------------- weight conversion kernels ----------------
__global__ void __launch_bounds__(256) round_f16_kernel(const float* __restrict__ in,
                                                        __half* __restrict__ outp, int n8) {
    int i = blockIdx.x * 256 + threadIdx.x;
    if (i < n8) {
        float4 v0 = ((const float4*)in)[2 * i];
        float4 v1 = ((const float4*)in)[2 * i + 1];
        __half2 h0 = __floats2half2_rn(v0.x, v0.y);
        __half2 h1 = __floats2half2_rn(v0.z, v0.w);
        __half2 h2 = __floats2half2_rn(v1.x, v1.y);
        __half2 h3 = __floats2half2_rn(v1.z, v1.w);
        uint4 o;
        o.x = *(uint32_t*)&h0; o.y = *(uint32_t*)&h1;
        o.z = *(uint32_t*)&h2; o.w = *(uint32_t*)&h3;
        ((uint4*)outp)[i] = o;
    }
}
// out[DIM, FFN] (fp16) = in[FFN, DIM]^T
__global__ void __launch_bounds__(256) transpose_f16_kernel(const float* __restrict__ in,
                                                            __half* __restrict__ outp) {
    __shared__ float t[32][33];
    int bx = blockIdx.x;   // over DIM/32
    int by = blockIdx.y;   // over FFN/32
    int x = threadIdx.x, y = threadIdx.y;    // 32 x 8
    #pragma unroll
    for (int i = 0; i < 32; i += 8)
        t[y + i][x] = in[(size_t)(by * 32 + y + i) * DIM + bx * 32 + x];
    __syncthreads();
    #pragma unroll
    for (int i = 0; i < 32; i += 8)
        outp[(size_t)(bx * 32 + y + i) * FFN + by * 32 + x] = __float2half_rn(t[x][y + i]);
}

// ---------------- RMSNorm (fp16 output) ----------------
__global__ void __launch_bounds__(256) rmsnorm_kernel(const float* __restrict__ in,
                                                      __half* __restrict__ outp) {
    int t = blockIdx.x;
    const float* r = in + (size_t)t * DIM;
    float ss = 0.f;
    float vals[8];
    #pragma unroll
    for (int j = 0; j < 8; j++) {
        float v = r[threadIdx.x + j * 256];
        vals[j] = v; ss += v * v;
    }
    __shared__ float sred[8];
    for (int o = 16; o; o >>= 1) ss += __shfl_xor_sync(0xffffffffu, ss, o);
    if ((threadIdx.x & 31) == 0) sred[threadIdx.x >> 5] = ss;
    __syncthreads();
    float tot = 0.f;
    #pragma unroll
    for (int i = 0; i < 8; i++) tot += sred[i];
    float scale = rsqrtf(tot / (float)DIM + EPS_F);
    #pragma unroll
    for (int j = 0; j < 8; j++)
        outp[(size_t)t * DIM + threadIdx.x + j * 256] = __float2half_rn(vals[j] * scale);
}

// ---------------- per-(t, head-slot) QK rmsnorm + rotary (tf32-rounded out) ----------------
__global__ void __launch_bounds__(128) qkrot_kernel(
    float* __restrict__ qkv, float* __restrict__ krot,
    const float* __restrict__ cosb, const float* __restrict__ sinb)
{
    int hs = blockIdx.x;
    int t  = blockIdx.y;
    int d  = threadIdx.x;
    float v = qkv[((size_t)t * 48 + hs) * HD + d];
    __shared__ float sm[HD];
    __shared__ float red[4];
    float ss = v * v;
    for (int o = 16; o; o >>= 1) ss += __shfl_xor_sync(0xffffffffu, ss, o);
    if ((d & 31) == 0) red[d >> 5] = ss;
    __syncthreads();
    float tot = red[0] + red[1] + red[2] + red[3];
    float n = v * rsqrtf(tot / (float)HD + EPS_F);
    sm[d] = n;
    __syncthreads();
    float o;
    if (d < 64) {
        float c = cosb[t * 64 + d], s = sinb[t * 64 + d];
        o = sm[d] * c + sm[d + 64] * s;
    } else {
        float c = cosb[t * 64 + d - 64], s = sinb[t * 64 + d - 64];
        o = -sm[d - 64] * s + sm[d] * c;
    }
    o = to_tf32(o);
    if (hs < 16) qkv[((size_t)t * 48 + hs) * HD + d] = o;
    else         krot[((size_t)t * NH + (hs - 16)) * HD + d] = o;
}

// ---------------- key-offset shift ----------------
__global__ void __launch_bounds__(256) kshift_kernel(
    const float* __restrict__ krot, float* __restrict__ qkv,
    const int* __restrict__ key_offset)
{
    int idx = blockIdx.x * 256 + threadIdx.x;
    int d = idx & 127;
    int h = (idx >> 7) & 15;
    int t = idx >> 11;
    int ko = key_offset[0];
    bool up = (d >= 32 && d < 64) || (d >= 96);
    int st = (ko && up && t > 0) ? (t - 1) : t;
    qkv[((size_t)t * 48 + 16 + h) * HD + d] = krot[((size_t)st * NH + h) * HD + d];
}

// ---------------- gate logits (xn is fp16) ----------------
__global__ void __launch_bounds__(256) gates_kernel(
    const __half* __restrict__ xn, const float* __restrict__ agw,
    const float* __restrict__ vgw, float* __restrict__ agate,
    float* __restrict__ vgate)
{
    int t = blockIdx.x;
    int w = threadIdx.x >> 5, lane = threadIdx.x & 31;
    const __half* xr = xn + (size_t)t * DIM;
    float acc[4] = {};
    const float* wbase[4];
    #pragma unroll
    for (int q = 0; q < 4; q++) {
        int o = w * 4 + q;
        wbase[q] = (o < 16) ? (agw + (size_t)o * DIM) : (vgw + (size_t)(o - 16) * DIM);
    }
    for (int dd = lane; dd < DIM; dd += 32) {
        float xv = __half2float(xr[dd]);
        #pragma unroll
        for (int q = 0; q < 4; q++) acc[q] = fmaf(xv, wbase[q][dd], acc[q]);
    }
    #pragma unroll
    for (int q = 0; q < 4; q++)
        for (int o2 = 16; o2; o2 >>= 1) acc[q] += __shfl_xor_sync(0xffffffffu, acc[q], o2);
    if (lane == 0) {
        #pragma unroll
        for (int q = 0; q < 4; q++) {
            int o = w * 4 + q;
            float g = 1.f / (1.f + expf(-acc[q]));
            if (o < 16) agate[t * NH + o] = g;
            else        vgate[t * NH + (o - 16)] = g;
        }
    }
}

// ---------------- v = round_tf32(v + ve_gate * ve) ----------------
__global__ void __launch_bounds__(256) vupdate_kernel(
    float* __restrict__ qkv, const float* __restrict__ ve,
    const float* __restrict__ vgate)
{
    int idx = blockIdx.x * 256 + threadIdx.x;
    int d = idx & 127;
    int h = (idx >> 7) & 15;
    int t = idx >> 11;
    float g = vgate[t * NH + h];
    size_t o = ((size_t)t * 48 + 32 + h) * HD + d;
    qkv[o] = to_tf32(qkv[o] + g * ve[idx]);
}

// ================= MMA flash attention (tf32, fp16 y output) =================
#define ROWP 132
#define FL_SMEM ((3 * 64 * ROWP + 64) * 4)

__global__ void __launch_bounds__(128) flash_mma_kernel(
    const float* __restrict__ qkv, const int* __restrict__ docs,
    const float* __restrict__ attn_scale, const float* __restrict__ agate,
    __half* __restrict__ y)
{
    extern __shared__ float fs[];
    float* Qs = fs;
    float* Ks = fs + 64 * ROWP;
    float* Vs = fs + 2 * 64 * ROWP;
    int*   kd = (int*)(fs + 3 * 64 * ROWP);

    const int tid = threadIdx.x, wid = tid >> 5, lane = tid & 31;
    const int g = lane >> 2, tig = lane & 3;
    const int h = blockIdx.y;
    const int qi = (int)gridDim.x - 1 - (int)blockIdx.x;
    const int qbase = qi * 64;
    const float scale = attn_scale[0];

    #pragma unroll
    for (int i = 0; i < 16; i++) {
        int c = tid + i * 128;
        int r = c >> 5, co = (c & 31) * 4;
        float4 f = *(const float4*)&qkv[((size_t)(qbase + r) * 48 + h) * HD + co];
        *(float4*)&Qs[r * ROWP + co] = f;
    }
    const int rg0 = qbase + wid * 16 + g;
    const int rg1 = rg0 + 8;
    const int qd0 = docs[rg0], qd1 = docs[rg1];
    const int qdmin = docs[qbase];

    float o[16][4] = {};
    float m0 = NEG_INF_F, m1 = NEG_INF_F, l0 = 0.f, l1 = 0.f;
    __syncthreads();

    for (int kb = 0; kb <= qi; kb++) {
        const int kbase = kb * 64;
        if (docs[kbase + 63] < qdmin) continue;
        __syncthreads();
        #pragma unroll
        for (int i = 0; i < 16; i++) {
            int c = tid + i * 128;
            int r = c >> 5, co = (c & 31) * 4;
            float4 f = *(const float4*)&qkv[((size_t)(kbase + r) * 48 + 16 + h) * HD + co];
            *(float4*)&Ks[r * ROWP + co] = f;
            float4 v4 = *(const float4*)&qkv[((size_t)(kbase + r) * 48 + 32 + h) * HD + co];
            *(float4*)&Vs[r * ROWP + co] = v4;
        }
        if (tid < 64) kd[tid] = docs[kbase + tid];
        __syncthreads();

        float s[8][4] = {};
        #pragma unroll
        for (int ks = 0; ks < 16; ks++) {
            const int k0 = ks * 8;
            uint32_t a0 = __float_as_uint(Qs[(wid * 16 + g) * ROWP + k0 + tig]);
            uint32_t a1 = __float_as_uint(Qs[(wid * 16 + g + 8) * ROWP + k0 + tig]);
            uint32_t a2 = __float_as_uint(Qs[(wid * 16 + g) * ROWP + k0 + tig + 4]);
            uint32_t a3 = __float_as_uint(Qs[(wid * 16 + g + 8) * ROWP + k0 + tig + 4]);
            #pragma unroll
            for (int nt = 0; nt < 8; nt++) {
                uint32_t b0 = __float_as_uint(Ks[(nt * 8 + g) * ROWP + k0 + tig]);
                uint32_t b1 = __float_as_uint(Ks[(nt * 8 + g) * ROWP + k0 + tig + 4]);
                mma_tf32(s[nt][0], s[nt][1], s[nt][2], s[nt][3], a0, a1, a2, a3, b0, b1);
            }
        }

        float mx0 = m0, mx1 = m1;
        #pragma unroll
        for (int nt = 0; nt < 8; nt++) {
            int c0i = kbase + nt * 8 + 2 * tig;
            int d0 = kd[nt * 8 + 2 * tig], d1 = kd[nt * 8 + 2 * tig + 1];
            float v00 = (c0i     <= rg0 && d0 == qd0) ? s[nt][0] * scale : NEG_INF_F;
            float v01 = (c0i + 1 <= rg0 && d1 == qd0) ? s[nt][1] * scale : NEG_INF_F;
            float v10 = (c0i     <= rg1 && d0 == qd1) ? s[nt][2] * scale : NEG_INF_F;
            float v11 = (c0i + 1 <= rg1 && d1 == qd1) ? s[nt][3] * scale : NEG_INF_F;
            s[nt][0] = v00; s[nt][1] = v01; s[nt][2] = v10; s[nt][3] = v11;
            mx0 = fmaxf(mx0, fmaxf(v00, v01));
            mx1 = fmaxf(mx1, fmaxf(v10, v11));
        }
        mx0 = fmaxf(mx0, __shfl_xor_sync(0xffffffffu, mx0, 1));
        mx0 = fmaxf(mx0, __shfl_xor_sync(0xffffffffu, mx0, 2));
        mx1 = fmaxf(mx1, __shfl_xor_sync(0xffffffffu, mx1, 1));
        mx1 = fmaxf(mx1, __shfl_xor_sync(0xffffffffu, mx1, 2));
        float al0 = __expf(m0 - mx0), al1 = __expf(m1 - mx1);
        m0 = mx0; m1 = mx1;

        float sum0 = 0.f, sum1 = 0.f;
        #pragma unroll
        for (int nt = 0; nt < 8; nt++) {
            float p00 = __expf(s[nt][0] - m0);
            float p01 = __expf(s[nt][1] - m0);
            float p10 = __expf(s[nt][2] - m1);
            float p11 = __expf(s[nt][3] - m1);
            sum0 += p00 + p01; sum1 += p10 + p11;
            s[nt][0] = to_tf32(p00); s[nt][1] = to_tf32(p01);
            s[nt][2] = to_tf32(p10); s[nt][3] = to_tf32(p11);
        }
        sum0 += __shfl_xor_sync(0xffffffffu, sum0, 1);
        sum0 += __shfl_xor_sync(0xffffffffu, sum0, 2);
        sum1 += __shfl_xor_sync(0xffffffffu, sum1, 1);
        sum1 += __shfl_xor_sync(0xffffffffu, sum1, 2);
        l0 = l0 * al0 + sum0;
        l1 = l1 * al1 + sum1;
        #pragma unroll
        for (int nt = 0; nt < 16; nt++) {
            o[nt][0] *= al0; o[nt][1] *= al0;
            o[nt][2] *= al1; o[nt][3] *= al1;
        }

        #pragma unroll
        for (int kc = 0; kc < 8; kc++) {
            int src = (g << 2) | (tig >> 1);
            float x0 = __shfl_sync(0xffffffffu, s[kc][0], src);
            float x1 = __shfl_sync(0xffffffffu, s[kc][1], src);
            float x2 = __shfl_sync(0xffffffffu, s[kc][2], src);
            float x3 = __shfl_sync(0xffffffffu, s[kc][3], src);
            float z0 = __shfl_sync(0xffffffffu, s[kc][0], src + 2);
            float z1 = __shfl_sync(0xffffffffu, s[kc][1], src + 2);
            float z2 = __shfl_sync(0xffffffffu, s[kc][2], src + 2);
            float z3 = __shfl_sync(0xffffffffu, s[kc][3], src + 2);
            bool odd = (tig & 1) != 0;
            uint32_t a0 = __float_as_uint(odd ? x1 : x0);
            uint32_t a1 = __float_as_uint(odd ? x3 : x2);
            uint32_t a2 = __float_as_uint(odd ? z1 : z0);
            uint32_t a3 = __float_as_uint(odd ? z3 : z2);
            #pragma unroll
            for (int nt = 0; nt < 16; nt++) {
                uint32_t b0 = __float_as_uint(Vs[(kc * 8 + tig) * ROWP + nt * 8 + g]);
                uint32_t b1 = __float_as_uint(Vs[(kc * 8 + tig + 4) * ROWP + nt * 8 + g]);
                mma_tf32(o[nt][0], o[nt][1], o[nt][2], o[nt][3], a0, a1, a2, a3, b0, b1);
            }
        }
    }

    float f0 = (1.f / l0) * agate[rg0 * NH + h];
    float f1 = (1.f / l1) * agate[rg1 * NH + h];
    #pragma unroll
    for (int nt = 0; nt < 16; nt++) {
        *(__half2*)&y[(size_t)rg0 * DIM + h * HD + nt * 8 + 2 * tig] =
            __floats2half2_rn(o[nt][0] * f0, o[nt][1] * f0);
        *(__half2*)&y[(size_t)rg1 * DIM + h * HD + nt * 8 + 2 * tig] =
            __floats2half2_rn(o[nt][2] * f1, o[nt][3] * f1);
    }
}

// ---------------- launch ----------------
extern "C" void kernel_launch(void* const* d_in, const int* in_sizes, int n_in,
                              void* d_out, int out_size) {
    const float* x           = (const float*)d_in[0];
    const float* ve          = (const float*)d_in[1];
    const float* qkvo_w      = (const float*)d_in[2];
    const float* attn_gate_w = (const float*)d_in[3];
    const float* ve_gate_w   = (const float*)d_in[4];
    const float* c_fc        = (const float*)d_in[5];
    const float* c_proj      = (const float*)d_in[6];
    const float* sa_lambdas  = (const float*)d_in[7];
    const float* cosb        = (const float*)d_in[8];
    const float* sinb        = (const float*)d_in[9];
    const float* attn_scale  = (const float*)d_in[10];
    const int*   docs        = (const int*)d_in[11];
    const int*   key_offset  = (const int*)d_in[12];
    float*       out         = (float*)d_out;

    __half *xn, *y, *hbuf, *wqkv, *wfc, *wpT;
    float *qkv, *krot, *x1, *agate, *vgate;
    cudaGetSymbolAddress((void**)&xn,    g_xn);
    cudaGetSymbolAddress((void**)&qkv,   g_qkv);
    cudaGetSymbolAddress((void**)&krot,  g_krot);
    cudaGetSymbolAddress((void**)&y,     g_y);
    cudaGetSymbolAddress((void**)&x1,    g_x1);
    cudaGetSymbolAddress((void**)&hbuf,  g_h);
    cudaGetSymbolAddress((void**)&agate, g_agate);
    cudaGetSymbolAddress((void**)&vgate, g_vgate);
    cudaGetSymbolAddress((void**)&wqkv,  g_wqkv);
    cudaGetSymbolAddress((void**)&wfc,   g_wfc);
    cudaGetSymbolAddress((void**)&wpT,   g_wpT);

    cudaFuncSetAttribute(flash_mma_kernel, cudaFuncAttributeMaxDynamicSharedMemorySize,
                         FL_SMEM);
    cudaFuncSetAttribute(f16_gemm_kernel<0>, cudaFuncAttributeMaxDynamicSharedMemorySize,
                         GEMM_SMEM);
    cudaFuncSetAttribute(f16_gemm_kernel<1>, cudaFuncAttributeMaxDynamicSharedMemorySize,
                         GEMM_SMEM);
    cudaFuncSetAttribute(f16_gemm_kernel<2>, cudaFuncAttributeMaxDynamicSharedMemorySize,
                         GEMM_SMEM);

    // weight conversions (fp16 copies; c_proj also transposed to [N,K])
    round_f16_kernel<<<(4 * DIM * DIM / 8 + 255) / 256, 256>>>(qkvo_w, wqkv, 4 * DIM * DIM / 8);
    round_f16_kernel<<<((size_t)FFN * DIM / 8 + 255) / 256, 256>>>(c_fc, wfc, FFN * DIM / 8);
    transpose_f16_kernel<<<dim3(DIM / 32, FFN / 32), dim3(32, 8)>>>(c_proj, wpT);

    // 1. xn = fp16(rmsnorm(x))
    rmsnorm_kernel<<<T_SEQ, 256>>>(x, xn);
    // 2. qkv = lam0 * xn @ Wqkv^T   (fp32 out)
    f16_gemm_kernel<0><<<dim3(3 * DIM / GBN, T_SEQ / GBM), 256, GEMM_SMEM>>>(
        xn, wqkv, qkv, nullptr, sa_lambdas, 0, 3 * DIM, DIM);
    // 3. per-head rmsnorm + rotary
    qkrot_kernel<<<dim3(32, T_SEQ), 128>>>(qkv, krot, cosb, sinb);
    // 4. key-offset shift
    kshift_kernel<<<(T_SEQ * NH * HD) / 256, 256>>>(krot, qkv, key_offset);
    // 5. gates
    gates_kernel<<<T_SEQ, 256>>>(xn, attn_gate_w, ve_gate_w, agate, vgate);
    // 6. v update
    vupdate_kernel<<<(T_SEQ * DIM) / 256, 256>>>(qkv, ve, vgate);
    // 7. MMA flash attention (fp16 y out)
    flash_mma_kernel<<<dim3(T_SEQ / 64, NH), 128, FL_SMEM>>>(
        qkv, docs, attn_scale, agate, y);
    // 8. x1 = x + lam1 * y @ Wo^T
    f16_gemm_kernel<2><<<dim3(DIM / GBN, T_SEQ / GBM), 256, GEMM_SMEM>>>(
        y, wqkv + (size_t)3 * DIM * DIM, x1, x, sa_lambdas, 1, DIM, DIM);
    // 9. xn = fp16(rmsnorm(x1))
    rmsnorm_kernel<<<T_SEQ, 256>>>(x1, xn);
    // 10. h = fp16(relu(xn @ c_fc^T)^2)
    f16_gemm_kernel<1><<<dim3(FFN / GBN, T_SEQ / GBM), 256, GEMM_SMEM>>>(
        xn, wfc, hbuf, nullptr, nullptr, 0, FFN, DIM);
    // 11. out = x1 + h @ c_proj   (via c_proj^T, K=8192)
    f16_gemm_kernel<2><<<dim3(DIM / GBN, T_SEQ / GBM), 256, GEMM_SMEM>>>(
        hbuf, wpT, out, x1, nullptr, 0, DIM, FFN);
}

// round 7
// speedup vs baseline: 7.5964x; 1.0383x over previous
#include <cuda_runtime.h>
#include <cuda_fp16.h>
#include <cstdint>
#include <cstddef>

// ---------------- problem constants ----------------
#define T_SEQ 2048
#define DIM   2048
#define NH    16
#define HD    128
#define FFN   8192
#define EPS_F 1.1920929e-07f
#define NEG_INF_F (-1e30f)

// ---------------- scratch (device globals; no runtime allocs) ----------------
__device__ __half g_xn  [(size_t)T_SEQ * DIM];     // fp16 rmsnorm output
__device__ float  g_qkv [(size_t)T_SEQ * 3 * DIM]; // [T, 48, 128] fp32
__device__ float  g_krot[(size_t)T_SEQ * NH * HD];
__device__ __half g_y   [(size_t)T_SEQ * DIM];     // fp16 attention output
__device__ float  g_x1  [(size_t)T_SEQ * DIM];
__device__ __half g_h   [(size_t)T_SEQ * FFN];     // fp16 MLP hidden
__device__ float  g_agate[(size_t)T_SEQ * NH];
__device__ float  g_vgate[(size_t)T_SEQ * NH];
__device__ __half g_wqkv[(size_t)4 * DIM * DIM];   // fp16 qkvo weights
__device__ __half g_wfc [(size_t)FFN * DIM];       // fp16 c_fc
__device__ __half g_wpT [(size_t)DIM * FFN];       // fp16 c_proj^T [DIM, FFN]

// ---------------- helpers ----------------
__device__ __forceinline__ float to_tf32(float x) {
    asm("cvt.rna.tf32.f32 %0, %1;" : "=f"(x) : "f"(x));
    return x;
}
__device__ __forceinline__ void cp_async16(uint32_t dst, const void* src) {
    asm volatile("cp.async.cg.shared.global [%0], [%1], 16;" :: "r"(dst), "l"(src));
}
__device__ __forceinline__ void cp_async_commit() {
    asm volatile("cp.async.commit_group;" ::: "memory");
}
template<int N>
__device__ __forceinline__ void cp_async_wait() {
    asm volatile("cp.async.wait_group %0;" :: "n"(N) : "memory");
}
__device__ __forceinline__ uint32_t smem_u32(const void* p) {
    uint32_t a;
    asm("{ .reg .u64 t; cvta.to.shared.u64 t, %1; cvt.u32.u64 %0, t; }" : "=r"(a) : "l"(p));
    return a;
}
__device__ __forceinline__ void ldsm_x4(uint32_t& r0, uint32_t& r1, uint32_t& r2, uint32_t& r3,
                                        uint32_t addr) {
    asm volatile("ldmatrix.sync.aligned.m8n8.x4.shared.b16 {%0,%1,%2,%3}, [%4];"
                 : "=r"(r0), "=r"(r1), "=r"(r2), "=r"(r3) : "r"(addr));
}
__device__ __forceinline__ void mma_f16(float& c0, float& c1, float& c2, float& c3,
                                        uint32_t a0, uint32_t a1, uint32_t a2, uint32_t a3,
                                        uint32_t b0, uint32_t b1) {
    asm volatile("mma.sync.aligned.m16n8k16.row.col.f32.f16.f16.f32 "
                 "{%0,%1,%2,%3}, {%4,%5,%6,%7}, {%8,%9}, {%0,%1,%2,%3};"
                 : "+f"(c0), "+f"(c1), "+f"(c2), "+f"(c3)
                 : "r"(a0), "r"(a1), "r"(a2), "r"(a3), "r"(b0), "r"(b1));
}
__device__ __forceinline__ void mma_tf32(float& c0, float& c1, float& c2, float& c3,
                                         uint32_t a0, uint32_t a1, uint32_t a2, uint32_t a3,
                                         uint32_t b0, uint32_t b1) {
    asm volatile("mma.sync.aligned.m16n8k8.row.col.f32.tf32.tf32.f32 "
                 "{%0,%1,%2,%3}, {%4,%5,%6,%7}, {%8,%9}, {%0,%1,%2,%3};"
                 : "+f"(c0), "+f"(c1), "+f"(c2), "+f"(c3)
                 : "r"(a0), "r"(a1), "r"(a2), "r"(a3), "r"(b0), "r"(b1));
}

// ================= fp16 warp-MMA GEMM =================
// C[M,N] = epi(alpha * A[M,K] @ B[N,K]^T), A/B fp16, accumulate fp32.
// BM=256 BN=128 BK=64, 256 threads (8 warps, 4x2 of 64x64 warp tiles),
// 4-stage cp.async pipeline, single __syncthreads per k-iter, loads lead compute.
#define GBM 256
#define GBN 128
#define GBK 64
#define GSTAGES 4
#define ROWH 72                               // halfs per smem row (144 B)
#define A_STAGE_B (GBM * ROWH * 2)            // 36864 bytes
#define B_STAGE_B (GBN * ROWH * 2)            // 18432 bytes
#define STAGE_B   (A_STAGE_B + B_STAGE_B)     // 55296 bytes
#define GEMM_SMEM (GSTAGES * STAGE_B)         // 221184 bytes

// EPI: 0=none->float, 1=relu^2->half, 2=add residual->float
template<int EPI>
__global__ void __launch_bounds__(256, 1)
f16_gemm_kernel(const __half* __restrict__ A, const __half* __restrict__ B,
                void* __restrict__ Cv, const float* __restrict__ addsrc,
                const float* __restrict__ alpha_ptr, int alpha_idx,
                int N, int K)
{
    extern __shared__ char smc[];
    const int tid = threadIdx.x;
    const int wid = tid >> 5, lane = tid & 31;
    const int g = lane >> 2, tig = lane & 3;
    const int wm = (wid & 3) * 64, wn = (wid >> 2) * 64;
    const int bn = blockIdx.x, bm = blockIdx.y;
    const int nk = K / GBK;
    const uint32_t sb = smem_u32(smc);

    const __half* Agm = A + (size_t)bm * GBM * K;
    const __half* Bgm = B + (size_t)bn * GBN * K;

    auto load_tile = [&](int stage, int ktile) {
        uint32_t sa = sb + stage * STAGE_B;
        uint32_t sB = sa + A_STAGE_B;
        int kt = ktile * GBK;
        #pragma unroll
        for (int i = 0; i < 8; i++) {                 // A: 256 rows x 8 chunks
            int c = tid + i * 256;
            int row = c >> 3, ch = c & 7;
            cp_async16(sa + (uint32_t)row * 144 + ch * 16,
                       Agm + (size_t)row * K + kt + ch * 8);
        }
        #pragma unroll
        for (int i = 0; i < 4; i++) {                 // B: 128 rows x 8 chunks
            int c = tid + i * 256;
            int row = c >> 3, ch = c & 7;
            cp_async16(sB + (uint32_t)row * 144 + ch * 16,
                       Bgm + (size_t)row * K + kt + ch * 8);
        }
    };

    // per-thread ldmatrix byte offsets (within a stage)
    uint32_t aoff[4], boff[4];
    #pragma unroll
    for (int mt = 0; mt < 4; mt++)
        aoff[mt] = (uint32_t)(wm + mt * 16 + (lane & 7) + ((lane >> 3) & 1) * 8) * 144
                 + ((lane >> 4) & 1) * 16;
    #pragma unroll
    for (int nb = 0; nb < 4; nb++)
        boff[nb] = (uint32_t)(wn + nb * 16 + (lane & 7) + ((lane >> 4) & 1) * 8) * 144
                 + ((lane >> 3) & 1) * 16;

    float acc[4][8][4];
    #pragma unroll
    for (int mt = 0; mt < 4; mt++)
        #pragma unroll
        for (int nt = 0; nt < 8; nt++)
            #pragma unroll
            for (int q = 0; q < 4; q++) acc[mt][nt][q] = 0.f;

    #pragma unroll
    for (int s = 0; s < GSTAGES - 1; s++) { load_tile(s, s); cp_async_commit(); }

    for (int k = 0; k < nk; k++) {
        cp_async_wait<GSTAGES - 2>();
        __syncthreads();                       // single barrier per k-iter
        // issue next tile's loads BEFORE compute (stage (k+3)&3 was freed at k-1)
        if (k + GSTAGES - 1 < nk) load_tile((k + GSTAGES - 1) & (GSTAGES - 1),
                                            k + GSTAGES - 1);
        cp_async_commit();

        uint32_t sa = sb + (k & (GSTAGES - 1)) * STAGE_B;
        uint32_t sB = sa + A_STAGE_B;
        #pragma unroll
        for (int ks = 0; ks < 4; ks++) {              // 4 x k16 = BK 64
            const uint32_t kb = ks * 32;              // 16 halfs = 32 bytes
            uint32_t a[4][4];
            #pragma unroll
            for (int mt = 0; mt < 4; mt++)
                ldsm_x4(a[mt][0], a[mt][1], a[mt][2], a[mt][3], sa + aoff[mt] + kb);
            #pragma unroll
            for (int nb = 0; nb < 4; nb++) {
                uint32_t b0, b1, b2, b3;
                ldsm_x4(b0, b1, b2, b3, sB + boff[nb] + kb);
                #pragma unroll
                for (int mt = 0; mt < 4; mt++) {
                    mma_f16(acc[mt][2 * nb][0], acc[mt][2 * nb][1],
                            acc[mt][2 * nb][2], acc[mt][2 * nb][3],
                            a[mt][0], a[mt][1], a[mt][2], a[mt][3], b0, b1);
                    mma_f16(acc[mt][2 * nb + 1][0], acc[mt][2 * nb + 1][1],
                            acc[mt][2 * nb + 1][2], acc[mt][2 * nb + 1][3],
                            a[mt][0], a[mt][1], a[mt][2], a[mt][3], b2, b3);
                }
            }
        }
    }

    float alpha = alpha_ptr ? alpha_ptr[alpha_idx] : 1.0f;
    #pragma unroll
    for (int mt = 0; mt < 4; mt++) {
        #pragma unroll
        for (int half_i = 0; half_i < 2; half_i++) {
            int row = bm * GBM + wm + mt * 16 + g + half_i * 8;
            #pragma unroll
            for (int nt = 0; nt < 8; nt++) {
                int col = bn * GBN + wn + nt * 8 + tig * 2;
                float vx = acc[mt][nt][half_i * 2 + 0] * alpha;
                float vy = acc[mt][nt][half_i * 2 + 1] * alpha;
                size_t idx = (size_t)row * N + col;
                if (EPI == 1) {
                    vx = fmaxf(vx, 0.f); vx = vx * vx;
                    vy = fmaxf(vy, 0.f); vy = vy * vy;
                    *(__half2*)((__half*)Cv + idx) = __floats2half2_rn(vx, vy);
                } else if (EPI == 2) {
                    float2 a2 = *(const float2*)&addsrc[idx];
                    float2 v; v.x = vx + a2.x; v.y = vy + a2.y;
                    *(float2*)((float*)Cv + idx) = v;
                } else {
                    float2 v; v.x = vx; v.y = vy;
                    *(float2*)((float*)Cv + idx) = v;
                }
            }
        }
    }
}

// ---------------- weight conversion kernels ----------------
__global__ void __launch_bounds__(256) round_f16_kernel(const float* __restrict__ in,
                                                        __half* __restrict__ outp, int n8) {
    int i = blockIdx.x * 256 + threadIdx.x;
    if (i < n8) {
        float4 v0 = ((const float4*)in)[2 * i];
        float4 v1 = ((const float4*)in)[2 * i + 1];
        __half2 h0 = __floats2half2_rn(v0.x, v0.y);
        __half2 h1 = __floats2half2_rn(v0.z, v0.w);
        __half2 h2 = __floats2half2_rn(v1.x, v1.y);
        __half2 h3 = __floats2half2_rn(v1.z, v1.w);
        uint4 o;
        o.x = *(uint32_t*)&h0; o.y = *(uint32_t*)&h1;
        o.z = *(uint32_t*)&h2; o.w = *(uint32_t*)&h3;
        ((uint4*)outp)[i] = o;
    }
}
// out[DIM, FFN] (fp16) = in[FFN, DIM]^T
__global__ void __launch_bounds__(256) transpose_f16_kernel(const float* __restrict__ in,
                                                            __half* __restrict__ outp) {
    __shared__ float t[32][33];
    int bx = blockIdx.x;   // over DIM/32
    int by = blockIdx.y;   // over FFN/32
    int x = threadIdx.x, y = threadIdx.y;    // 32 x 8
    #pragma unroll
    for (int i = 0; i < 32; i += 8)
        t[y + i][x] = in[(size_t)(by * 32 + y + i) * DIM + bx * 32 + x];
    __syncthreads();
    #pragma unroll
    for (int i = 0; i < 32; i += 8)
        outp[(size_t)(bx * 32 + y + i) * FFN + by * 32 + x] = __float2half_rn(t[x][y + i]);
}

// ---------------- RMSNorm (fp16 output) ----------------
__global__ void __launch_bounds__(256) rmsnorm_kernel(const float* __restrict__ in,
                                                      __half* __restrict__ outp) {
    int t = blockIdx.x;
    const float* r = in + (size_t)t * DIM;
    float ss = 0.f;
    float vals[8];
    #pragma unroll
    for (int j = 0; j < 8; j++) {
        float v = r[threadIdx.x + j * 256];
        vals[j] = v; ss += v * v;
    }
    __shared__ float sred[8];
    for (int o = 16; o; o >>= 1) ss += __shfl_xor_sync(0xffffffffu, ss, o);
    if ((threadIdx.x & 31) == 0) sred[threadIdx.x >> 5] = ss;
    __syncthreads();
    float tot = 0.f;
    #pragma unroll
    for (int i = 0; i < 8; i++) tot += sred[i];
    float scale = rsqrtf(tot / (float)DIM + EPS_F);
    #pragma unroll
    for (int j = 0; j < 8; j++)
        outp[(size_t)t * DIM + threadIdx.x + j * 256] = __float2half_rn(vals[j] * scale);
}

// ---------------- per-(t, head-slot) QK rmsnorm + rotary (tf32-rounded out) ----------------
__global__ void __launch_bounds__(128) qkrot_kernel(
    float* __restrict__ qkv, float* __restrict__ krot,
    const float* __restrict__ cosb, const float* __restrict__ sinb)
{
    int hs = blockIdx.x;
    int t  = blockIdx.y;
    int d  = threadIdx.x;
    float v = qkv[((size_t)t * 48 + hs) * HD + d];
    __shared__ float sm[HD];
    __shared__ float red[4];
    float ss = v * v;
    for (int o = 16; o; o >>= 1) ss += __shfl_xor_sync(0xffffffffu, ss, o);
    if ((d & 31) == 0) red[d >> 5] = ss;
    __syncthreads();
    float tot = red[0] + red[1] + red[2] + red[3];
    float n = v * rsqrtf(tot / (float)HD + EPS_F);
    sm[d] = n;
    __syncthreads();
    float o;
    if (d < 64) {
        float c = cosb[t * 64 + d], s = sinb[t * 64 + d];
        o = sm[d] * c + sm[d + 64] * s;
    } else {
        float c = cosb[t * 64 + d - 64], s = sinb[t * 64 + d - 64];
        o = -sm[d - 64] * s + sm[d] * c;
    }
    o = to_tf32(o);
    if (hs < 16) qkv[((size_t)t * 48 + hs) * HD + d] = o;
    else         krot[((size_t)t * NH + (hs - 16)) * HD + d] = o;
}

// ---------------- key-offset shift ----------------
__global__ void __launch_bounds__(256) kshift_kernel(
    const float* __restrict__ krot, float* __restrict__ qkv,
    const int* __restrict__ key_offset)
{
    int idx = blockIdx.x * 256 + threadIdx.x;
    int d = idx & 127;
    int h = (idx >> 7) & 15;
    int t = idx >> 11;
    int ko = key_offset[0];
    bool up = (d >= 32 && d < 64) || (d >= 96);
    int st = (ko && up && t > 0) ? (t - 1) : t;
    qkv[((size_t)t * 48 + 16 + h) * HD + d] = krot[((size_t)st * NH + h) * HD + d];
}

// ---------------- gate logits (xn is fp16) ----------------
__global__ void __launch_bounds__(256) gates_kernel(
    const __half* __restrict__ xn, const float* __restrict__ agw,
    const float* __restrict__ vgw, float* __restrict__ agate,
    float* __restrict__ vgate)
{
    int t = blockIdx.x;
    int w = threadIdx.x >> 5, lane = threadIdx.x & 31;
    const __half* xr = xn + (size_t)t * DIM;
    float acc[4] = {};
    const float* wbase[4];
    #pragma unroll
    for (int q = 0; q < 4; q++) {
        int o = w * 4 + q;
        wbase[q] = (o < 16) ? (agw + (size_t)o * DIM) : (vgw + (size_t)(o - 16) * DIM);
    }
    for (int dd = lane; dd < DIM; dd += 32) {
        float xv = __half2float(xr[dd]);
        #pragma unroll
        for (int q = 0; q < 4; q++) acc[q] = fmaf(xv, wbase[q][dd], acc[q]);
    }
    #pragma unroll
    for (int q = 0; q < 4; q++)
        for (int o2 = 16; o2; o2 >>= 1) acc[q] += __shfl_xor_sync(0xffffffffu, acc[q], o2);
    if (lane == 0) {
        #pragma unroll
        for (int q = 0; q < 4; q++) {
            int o = w * 4 + q;
            float g = 1.f / (1.f + expf(-acc[q]));
            if (o < 16) agate[t * NH + o] = g;
            else        vgate[t * NH + (o - 16)] = g;
        }
    }
}

// ---------------- v = round_tf32(v + ve_gate * ve) ----------------
__global__ void __launch_bounds__(256) vupdate_kernel(
    float* __restrict__ qkv, const float* __restrict__ ve,
    const float* __restrict__ vgate)
{
    int idx = blockIdx.x * 256 + threadIdx.x;
    int d = idx & 127;
    int h = (idx >> 7) & 15;
    int t = idx >> 11;
    float g = vgate[t * NH + h];
    size_t o = ((size_t)t * 48 + 32 + h) * HD + d;
    qkv[o] = to_tf32(qkv[o] + g * ve[idx]);
}

// ================= MMA flash attention (tf32, fp16 y output) =================
#define ROWP 132
#define FL_SMEM ((3 * 64 * ROWP + 64) * 4)

__global__ void __launch_bounds__(128) flash_mma_kernel(
    const float* __restrict__ qkv, const int* __restrict__ docs,
    const float* __restrict__ attn_scale, const float* __restrict__ agate,
    __half* __restrict__ y)
{
    extern __shared__ float fs[];
    float* Qs = fs;
    float* Ks = fs + 64 * ROWP;
    float* Vs = fs + 2 * 64 * ROWP;
    int*   kd = (int*)(fs + 3 * 64 * ROWP);

    const int tid = threadIdx.x, wid = tid >> 5, lane = tid & 31;
    const int g = lane >> 2, tig = lane & 3;
    const int h = blockIdx.y;
    const int qi = (int)gridDim.x - 1 - (int)blockIdx.x;
    const int qbase = qi * 64;
    const float scale = attn_scale[0];

    #pragma unroll
    for (int i = 0; i < 16; i++) {
        int c = tid + i * 128;
        int r = c >> 5, co = (c & 31) * 4;
        float4 f = *(const float4*)&qkv[((size_t)(qbase + r) * 48 + h) * HD + co];
        *(float4*)&Qs[r * ROWP + co] = f;
    }
    const int rg0 = qbase + wid * 16 + g;
    const int rg1 = rg0 + 8;
    const int qd0 = docs[rg0], qd1 = docs[rg1];
    const int qdmin = docs[qbase];

    float o[16][4] = {};
    float m0 = NEG_INF_F, m1 = NEG_INF_F, l0 = 0.f, l1 = 0.f;
    __syncthreads();

    for (int kb = 0; kb <= qi; kb++) {
        const int kbase = kb * 64;
        if (docs[kbase + 63] < qdmin) continue;
        __syncthreads();
        #pragma unroll
        for (int i = 0; i < 16; i++) {
            int c = tid + i * 128;
            int r = c >> 5, co = (c & 31) * 4;
            float4 f = *(const float4*)&qkv[((size_t)(kbase + r) * 48 + 16 + h) * HD + co];
            *(float4*)&Ks[r * ROWP + co] = f;
            float4 v4 = *(const float4*)&qkv[((size_t)(kbase + r) * 48 + 32 + h) * HD + co];
            *(float4*)&Vs[r * ROWP + co] = v4;
        }
        if (tid < 64) kd[tid] = docs[kbase + tid];
        __syncthreads();

        float s[8][4] = {};
        #pragma unroll
        for (int ks = 0; ks < 16; ks++) {
            const int k0 = ks * 8;
            uint32_t a0 = __float_as_uint(Qs[(wid * 16 + g) * ROWP + k0 + tig]);
            uint32_t a1 = __float_as_uint(Qs[(wid * 16 + g + 8) * ROWP + k0 + tig]);
            uint32_t a2 = __float_as_uint(Qs[(wid * 16 + g) * ROWP + k0 + tig + 4]);
            uint32_t a3 = __float_as_uint(Qs[(wid * 16 + g + 8) * ROWP + k0 + tig + 4]);
            #pragma unroll
            for (int nt = 0; nt < 8; nt++) {
                uint32_t b0 = __float_as_uint(Ks[(nt * 8 + g) * ROWP + k0 + tig]);
                uint32_t b1 = __float_as_uint(Ks[(nt * 8 + g) * ROWP + k0 + tig + 4]);
                mma_tf32(s[nt][0], s[nt][1], s[nt][2], s[nt][3], a0, a1, a2, a3, b0, b1);
            }
        }

        float mx0 = m0, mx1 = m1;
        #pragma unroll
        for (int nt = 0; nt < 8; nt++) {
            int c0i = kbase + nt * 8 + 2 * tig;
            int d0 = kd[nt * 8 + 2 * tig], d1 = kd[nt * 8 + 2 * tig + 1];
            float v00 = (c0i     <= rg0 && d0 == qd0) ? s[nt][0] * scale : NEG_INF_F;
            float v01 = (c0i + 1 <= rg0 && d1 == qd0) ? s[nt][1] * scale : NEG_INF_F;
            float v10 = (c0i     <= rg1 && d0 == qd1) ? s[nt][2] * scale : NEG_INF_F;
            float v11 = (c0i + 1 <= rg1 && d1 == qd1) ? s[nt][3] * scale : NEG_INF_F;
            s[nt][0] = v00; s[nt][1] = v01; s[nt][2] = v10; s[nt][3] = v11;
            mx0 = fmaxf(mx0, fmaxf(v00, v01));
            mx1 = fmaxf(mx1, fmaxf(v10, v11));
        }
        mx0 = fmaxf(mx0, __shfl_xor_sync(0xffffffffu, mx0, 1));
        mx0 = fmaxf(mx0, __shfl_xor_sync(0xffffffffu, mx0, 2));
        mx1 = fmaxf(mx1, __shfl_xor_sync(0xffffffffu, mx1, 1));
        mx1 = fmaxf(mx1, __shfl_xor_sync(0xffffffffu, mx1, 2));
        float al0 = __expf(m0 - mx0), al1 = __expf(m1 - mx1);
        m0 = mx0; m1 = mx1;

        float sum0 = 0.f, sum1 = 0.f;
        #pragma unroll
        for (int nt = 0; nt < 8; nt++) {
            float p00 = __expf(s[nt][0] - m0);
            float p01 = __expf(s[nt][1] - m0);
            float p10 = __expf(s[nt][2] - m1);
            float p11 = __expf(s[nt][3] - m1);
            sum0 += p00 + p01; sum1 += p10 + p11;
            s[nt][0] = to_tf32(p00); s[nt][1] = to_tf32(p01);
            s[nt][2] = to_tf32(p10); s[nt][3] = to_tf32(p11);
        }
        sum0 += __shfl_xor_sync(0xffffffffu, sum0, 1);
        sum0 += __shfl_xor_sync(0xffffffffu, sum0, 2);
        sum1 += __shfl_xor_sync(0xffffffffu, sum1, 1);
        sum1 += __shfl_xor_sync(0xffffffffu, sum1, 2);
        l0 = l0 * al0 + sum0;
        l1 = l1 * al1 + sum1;
        #pragma unroll
        for (int nt = 0; nt < 16; nt++) {
            o[nt][0] *= al0; o[nt][1] *= al0;
            o[nt][2] *= al1; o[nt][3] *= al1;
        }

        #pragma unroll
        for (int kc = 0; kc < 8; kc++) {
            int src = (g << 2) | (tig >> 1);
            float x0 = __shfl_sync(0xffffffffu, s[kc][0], src);
            float x1 = __shfl_sync(0xffffffffu, s[kc][1], src);
            float x2 = __shfl_sync(0xffffffffu, s[kc][2], src);
            float x3 = __shfl_sync(0xffffffffu, s[kc][3], src);
            float z0 = __shfl_sync(0xffffffffu, s[kc][0], src + 2);
            float z1 = __shfl_sync(0xffffffffu, s[kc][1], src + 2);
            float z2 = __shfl_sync(0xffffffffu, s[kc][2], src + 2);
            float z3 = __shfl_sync(0xffffffffu, s[kc][3], src + 2);
            bool odd = (tig & 1) != 0;
            uint32_t a0 = __float_as_uint(odd ? x1 : x0);
            uint32_t a1 = __float_as_uint(odd ? x3 : x2);
            uint32_t a2 = __float_as_uint(odd ? z1 : z0);
            uint32_t a3 = __float_as_uint(odd ? z3 : z2);
            #pragma unroll
            for (int nt = 0; nt < 16; nt++) {
                uint32_t b0 = __float_as_uint(Vs[(kc * 8 + tig) * ROWP + nt * 8 + g]);
                uint32_t b1 = __float_as_uint(Vs[(kc * 8 + tig + 4) * ROWP + nt * 8 + g]);
                mma_tf32(o[nt][0], o[nt][1], o[nt][2], o[nt][3], a0, a1, a2, a3, b0, b1);
            }
        }
    }

    float f0 = (1.f / l0) * agate[rg0 * NH + h];
    float f1 = (1.f / l1) * agate[rg1 * NH + h];
    #pragma unroll
    for (int nt = 0; nt < 16; nt++) {
        *(__half2*)&y[(size_t)rg0 * DIM + h * HD + nt * 8 + 2 * tig] =
            __floats2half2_rn(o[nt][0] * f0, o[nt][1] * f0);
        *(__half2*)&y[(size_t)rg1 * DIM + h * HD + nt * 8 + 2 * tig] =
            __floats2half2_rn(o[nt][2] * f1, o[nt][3] * f1);
    }
}

// ---------------- launch ----------------
extern "C" void kernel_launch(void* const* d_in, const int* in_sizes, int n_in,
                              void* d_out, int out_size) {
    const float* x           = (const float*)d_in[0];
    const float* ve          = (const float*)d_in[1];
    const float* qkvo_w      = (const float*)d_in[2];
    const float* attn_gate_w = (const float*)d_in[3];
    const float* ve_gate_w   = (const float*)d_in[4];
    const float* c_fc        = (const float*)d_in[5];
    const float* c_proj      = (const float*)d_in[6];
    const float* sa_lambdas  = (const float*)d_in[7];
    const float* cosb        = (const float*)d_in[8];
    const float* sinb        = (const float*)d_in[9];
    const float* attn_scale  = (const float*)d_in[10];
    const int*   docs        = (const int*)d_in[11];
    const int*   key_offset  = (const int*)d_in[12];
    float*       out         = (float*)d_out;

    __half *xn, *y, *hbuf, *wqkv, *wfc, *wpT;
    float *qkv, *krot, *x1, *agate, *vgate;
    cudaGetSymbolAddress((void**)&xn,    g_xn);
    cudaGetSymbolAddress((void**)&qkv,   g_qkv);
    cudaGetSymbolAddress((void**)&krot,  g_krot);
    cudaGetSymbolAddress((void**)&y,     g_y);
    cudaGetSymbolAddress((void**)&x1,    g_x1);
    cudaGetSymbolAddress((void**)&hbuf,  g_h);
    cudaGetSymbolAddress((void**)&agate, g_agate);
    cudaGetSymbolAddress((void**)&vgate, g_vgate);
    cudaGetSymbolAddress((void**)&wqkv,  g_wqkv);
    cudaGetSymbolAddress((void**)&wfc,   g_wfc);
    cudaGetSymbolAddress((void**)&wpT,   g_wpT);

    cudaFuncSetAttribute(flash_mma_kernel, cudaFuncAttributeMaxDynamicSharedMemorySize,
                         FL_SMEM);
    cudaFuncSetAttribute(f16_gemm_kernel<0>, cudaFuncAttributeMaxDynamicSharedMemorySize,
                         GEMM_SMEM);
    cudaFuncSetAttribute(f16_gemm_kernel<1>, cudaFuncAttributeMaxDynamicSharedMemorySize,
                         GEMM_SMEM);
    cudaFuncSetAttribute(f16_gemm_kernel<2>, cudaFuncAttributeMaxDynamicSharedMemorySize,
                         GEMM_SMEM);

    // weight conversions (fp16 copies; c_proj also transposed to [N,K])
    round_f16_kernel<<<(4 * DIM * DIM / 8 + 255) / 256, 256>>>(qkvo_w, wqkv, 4 * DIM * DIM / 8);
    round_f16_kernel<<<((size_t)FFN * DIM / 8 + 255) / 256, 256>>>(c_fc, wfc, FFN * DIM / 8);
    transpose_f16_kernel<<<dim3(DIM / 32, FFN / 32), dim3(32, 8)>>>(c_proj, wpT);

    // 1. xn = fp16(rmsnorm(x))
    rmsnorm_kernel<<<T_SEQ, 256>>>(x, xn);
    // 2. qkv = lam0 * xn @ Wqkv^T   (fp32 out)
    f16_gemm_kernel<0><<<dim3(3 * DIM / GBN, T_SEQ / GBM), 256, GEMM_SMEM>>>(
        xn, wqkv, qkv, nullptr, sa_lambdas, 0, 3 * DIM, DIM);
    // 3. per-head rmsnorm + rotary
    qkrot_kernel<<<dim3(32, T_SEQ), 128>>>(qkv, krot, cosb, sinb);
    // 4. key-offset shift
    kshift_kernel<<<(T_SEQ * NH * HD) / 256, 256>>>(krot, qkv, key_offset);
    // 5. gates
    gates_kernel<<<T_SEQ, 256>>>(xn, attn_gate_w, ve_gate_w, agate, vgate);
    // 6. v update
    vupdate_kernel<<<(T_SEQ * DIM) / 256, 256>>>(qkv, ve, vgate);
    // 7. MMA flash attention (fp16 y out)
    flash_mma_kernel<<<dim3(T_SEQ / 64, NH), 128, FL_SMEM>>>(
        qkv, docs, attn_scale, agate, y);
    // 8. x1 = x + lam1 * y @ Wo^T
    f16_gemm_kernel<2><<<dim3(DIM / GBN, T_SEQ / GBM), 256, GEMM_SMEM>>>(
        y, wqkv + (size_t)3 * DIM * DIM, x1, x, sa_lambdas, 1, DIM, DIM);
    // 9. xn = fp16(rmsnorm(x1))
    rmsnorm_kernel<<<T_SEQ, 256>>>(x1, xn);
    // 10. h = fp16(relu(xn @ c_fc^T)^2)
    f16_gemm_kernel<1><<<dim3(FFN / GBN, T_SEQ / GBM), 256, GEMM_SMEM>>>(
        xn, wfc, hbuf, nullptr, nullptr, 0, FFN, DIM);
    // 11. out = x1 + h @ c_proj   (via c_proj^T, K=8192)
    f16_gemm_kernel<2><<<dim3(DIM / GBN, T_SEQ / GBM), 256, GEMM_SMEM>>>(
        hbuf, wpT, out, x1, nullptr, 0, DIM, FFN);
}

// round 8
// speedup vs baseline: 7.6109x; 1.0019x over previous
#include <cuda_runtime.h>
#include <cuda_fp16.h>
#include <cstdint>
#include <cstddef>

// ---------------- problem constants ----------------
#define T_SEQ 2048
#define DIM   2048
#define NH    16
#define HD    128
#define FFN   8192
#define EPS_F 1.1920929e-07f
#define NEG_INF_F (-1e30f)

// ---------------- scratch (device globals; no runtime allocs) ----------------
__device__ __half g_xn  [(size_t)T_SEQ * DIM];     // fp16 rmsnorm output
__device__ float  g_qkv [(size_t)T_SEQ * 3 * DIM]; // [T, 48, 128] fp32
__device__ float  g_krot[(size_t)T_SEQ * NH * HD];
__device__ __half g_y   [(size_t)T_SEQ * DIM];     // fp16 attention output
__device__ float  g_x1  [(size_t)T_SEQ * DIM];
__device__ __half g_h   [(size_t)T_SEQ * FFN];     // fp16 MLP hidden
__device__ float  g_agate[(size_t)T_SEQ * NH];
__device__ float  g_vgate[(size_t)T_SEQ * NH];
__device__ __half g_wqkv[(size_t)4 * DIM * DIM];   // fp16 qkvo weights
__device__ __half g_wfc [(size_t)FFN * DIM];       // fp16 c_fc
__device__ __half g_wpT [(size_t)DIM * FFN];       // fp16 c_proj^T [DIM, FFN]

// ---------------- helpers ----------------
__device__ __forceinline__ float to_tf32(float x) {
    asm("cvt.rna.tf32.f32 %0, %1;" : "=f"(x) : "f"(x));
    return x;
}
__device__ __forceinline__ void cp_async16(uint32_t dst, const void* src) {
    asm volatile("cp.async.cg.shared.global [%0], [%1], 16;" :: "r"(dst), "l"(src));
}
__device__ __forceinline__ void cp_async_commit() {
    asm volatile("cp.async.commit_group;" ::: "memory");
}
template<int N>
__device__ __forceinline__ void cp_async_wait() {
    asm volatile("cp.async.wait_group %0;" :: "n"(N) : "memory");
}
__device__ __forceinline__ uint32_t smem_u32(const void* p) {
    uint32_t a;
    asm("{ .reg .u64 t; cvta.to.shared.u64 t, %1; cvt.u32.u64 %0, t; }" : "=r"(a) : "l"(p));
    return a;
}
__device__ __forceinline__ void ldsm_x4(uint32_t& r0, uint32_t& r1, uint32_t& r2, uint32_t& r3,
                                        uint32_t addr) {
    asm volatile("ldmatrix.sync.aligned.m8n8.x4.shared.b16 {%0,%1,%2,%3}, [%4];"
                 : "=r"(r0), "=r"(r1), "=r"(r2), "=r"(r3) : "r"(addr));
}
__device__ __forceinline__ void mma_f16(float& c0, float& c1, float& c2, float& c3,
                                        uint32_t a0, uint32_t a1, uint32_t a2, uint32_t a3,
                                        uint32_t b0, uint32_t b1) {
    asm volatile("mma.sync.aligned.m16n8k16.row.col.f32.f16.f16.f32 "
                 "{%0,%1,%2,%3}, {%4,%5,%6,%7}, {%8,%9}, {%0,%1,%2,%3};"
                 : "+f"(c0), "+f"(c1), "+f"(c2), "+f"(c3)
                 : "r"(a0), "r"(a1), "r"(a2), "r"(a3), "r"(b0), "r"(b1));
}
__device__ __forceinline__ void mma_tf32(float& c0, float& c1, float& c2, float& c3,
                                         uint32_t a0, uint32_t a1, uint32_t a2, uint32_t a3,
                                         uint32_t b0, uint32_t b1) {
    asm volatile("mma.sync.aligned.m16n8k8.row.col.f32.tf32.tf32.f32 "
                 "{%0,%1,%2,%3}, {%4,%5,%6,%7}, {%8,%9}, {%0,%1,%2,%3};"
                 : "+f"(c0), "+f"(c1), "+f"(c2), "+f"(c3)
                 : "r"(a0), "r"(a1), "r"(a2), "r"(a3), "r"(b0), "r"(b1));
}

// ================= fp16 warp-MMA GEMM =================
// C[M,N] = epi(alpha * A[M,K] @ B[N,K]^T), A/B fp16, accumulate fp32.
// BM=256 BN=128 BK=64, 256 threads (8 warps, 4x2 of 64x64 warp tiles),
// 4-stage cp.async pipeline + register double-buffered fragments.
#define GBM 256
#define GBN 128
#define GBK 64
#define GSTAGES 4
#define ROWH 72                               // halfs per smem row (144 B)
#define A_STAGE_B (GBM * ROWH * 2)            // 36864 bytes
#define B_STAGE_B (GBN * ROWH * 2)            // 18432 bytes
#define STAGE_B   (A_STAGE_B + B_STAGE_B)     // 55296 bytes
#define GEMM_SMEM (GSTAGES * STAGE_B)         // 221184 bytes

// EPI: 0=none->float, 1=relu^2->half, 2=add residual->float
template<int EPI>
__global__ void __launch_bounds__(256, 1)
f16_gemm_kernel(const __half* __restrict__ A, const __half* __restrict__ B,
                void* __restrict__ Cv, const float* __restrict__ addsrc,
                const float* __restrict__ alpha_ptr, int alpha_idx,
                int N, int K)
{
    extern __shared__ char smc[];
    const int tid = threadIdx.x;
    const int wid = tid >> 5, lane = tid & 31;
    const int g = lane >> 2, tig = lane & 3;
    const int wm = (wid & 3) * 64, wn = (wid >> 2) * 64;
    const int bn = blockIdx.x, bm = blockIdx.y;
    const int nk = K / GBK;
    const uint32_t sb = smem_u32(smc);

    const __half* Agm = A + (size_t)bm * GBM * K;
    const __half* Bgm = B + (size_t)bn * GBN * K;

    auto load_tile = [&](int stage, int ktile) {
        uint32_t sa = sb + stage * STAGE_B;
        uint32_t sB = sa + A_STAGE_B;
        int kt = ktile * GBK;
        #pragma unroll
        for (int i = 0; i < 8; i++) {                 // A: 256 rows x 8 chunks
            int c = tid + i * 256;
            int row = c >> 3, ch = c & 7;
            cp_async16(sa + (uint32_t)row * 144 + ch * 16,
                       Agm + (size_t)row * K + kt + ch * 8);
        }
        #pragma unroll
        for (int i = 0; i < 4; i++) {                 // B: 128 rows x 8 chunks
            int c = tid + i * 256;
            int row = c >> 3, ch = c & 7;
            cp_async16(sB + (uint32_t)row * 144 + ch * 16,
                       Bgm + (size_t)row * K + kt + ch * 8);
        }
    };

    // per-thread ldmatrix byte offsets (within a stage)
    uint32_t aoff[4], boff[4];
    #pragma unroll
    for (int mt = 0; mt < 4; mt++)
        aoff[mt] = (uint32_t)(wm + mt * 16 + (lane & 7) + ((lane >> 3) & 1) * 8) * 144
                 + ((lane >> 4) & 1) * 16;
    #pragma unroll
    for (int nb = 0; nb < 4; nb++)
        boff[nb] = (uint32_t)(wn + nb * 16 + (lane & 7) + ((lane >> 4) & 1) * 8) * 144
                 + ((lane >> 3) & 1) * 16;

    float acc[4][8][4];
    #pragma unroll
    for (int mt = 0; mt < 4; mt++)
        #pragma unroll
        for (int nt = 0; nt < 8; nt++)
            #pragma unroll
            for (int q = 0; q < 4; q++) acc[mt][nt][q] = 0.f;

    #pragma unroll
    for (int s = 0; s < GSTAGES - 1; s++) { load_tile(s, s); cp_async_commit(); }

    uint32_t af[2][4][4], bf[2][4][4];

    for (int k = 0; k < nk; k++) {
        cp_async_wait<GSTAGES - 2>();
        __syncthreads();
        // issue next tile's loads first (stage freed at k-1)
        if (k + GSTAGES - 1 < nk) load_tile((k + GSTAGES - 1) & (GSTAGES - 1),
                                            k + GSTAGES - 1);
        cp_async_commit();

        uint32_t sa = sb + (k & (GSTAGES - 1)) * STAGE_B;
        uint32_t sB = sa + A_STAGE_B;

        // prefetch ks=0 fragments
        #pragma unroll
        for (int mt = 0; mt < 4; mt++)
            ldsm_x4(af[0][mt][0], af[0][mt][1], af[0][mt][2], af[0][mt][3],
                    sa + aoff[mt]);
        #pragma unroll
        for (int nb = 0; nb < 4; nb++)
            ldsm_x4(bf[0][nb][0], bf[0][nb][1], bf[0][nb][2], bf[0][nb][3],
                    sB + boff[nb]);

        #pragma unroll
        for (int ks = 0; ks < 4; ks++) {
            const int cur = ks & 1, nxt = cur ^ 1;
            if (ks < 3) {                          // prefetch ks+1 fragments
                const uint32_t kb = (ks + 1) * 32;
                #pragma unroll
                for (int mt = 0; mt < 4; mt++)
                    ldsm_x4(af[nxt][mt][0], af[nxt][mt][1], af[nxt][mt][2], af[nxt][mt][3],
                            sa + aoff[mt] + kb);
                #pragma unroll
                for (int nb = 0; nb < 4; nb++)
                    ldsm_x4(bf[nxt][nb][0], bf[nxt][nb][1], bf[nxt][nb][2], bf[nxt][nb][3],
                            sB + boff[nb] + kb);
            }
            #pragma unroll
            for (int nb = 0; nb < 4; nb++) {
                #pragma unroll
                for (int mt = 0; mt < 4; mt++) {
                    mma_f16(acc[mt][2 * nb][0], acc[mt][2 * nb][1],
                            acc[mt][2 * nb][2], acc[mt][2 * nb][3],
                            af[cur][mt][0], af[cur][mt][1], af[cur][mt][2], af[cur][mt][3],
                            bf[cur][nb][0], bf[cur][nb][1]);
                    mma_f16(acc[mt][2 * nb + 1][0], acc[mt][2 * nb + 1][1],
                            acc[mt][2 * nb + 1][2], acc[mt][2 * nb + 1][3],
                            af[cur][mt][0], af[cur][mt][1], af[cur][mt][2], af[cur][mt][3],
                            bf[cur][nb][2], bf[cur][nb][3]);
                }
            }
        }
    }

    float alpha = alpha_ptr ? alpha_ptr[alpha_idx] : 1.0f;
    #pragma unroll
    for (int mt = 0; mt < 4; mt++) {
        #pragma unroll
        for (int half_i = 0; half_i < 2; half_i++) {
            int row = bm * GBM + wm + mt * 16 + g + half_i * 8;
            #pragma unroll
            for (int nt = 0; nt < 8; nt++) {
                int col = bn * GBN + wn + nt * 8 + tig * 2;
                float vx = acc[mt][nt][half_i * 2 + 0] * alpha;
                float vy = acc[mt][nt][half_i * 2 + 1] * alpha;
                size_t idx = (size_t)row * N + col;
                if (EPI == 1) {
                    vx = fmaxf(vx, 0.f); vx = vx * vx;
                    vy = fmaxf(vy, 0.f); vy = vy * vy;
                    *(__half2*)((__half*)Cv + idx) = __floats2half2_rn(vx, vy);
                } else if (EPI == 2) {
                    float2 a2 = *(const float2*)&addsrc[idx];
                    float2 v; v.x = vx + a2.x; v.y = vy + a2.y;
                    *(float2*)((float*)Cv + idx) = v;
                } else {
                    float2 v; v.x = vx; v.y = vy;
                    *(float2*)((float*)Cv + idx) = v;
                }
            }
        }
    }
}

// ---------------- weight conversion kernels ----------------
__global__ void __launch_bounds__(256) round_f16_kernel(const float* __restrict__ in,
                                                        __half* __restrict__ outp, int n8) {
    int i = blockIdx.x * 256 + threadIdx.x;
    if (i < n8) {
        float4 v0 = ((const float4*)in)[2 * i];
        float4 v1 = ((const float4*)in)[2 * i + 1];
        __half2 h0 = __floats2half2_rn(v0.x, v0.y);
        __half2 h1 = __floats2half2_rn(v0.z, v0.w);
        __half2 h2 = __floats2half2_rn(v1.x, v1.y);
        __half2 h3 = __floats2half2_rn(v1.z, v1.w);
        uint4 o;
        o.x = *(uint32_t*)&h0; o.y = *(uint32_t*)&h1;
        o.z = *(uint32_t*)&h2; o.w = *(uint32_t*)&h3;
        ((uint4*)outp)[i] = o;
    }
}
// out[DIM, FFN] (fp16) = in[FFN, DIM]^T
__global__ void __launch_bounds__(256) transpose_f16_kernel(const float* __restrict__ in,
                                                            __half* __restrict__ outp) {
    __shared__ float t[32][33];
    int bx = blockIdx.x;   // over DIM/32
    int by = blockIdx.y;   // over FFN/32
    int x = threadIdx.x, y = threadIdx.y;    // 32 x 8
    #pragma unroll
    for (int i = 0; i < 32; i += 8)
        t[y + i][x] = in[(size_t)(by * 32 + y + i) * DIM + bx * 32 + x];
    __syncthreads();
    #pragma unroll
    for (int i = 0; i < 32; i += 8)
        outp[(size_t)(bx * 32 + y + i) * FFN + by * 32 + x] = __float2half_rn(t[x][y + i]);
}

// ---------------- RMSNorm (fp16 output) ----------------
__global__ void __launch_bounds__(256) rmsnorm_kernel(const float* __restrict__ in,
                                                      __half* __restrict__ outp) {
    int t = blockIdx.x;
    const float* r = in + (size_t)t * DIM;
    float ss = 0.f;
    float vals[8];
    #pragma unroll
    for (int j = 0; j < 8; j++) {
        float v = r[threadIdx.x + j * 256];
        vals[j] = v; ss += v * v;
    }
    __shared__ float sred[8];
    for (int o = 16; o; o >>= 1) ss += __shfl_xor_sync(0xffffffffu, ss, o);
    if ((threadIdx.x & 31) == 0) sred[threadIdx.x >> 5] = ss;
    __syncthreads();
    float tot = 0.f;
    #pragma unroll
    for (int i = 0; i < 8; i++) tot += sred[i];
    float scale = rsqrtf(tot / (float)DIM + EPS_F);
    #pragma unroll
    for (int j = 0; j < 8; j++)
        outp[(size_t)t * DIM + threadIdx.x + j * 256] = __float2half_rn(vals[j] * scale);
}

// ---------------- per-(t, head-slot) QK rmsnorm + rotary (tf32-rounded out) ----------------
__global__ void __launch_bounds__(128) qkrot_kernel(
    float* __restrict__ qkv, float* __restrict__ krot,
    const float* __restrict__ cosb, const float* __restrict__ sinb)
{
    int hs = blockIdx.x;
    int t  = blockIdx.y;
    int d  = threadIdx.x;
    float v = qkv[((size_t)t * 48 + hs) * HD + d];
    __shared__ float sm[HD];
    __shared__ float red[4];
    float ss = v * v;
    for (int o = 16; o; o >>= 1) ss += __shfl_xor_sync(0xffffffffu, ss, o);
    if ((d & 31) == 0) red[d >> 5] = ss;
    __syncthreads();
    float tot = red[0] + red[1] + red[2] + red[3];
    float n = v * rsqrtf(tot / (float)HD + EPS_F);
    sm[d] = n;
    __syncthreads();
    float o;
    if (d < 64) {
        float c = cosb[t * 64 + d], s = sinb[t * 64 + d];
        o = sm[d] * c + sm[d + 64] * s;
    } else {
        float c = cosb[t * 64 + d - 64], s = sinb[t * 64 + d - 64];
        o = -sm[d - 64] * s + sm[d] * c;
    }
    o = to_tf32(o);
    if (hs < 16) qkv[((size_t)t * 48 + hs) * HD + d] = o;
    else         krot[((size_t)t * NH + (hs - 16)) * HD + d] = o;
}

// ---------------- fused key-offset shift + v update ----------------
// first T*NH*HD ids: k shift; second: v = round_tf32(v + gate*ve)
__global__ void __launch_bounds__(256) kv_post_kernel(
    const float* __restrict__ krot, float* __restrict__ qkv,
    const float* __restrict__ ve, const float* __restrict__ vgate,
    const int* __restrict__ key_offset)
{
    int idx = blockIdx.x * 256 + threadIdx.x;
    int half_sel = idx >= T_SEQ * NH * HD;
    int id = idx - half_sel * (T_SEQ * NH * HD);
    int d = id & 127;
    int h = (id >> 7) & 15;
    int t = id >> 11;
    if (!half_sel) {
        int ko = key_offset[0];
        bool up = (d >= 32 && d < 64) || (d >= 96);
        int st = (ko && up && t > 0) ? (t - 1) : t;
        qkv[((size_t)t * 48 + 16 + h) * HD + d] = krot[((size_t)st * NH + h) * HD + d];
    } else {
        float gv = vgate[t * NH + h];
        size_t o = ((size_t)t * 48 + 32 + h) * HD + d;
        qkv[o] = to_tf32(qkv[o] + gv * ve[id]);
    }
}

// ---------------- gate logits (xn is fp16) ----------------
__global__ void __launch_bounds__(256) gates_kernel(
    const __half* __restrict__ xn, const float* __restrict__ agw,
    const float* __restrict__ vgw, float* __restrict__ agate,
    float* __restrict__ vgate)
{
    int t = blockIdx.x;
    int w = threadIdx.x >> 5, lane = threadIdx.x & 31;
    const __half* xr = xn + (size_t)t * DIM;
    float acc[4] = {};
    const float* wbase[4];
    #pragma unroll
    for (int q = 0; q < 4; q++) {
        int o = w * 4 + q;
        wbase[q] = (o < 16) ? (agw + (size_t)o * DIM) : (vgw + (size_t)(o - 16) * DIM);
    }
    for (int dd = lane; dd < DIM; dd += 32) {
        float xv = __half2float(xr[dd]);
        #pragma unroll
        for (int q = 0; q < 4; q++) acc[q] = fmaf(xv, wbase[q][dd], acc[q]);
    }
    #pragma unroll
    for (int q = 0; q < 4; q++)
        for (int o2 = 16; o2; o2 >>= 1) acc[q] += __shfl_xor_sync(0xffffffffu, acc[q], o2);
    if (lane == 0) {
        #pragma unroll
        for (int q = 0; q < 4; q++) {
            int o = w * 4 + q;
            float gg = 1.f / (1.f + expf(-acc[q]));
            if (o < 16) agate[t * NH + o] = gg;
            else        vgate[t * NH + (o - 16)] = gg;
        }
    }
}

// ================= MMA flash attention (tf32, fp16 y output) =================
#define ROWP 132
#define FL_SMEM ((3 * 64 * ROWP + 64) * 4)

__global__ void __launch_bounds__(128) flash_mma_kernel(
    const float* __restrict__ qkv, const int* __restrict__ docs,
    const float* __restrict__ attn_scale, const float* __restrict__ agate,
    __half* __restrict__ y)
{
    extern __shared__ float fs[];
    float* Qs = fs;
    float* Ks = fs + 64 * ROWP;
    float* Vs = fs + 2 * 64 * ROWP;
    int*   kd = (int*)(fs + 3 * 64 * ROWP);

    const int tid = threadIdx.x, wid = tid >> 5, lane = tid & 31;
    const int g = lane >> 2, tig = lane & 3;
    const int h = blockIdx.y;
    const int qi = (int)gridDim.x - 1 - (int)blockIdx.x;
    const int qbase = qi * 64;
    const float scale = attn_scale[0];

    #pragma unroll
    for (int i = 0; i < 16; i++) {
        int c = tid + i * 128;
        int r = c >> 5, co = (c & 31) * 4;
        float4 f = *(const float4*)&qkv[((size_t)(qbase + r) * 48 + h) * HD + co];
        *(float4*)&Qs[r * ROWP + co] = f;
    }
    const int rg0 = qbase + wid * 16 + g;
    const int rg1 = rg0 + 8;
    const int qd0 = docs[rg0], qd1 = docs[rg1];
    const int qdmin = docs[qbase];

    float o[16][4] = {};
    float m0 = NEG_INF_F, m1 = NEG_INF_F, l0 = 0.f, l1 = 0.f;
    __syncthreads();

    for (int kb = 0; kb <= qi; kb++) {
        const int kbase = kb * 64;
        if (docs[kbase + 63] < qdmin) continue;
        __syncthreads();
        #pragma unroll
        for (int i = 0; i < 16; i++) {
            int c = tid + i * 128;
            int r = c >> 5, co = (c & 31) * 4;
            float4 f = *(const float4*)&qkv[((size_t)(kbase + r) * 48 + 16 + h) * HD + co];
            *(float4*)&Ks[r * ROWP + co] = f;
            float4 v4 = *(const float4*)&qkv[((size_t)(kbase + r) * 48 + 32 + h) * HD + co];
            *(float4*)&Vs[r * ROWP + co] = v4;
        }
        if (tid < 64) kd[tid] = docs[kbase + tid];
        __syncthreads();

        float s[8][4] = {};
        #pragma unroll
        for (int ks = 0; ks < 16; ks++) {
            const int k0 = ks * 8;
            uint32_t a0 = __float_as_uint(Qs[(wid * 16 + g) * ROWP + k0 + tig]);
            uint32_t a1 = __float_as_uint(Qs[(wid * 16 + g + 8) * ROWP + k0 + tig]);
            uint32_t a2 = __float_as_uint(Qs[(wid * 16 + g) * ROWP + k0 + tig + 4]);
            uint32_t a3 = __float_as_uint(Qs[(wid * 16 + g + 8) * ROWP + k0 + tig + 4]);
            #pragma unroll
            for (int nt = 0; nt < 8; nt++) {
                uint32_t b0 = __float_as_uint(Ks[(nt * 8 + g) * ROWP + k0 + tig]);
                uint32_t b1 = __float_as_uint(Ks[(nt * 8 + g) * ROWP + k0 + tig + 4]);
                mma_tf32(s[nt][0], s[nt][1], s[nt][2], s[nt][3], a0, a1, a2, a3, b0, b1);
            }
        }

        float mx0 = m0, mx1 = m1;
        #pragma unroll
        for (int nt = 0; nt < 8; nt++) {
            int c0i = kbase + nt * 8 + 2 * tig;
            int d0 = kd[nt * 8 + 2 * tig], d1 = kd[nt * 8 + 2 * tig + 1];
            float v00 = (c0i     <= rg0 && d0 == qd0) ? s[nt][0] * scale : NEG_INF_F;
            float v01 = (c0i + 1 <= rg0 && d1 == qd0) ? s[nt][1] * scale : NEG_INF_F;
            float v10 = (c0i     <= rg1 && d0 == qd1) ? s[nt][2] * scale : NEG_INF_F;
            float v11 = (c0i + 1 <= rg1 && d1 == qd1) ? s[nt][3] * scale : NEG_INF_F;
            s[nt][0] = v00; s[nt][1] = v01; s[nt][2] = v10; s[nt][3] = v11;
            mx0 = fmaxf(mx0, fmaxf(v00, v01));
            mx1 = fmaxf(mx1, fmaxf(v10, v11));
        }
        mx0 = fmaxf(mx0, __shfl_xor_sync(0xffffffffu, mx0, 1));
        mx0 = fmaxf(mx0, __shfl_xor_sync(0xffffffffu, mx0, 2));
        mx1 = fmaxf(mx1, __shfl_xor_sync(0xffffffffu, mx1, 1));
        mx1 = fmaxf(mx1, __shfl_xor_sync(0xffffffffu, mx1, 2));
        float al0 = __expf(m0 - mx0), al1 = __expf(m1 - mx1);
        m0 = mx0; m1 = mx1;

        float sum0 = 0.f, sum1 = 0.f;
        #pragma unroll
        for (int nt = 0; nt < 8; nt++) {
            float p00 = __expf(s[nt][0] - m0);
            float p01 = __expf(s[nt][1] - m0);
            float p10 = __expf(s[nt][2] - m1);
            float p11 = __expf(s[nt][3] - m1);
            sum0 += p00 + p01; sum1 += p10 + p11;
            s[nt][0] = to_tf32(p00); s[nt][1] = to_tf32(p01);
            s[nt][2] = to_tf32(p10); s[nt][3] = to_tf32(p11);
        }
        sum0 += __shfl_xor_sync(0xffffffffu, sum0, 1);
        sum0 += __shfl_xor_sync(0xffffffffu, sum0, 2);
        sum1 += __shfl_xor_sync(0xffffffffu, sum1, 1);
        sum1 += __shfl_xor_sync(0xffffffffu, sum1, 2);
        l0 = l0 * al0 + sum0;
        l1 = l1 * al1 + sum1;
        #pragma unroll
        for (int nt = 0; nt < 16; nt++) {
            o[nt][0] *= al0; o[nt][1] *= al0;
            o[nt][2] *= al1; o[nt][3] *= al1;
        }

        #pragma unroll
        for (int kc = 0; kc < 8; kc++) {
            int src = (g << 2) | (tig >> 1);
            float x0 = __shfl_sync(0xffffffffu, s[kc][0], src);
            float x1 = __shfl_sync(0xffffffffu, s[kc][1], src);
            float x2 = __shfl_sync(0xffffffffu, s[kc][2], src);
            float x3 = __shfl_sync(0xffffffffu, s[kc][3], src);
            float z0 = __shfl_sync(0xffffffffu, s[kc][0], src + 2);
            float z1 = __shfl_sync(0xffffffffu, s[kc][1], src + 2);
            float z2 = __shfl_sync(0xffffffffu, s[kc][2], src + 2);
            float z3 = __shfl_sync(0xffffffffu, s[kc][3], src + 2);
            bool odd = (tig & 1) != 0;
            uint32_t a0 = __float_as_uint(odd ? x1 : x0);
            uint32_t a1 = __float_as_uint(odd ? x3 : x2);
            uint32_t a2 = __float_as_uint(odd ? z1 : z0);
            uint32_t a3 = __float_as_uint(odd ? z3 : z2);
            #pragma unroll
            for (int nt = 0; nt < 16; nt++) {
                uint32_t b0 = __float_as_uint(Vs[(kc * 8 + tig) * ROWP + nt * 8 + g]);
                uint32_t b1 = __float_as_uint(Vs[(kc * 8 + tig + 4) * ROWP + nt * 8 + g]);
                mma_tf32(o[nt][0], o[nt][1], o[nt][2], o[nt][3], a0, a1, a2, a3, b0, b1);
            }
        }
    }

    float f0 = (1.f / l0) * agate[rg0 * NH + h];
    float f1 = (1.f / l1) * agate[rg1 * NH + h];
    #pragma unroll
    for (int nt = 0; nt < 16; nt++) {
        *(__half2*)&y[(size_t)rg0 * DIM + h * HD + nt * 8 + 2 * tig] =
            __floats2half2_rn(o[nt][0] * f0, o[nt][1] * f0);
        *(__half2*)&y[(size_t)rg1 * DIM + h * HD + nt * 8 + 2 * tig] =
            __floats2half2_rn(o[nt][2] * f1, o[nt][3] * f1);
    }
}

// ---------------- launch ----------------
extern "C" void kernel_launch(void* const* d_in, const int* in_sizes, int n_in,
                              void* d_out, int out_size) {
    const float* x           = (const float*)d_in[0];
    const float* ve          = (const float*)d_in[1];
    const float* qkvo_w      = (const float*)d_in[2];
    const float* attn_gate_w = (const float*)d_in[3];
    const float* ve_gate_w   = (const float*)d_in[4];
    const float* c_fc        = (const float*)d_in[5];
    const float* c_proj      = (const float*)d_in[6];
    const float* sa_lambdas  = (const float*)d_in[7];
    const float* cosb        = (const float*)d_in[8];
    const float* sinb        = (const float*)d_in[9];
    const float* attn_scale  = (const float*)d_in[10];
    const int*   docs        = (const int*)d_in[11];
    const int*   key_offset  = (const int*)d_in[12];
    float*       out         = (float*)d_out;

    __half *xn, *y, *hbuf, *wqkv, *wfc, *wpT;
    float *qkv, *krot, *x1, *agate, *vgate;
    cudaGetSymbolAddress((void**)&xn,    g_xn);
    cudaGetSymbolAddress((void**)&qkv,   g_qkv);
    cudaGetSymbolAddress((void**)&krot,  g_krot);
    cudaGetSymbolAddress((void**)&y,     g_y);
    cudaGetSymbolAddress((void**)&x1,    g_x1);
    cudaGetSymbolAddress((void**)&hbuf,  g_h);
    cudaGetSymbolAddress((void**)&agate, g_agate);
    cudaGetSymbolAddress((void**)&vgate, g_vgate);
    cudaGetSymbolAddress((void**)&wqkv,  g_wqkv);
    cudaGetSymbolAddress((void**)&wfc,   g_wfc);
    cudaGetSymbolAddress((void**)&wpT,   g_wpT);

    cudaFuncSetAttribute(flash_mma_kernel, cudaFuncAttributeMaxDynamicSharedMemorySize,
                         FL_SMEM);
    cudaFuncSetAttribute(f16_gemm_kernel<0>, cudaFuncAttributeMaxDynamicSharedMemorySize,
                         GEMM_SMEM);
    cudaFuncSetAttribute(f16_gemm_kernel<1>, cudaFuncAttributeMaxDynamicSharedMemorySize,
                         GEMM_SMEM);
    cudaFuncSetAttribute(f16_gemm_kernel<2>, cudaFuncAttributeMaxDynamicSharedMemorySize,
                         GEMM_SMEM);

    // weight conversions (fp16 copies; c_proj also transposed to [N,K])
    round_f16_kernel<<<(4 * DIM * DIM / 8 + 255) / 256, 256>>>(qkvo_w, wqkv, 4 * DIM * DIM / 8);
    round_f16_kernel<<<((size_t)FFN * DIM / 8 + 255) / 256, 256>>>(c_fc, wfc, FFN * DIM / 8);
    transpose_f16_kernel<<<dim3(DIM / 32, FFN / 32), dim3(32, 8)>>>(c_proj, wpT);

    // 1. xn = fp16(rmsnorm(x))
    rmsnorm_kernel<<<T_SEQ, 256>>>(x, xn);
    // 2. qkv = lam0 * xn @ Wqkv^T   (fp32 out)
    f16_gemm_kernel<0><<<dim3(3 * DIM / GBN, T_SEQ / GBM), 256, GEMM_SMEM>>>(
        xn, wqkv, qkv, nullptr, sa_lambdas, 0, 3 * DIM, DIM);
    // 3. per-head rmsnorm + rotary
    qkrot_kernel<<<dim3(32, T_SEQ), 128>>>(qkv, krot, cosb, sinb);
    // 4. gates
    gates_kernel<<<T_SEQ, 256>>>(xn, attn_gate_w, ve_gate_w, agate, vgate);
    // 5. fused key-offset shift + v update
    kv_post_kernel<<<(2 * T_SEQ * NH * HD) / 256, 256>>>(krot, qkv, ve, vgate, key_offset);
    // 6. MMA flash attention (fp16 y out)
    flash_mma_kernel<<<dim3(T_SEQ / 64, NH), 128, FL_SMEM>>>(
        qkv, docs, attn_scale, agate, y);
    // 7. x1 = x + lam1 * y @ Wo^T
    f16_gemm_kernel<2><<<dim3(DIM / GBN, T_SEQ / GBM), 256, GEMM_SMEM>>>(
        y, wqkv + (size_t)3 * DIM * DIM, x1, x, sa_lambdas, 1, DIM, DIM);
    // 8. xn = fp16(rmsnorm(x1))
    rmsnorm_kernel<<<T_SEQ, 256>>>(x1, xn);
    // 9. h = fp16(relu(xn @ c_fc^T)^2)
    f16_gemm_kernel<1><<<dim3(FFN / GBN, T_SEQ / GBM), 256, GEMM_SMEM>>>(
        xn, wfc, hbuf, nullptr, nullptr, 0, FFN, DIM);
    // 10. out = x1 + h @ c_proj   (via c_proj^T, K=8192)
    f16_gemm_kernel<2><<<dim3(DIM / GBN, T_SEQ / GBM), 256, GEMM_SMEM>>>(
        hbuf, wpT, out, x1, nullptr, 0, DIM, FFN);
}

// round 9
// speedup vs baseline: 7.6249x; 1.0018x over previous
#include <cuda_runtime.h>
#include <cuda_fp16.h>
#include <cstdint>
#include <cstddef>

// ---------------- problem constants ----------------
#define T_SEQ 2048
#define DIM   2048
#define NH    16
#define HD    128
#define FFN   8192
#define EPS_F 1.1920929e-07f
#define NEG_INF_F (-1e30f)

// ---------------- scratch (device globals; no runtime allocs) ----------------
__device__ __half g_xn  [(size_t)T_SEQ * DIM];     // fp16 rmsnorm output
__device__ float  g_qkv [(size_t)T_SEQ * 3 * DIM]; // [T, 48, 128] fp32
__device__ float  g_krot[(size_t)T_SEQ * NH * HD];
__device__ __half g_y   [(size_t)T_SEQ * DIM];     // fp16 attention output
__device__ float  g_x1  [(size_t)T_SEQ * DIM];
__device__ __half g_h   [(size_t)T_SEQ * FFN];     // fp16 MLP hidden
__device__ float  g_agate[(size_t)T_SEQ * NH];
__device__ float  g_vgate[(size_t)T_SEQ * NH];
__device__ __half g_wqkv[(size_t)4 * DIM * DIM];   // fp16 qkvo weights
__device__ __half g_wfc [(size_t)FFN * DIM];       // fp16 c_fc
__device__ __half g_wpT [(size_t)DIM * FFN];       // fp16 c_proj^T [DIM, FFN]

// ---------------- helpers ----------------
__device__ __forceinline__ float to_tf32(float x) {
    asm("cvt.rna.tf32.f32 %0, %1;" : "=f"(x) : "f"(x));
    return x;
}
__device__ __forceinline__ void cp_async16(uint32_t dst, const void* src) {
    asm volatile("cp.async.cg.shared.global [%0], [%1], 16;" :: "r"(dst), "l"(src));
}
__device__ __forceinline__ void cp_async_commit() {
    asm volatile("cp.async.commit_group;" ::: "memory");
}
template<int N>
__device__ __forceinline__ void cp_async_wait() {
    asm volatile("cp.async.wait_group %0;" :: "n"(N) : "memory");
}
__device__ __forceinline__ uint32_t smem_u32(const void* p) {
    uint32_t a;
    asm("{ .reg .u64 t; cvta.to.shared.u64 t, %1; cvt.u32.u64 %0, t; }" : "=r"(a) : "l"(p));
    return a;
}
__device__ __forceinline__ void ldsm_x4(uint32_t& r0, uint32_t& r1, uint32_t& r2, uint32_t& r3,
                                        uint32_t addr) {
    asm volatile("ldmatrix.sync.aligned.m8n8.x4.shared.b16 {%0,%1,%2,%3}, [%4];"
                 : "=r"(r0), "=r"(r1), "=r"(r2), "=r"(r3) : "r"(addr));
}
__device__ __forceinline__ void mma_f16(float& c0, float& c1, float& c2, float& c3,
                                        uint32_t a0, uint32_t a1, uint32_t a2, uint32_t a3,
                                        uint32_t b0, uint32_t b1) {
    asm volatile("mma.sync.aligned.m16n8k16.row.col.f32.f16.f16.f32 "
                 "{%0,%1,%2,%3}, {%4,%5,%6,%7}, {%8,%9}, {%0,%1,%2,%3};"
                 : "+f"(c0), "+f"(c1), "+f"(c2), "+f"(c3)
                 : "r"(a0), "r"(a1), "r"(a2), "r"(a3), "r"(b0), "r"(b1));
}
__device__ __forceinline__ void mma_tf32(float& c0, float& c1, float& c2, float& c3,
                                         uint32_t a0, uint32_t a1, uint32_t a2, uint32_t a3,
                                         uint32_t b0, uint32_t b1) {
    asm volatile("mma.sync.aligned.m16n8k8.row.col.f32.tf32.tf32.f32 "
                 "{%0,%1,%2,%3}, {%4,%5,%6,%7}, {%8,%9}, {%0,%1,%2,%3};"
                 : "+f"(c0), "+f"(c1), "+f"(c2), "+f"(c3)
                 : "r"(a0), "r"(a1), "r"(a2), "r"(a3), "r"(b0), "r"(b1));
}

// ================= fp16 warp-MMA GEMM =================
// C[M,N] = epi(alpha * A[M,K] @ B[N,K]^T), A/B fp16, accumulate fp32.
// BM=256 BN=128 BK=64, 512 threads (16 warps, 4x4 grid of 64x32 warp tiles),
// 4-stage cp.async pipeline. 4 warps/SMSP to cover HMMA pipe latency.
#define GBM 256
#define GBN 128
#define GBK 64
#define GSTAGES 4
#define ROWH 72                               // halfs per smem row (144 B)
#define A_STAGE_B (GBM * ROWH * 2)            // 36864 bytes
#define B_STAGE_B (GBN * ROWH * 2)            // 18432 bytes
#define STAGE_B   (A_STAGE_B + B_STAGE_B)     // 55296 bytes
#define GEMM_SMEM (GSTAGES * STAGE_B)         // 221184 bytes

// EPI: 0=none->float, 1=relu^2->half, 2=add residual->float
template<int EPI>
__global__ void __launch_bounds__(512, 1)
f16_gemm_kernel(const __half* __restrict__ A, const __half* __restrict__ B,
                void* __restrict__ Cv, const float* __restrict__ addsrc,
                const float* __restrict__ alpha_ptr, int alpha_idx,
                int N, int K)
{
    extern __shared__ char smc[];
    const int tid = threadIdx.x;
    const int wid = tid >> 5, lane = tid & 31;
    const int g = lane >> 2, tig = lane & 3;
    const int wm = (wid & 3) * 64, wn = (wid >> 2) * 32;
    const int bn = blockIdx.x, bm = blockIdx.y;
    const int nk = K / GBK;
    const uint32_t sb = smem_u32(smc);

    const __half* Agm = A + (size_t)bm * GBM * K;
    const __half* Bgm = B + (size_t)bn * GBN * K;

    auto load_tile = [&](int stage, int ktile) {
        uint32_t sa = sb + stage * STAGE_B;
        uint32_t sB = sa + A_STAGE_B;
        int kt = ktile * GBK;
        #pragma unroll
        for (int i = 0; i < 4; i++) {                 // A: 256 rows x 8 chunks
            int c = tid + i * 512;
            int row = c >> 3, ch = c & 7;
            cp_async16(sa + (uint32_t)row * 144 + ch * 16,
                       Agm + (size_t)row * K + kt + ch * 8);
        }
        #pragma unroll
        for (int i = 0; i < 2; i++) {                 // B: 128 rows x 8 chunks
            int c = tid + i * 512;
            int row = c >> 3, ch = c & 7;
            cp_async16(sB + (uint32_t)row * 144 + ch * 16,
                       Bgm + (size_t)row * K + kt + ch * 8);
        }
    };

    // per-thread ldmatrix byte offsets (within a stage)
    uint32_t aoff[4], boff[2];
    #pragma unroll
    for (int mt = 0; mt < 4; mt++)
        aoff[mt] = (uint32_t)(wm + mt * 16 + (lane & 7) + ((lane >> 3) & 1) * 8) * 144
                 + ((lane >> 4) & 1) * 16;
    #pragma unroll
    for (int nb = 0; nb < 2; nb++)
        boff[nb] = (uint32_t)(wn + nb * 16 + (lane & 7) + ((lane >> 4) & 1) * 8) * 144
                 + ((lane >> 3) & 1) * 16;

    float acc[4][4][4];
    #pragma unroll
    for (int mt = 0; mt < 4; mt++)
        #pragma unroll
        for (int nt = 0; nt < 4; nt++)
            #pragma unroll
            for (int q = 0; q < 4; q++) acc[mt][nt][q] = 0.f;

    #pragma unroll
    for (int s = 0; s < GSTAGES - 1; s++) { load_tile(s, s); cp_async_commit(); }

    for (int k = 0; k < nk; k++) {
        cp_async_wait<GSTAGES - 2>();
        __syncthreads();
        // issue next tile's loads first (stage freed at k-1)
        if (k + GSTAGES - 1 < nk) load_tile((k + GSTAGES - 1) & (GSTAGES - 1),
                                            k + GSTAGES - 1);
        cp_async_commit();

        uint32_t sa = sb + (k & (GSTAGES - 1)) * STAGE_B;
        uint32_t sB = sa + A_STAGE_B;

        #pragma unroll
        for (int ks = 0; ks < 4; ks++) {              // 4 x k16 = BK 64
            const uint32_t kb = ks * 32;              // 16 halfs = 32 bytes
            uint32_t a[4][4];
            #pragma unroll
            for (int mt = 0; mt < 4; mt++)
                ldsm_x4(a[mt][0], a[mt][1], a[mt][2], a[mt][3], sa + aoff[mt] + kb);
            #pragma unroll
            for (int nb = 0; nb < 2; nb++) {
                uint32_t b0, b1, b2, b3;
                ldsm_x4(b0, b1, b2, b3, sB + boff[nb] + kb);
                #pragma unroll
                for (int mt = 0; mt < 4; mt++) {
                    mma_f16(acc[mt][2 * nb][0], acc[mt][2 * nb][1],
                            acc[mt][2 * nb][2], acc[mt][2 * nb][3],
                            a[mt][0], a[mt][1], a[mt][2], a[mt][3], b0, b1);
                    mma_f16(acc[mt][2 * nb + 1][0], acc[mt][2 * nb + 1][1],
                            acc[mt][2 * nb + 1][2], acc[mt][2 * nb + 1][3],
                            a[mt][0], a[mt][1], a[mt][2], a[mt][3], b2, b3);
                }
            }
        }
    }

    float alpha = alpha_ptr ? alpha_ptr[alpha_idx] : 1.0f;
    #pragma unroll
    for (int mt = 0; mt < 4; mt++) {
        #pragma unroll
        for (int half_i = 0; half_i < 2; half_i++) {
            int row = bm * GBM + wm + mt * 16 + g + half_i * 8;
            #pragma unroll
            for (int nt = 0; nt < 4; nt++) {
                int col = bn * GBN + wn + nt * 8 + tig * 2;
                float vx = acc[mt][nt][half_i * 2 + 0] * alpha;
                float vy = acc[mt][nt][half_i * 2 + 1] * alpha;
                size_t idx = (size_t)row * N + col;
                if (EPI == 1) {
                    vx = fmaxf(vx, 0.f); vx = vx * vx;
                    vy = fmaxf(vy, 0.f); vy = vy * vy;
                    *(__half2*)((__half*)Cv + idx) = __floats2half2_rn(vx, vy);
                } else if (EPI == 2) {
                    float2 a2 = *(const float2*)&addsrc[idx];
                    float2 v; v.x = vx + a2.x; v.y = vy + a2.y;
                    *(float2*)((float*)Cv + idx) = v;
                } else {
                    float2 v; v.x = vx; v.y = vy;
                    *(float2*)((float*)Cv + idx) = v;
                }
            }
        }
    }
}

// ---------------- weight conversion kernels ----------------
__global__ void __launch_bounds__(256) round_f16_kernel(const float* __restrict__ in,
                                                        __half* __restrict__ outp, int n8) {
    int i = blockIdx.x * 256 + threadIdx.x;
    if (i < n8) {
        float4 v0 = ((const float4*)in)[2 * i];
        float4 v1 = ((const float4*)in)[2 * i + 1];
        __half2 h0 = __floats2half2_rn(v0.x, v0.y);
        __half2 h1 = __floats2half2_rn(v0.z, v0.w);
        __half2 h2 = __floats2half2_rn(v1.x, v1.y);
        __half2 h3 = __floats2half2_rn(v1.z, v1.w);
        uint4 o;
        o.x = *(uint32_t*)&h0; o.y = *(uint32_t*)&h1;
        o.z = *(uint32_t*)&h2; o.w = *(uint32_t*)&h3;
        ((uint4*)outp)[i] = o;
    }
}
// out[DIM, FFN] (fp16) = in[FFN, DIM]^T
__global__ void __launch_bounds__(256) transpose_f16_kernel(const float* __restrict__ in,
                                                            __half* __restrict__ outp) {
    __shared__ float t[32][33];
    int bx = blockIdx.x;   // over DIM/32
    int by = blockIdx.y;   // over FFN/32
    int x = threadIdx.x, y = threadIdx.y;    // 32 x 8
    #pragma unroll
    for (int i = 0; i < 32; i += 8)
        t[y + i][x] = in[(size_t)(by * 32 + y + i) * DIM + bx * 32 + x];
    __syncthreads();
    #pragma unroll
    for (int i = 0; i < 32; i += 8)
        outp[(size_t)(bx * 32 + y + i) * FFN + by * 32 + x] = __float2half_rn(t[x][y + i]);
}

// ---------------- RMSNorm (fp16 output) ----------------
__global__ void __launch_bounds__(256) rmsnorm_kernel(const float* __restrict__ in,
                                                      __half* __restrict__ outp) {
    int t = blockIdx.x;
    const float* r = in + (size_t)t * DIM;
    float ss = 0.f;
    float vals[8];
    #pragma unroll
    for (int j = 0; j < 8; j++) {
        float v = r[threadIdx.x + j * 256];
        vals[j] = v; ss += v * v;
    }
    __shared__ float sred[8];
    for (int o = 16; o; o >>= 1) ss += __shfl_xor_sync(0xffffffffu, ss, o);
    if ((threadIdx.x & 31) == 0) sred[threadIdx.x >> 5] = ss;
    __syncthreads();
    float tot = 0.f;
    #pragma unroll
    for (int i = 0; i < 8; i++) tot += sred[i];
    float scale = rsqrtf(tot / (float)DIM + EPS_F);
    #pragma unroll
    for (int j = 0; j < 8; j++)
        outp[(size_t)t * DIM + threadIdx.x + j * 256] = __float2half_rn(vals[j] * scale);
}

// ---------------- per-(t, head-slot) QK rmsnorm + rotary (tf32-rounded out) ----------------
__global__ void __launch_bounds__(128) qkrot_kernel(
    float* __restrict__ qkv, float* __restrict__ krot,
    const float* __restrict__ cosb, const float* __restrict__ sinb)
{
    int hs = blockIdx.x;
    int t  = blockIdx.y;
    int d  = threadIdx.x;
    float v = qkv[((size_t)t * 48 + hs) * HD + d];
    __shared__ float sm[HD];
    __shared__ float red[4];
    float ss = v * v;
    for (int o = 16; o; o >>= 1) ss += __shfl_xor_sync(0xffffffffu, ss, o);
    if ((d & 31) == 0) red[d >> 5] = ss;
    __syncthreads();
    float tot = red[0] + red[1] + red[2] + red[3];
    float n = v * rsqrtf(tot / (float)HD + EPS_F);
    sm[d] = n;
    __syncthreads();
    float o;
    if (d < 64) {
        float c = cosb[t * 64 + d], s = sinb[t * 64 + d];
        o = sm[d] * c + sm[d + 64] * s;
    } else {
        float c = cosb[t * 64 + d - 64], s = sinb[t * 64 + d - 64];
        o = -sm[d - 64] * s + sm[d] * c;
    }
    o = to_tf32(o);
    if (hs < 16) qkv[((size_t)t * 48 + hs) * HD + d] = o;
    else         krot[((size_t)t * NH + (hs - 16)) * HD + d] = o;
}

// ---------------- fused key-offset shift + v update ----------------
__global__ void __launch_bounds__(256) kv_post_kernel(
    const float* __restrict__ krot, float* __restrict__ qkv,
    const float* __restrict__ ve, const float* __restrict__ vgate,
    const int* __restrict__ key_offset)
{
    int idx = blockIdx.x * 256 + threadIdx.x;
    int half_sel = idx >= T_SEQ * NH * HD;
    int id = idx - half_sel * (T_SEQ * NH * HD);
    int d = id & 127;
    int h = (id >> 7) & 15;
    int t = id >> 11;
    if (!half_sel) {
        int ko = key_offset[0];
        bool up = (d >= 32 && d < 64) || (d >= 96);
        int st = (ko && up && t > 0) ? (t - 1) : t;
        qkv[((size_t)t * 48 + 16 + h) * HD + d] = krot[((size_t)st * NH + h) * HD + d];
    } else {
        float gv = vgate[t * NH + h];
        size_t o = ((size_t)t * 48 + 32 + h) * HD + d;
        qkv[o] = to_tf32(qkv[o] + gv * ve[id]);
    }
}

// ---------------- gate logits (xn is fp16) ----------------
__global__ void __launch_bounds__(256) gates_kernel(
    const __half* __restrict__ xn, const float* __restrict__ agw,
    const float* __restrict__ vgw, float* __restrict__ agate,
    float* __restrict__ vgate)
{
    int t = blockIdx.x;
    int w = threadIdx.x >> 5, lane = threadIdx.x & 31;
    const __half* xr = xn + (size_t)t * DIM;
    float acc[4] = {};
    const float* wbase[4];
    #pragma unroll
    for (int q = 0; q < 4; q++) {
        int o = w * 4 + q;
        wbase[q] = (o < 16) ? (agw + (size_t)o * DIM) : (vgw + (size_t)(o - 16) * DIM);
    }
    for (int dd = lane; dd < DIM; dd += 32) {
        float xv = __half2float(xr[dd]);
        #pragma unroll
        for (int q = 0; q < 4; q++) acc[q] = fmaf(xv, wbase[q][dd], acc[q]);
    }
    #pragma unroll
    for (int q = 0; q < 4; q++)
        for (int o2 = 16; o2; o2 >>= 1) acc[q] += __shfl_xor_sync(0xffffffffu, acc[q], o2);
    if (lane == 0) {
        #pragma unroll
        for (int q = 0; q < 4; q++) {
            int o = w * 4 + q;
            float gg = 1.f / (1.f + expf(-acc[q]));
            if (o < 16) agate[t * NH + o] = gg;
            else        vgate[t * NH + (o - 16)] = gg;
        }
    }
}

// ================= MMA flash attention (tf32, fp16 y output) =================
#define ROWP 132
#define FL_SMEM ((3 * 64 * ROWP + 64) * 4)

__global__ void __launch_bounds__(128) flash_mma_kernel(
    const float* __restrict__ qkv, const int* __restrict__ docs,
    const float* __restrict__ attn_scale, const float* __restrict__ agate,
    __half* __restrict__ y)
{
    extern __shared__ float fs[];
    float* Qs = fs;
    float* Ks = fs + 64 * ROWP;
    float* Vs = fs + 2 * 64 * ROWP;
    int*   kd = (int*)(fs + 3 * 64 * ROWP);

    const int tid = threadIdx.x, wid = tid >> 5, lane = tid & 31;
    const int g = lane >> 2, tig = lane & 3;
    const int h = blockIdx.y;
    const int qi = (int)gridDim.x - 1 - (int)blockIdx.x;
    const int qbase = qi * 64;
    const float scale = attn_scale[0];

    #pragma unroll
    for (int i = 0; i < 16; i++) {
        int c = tid + i * 128;
        int r = c >> 5, co = (c & 31) * 4;
        float4 f = *(const float4*)&qkv[((size_t)(qbase + r) * 48 + h) * HD + co];
        *(float4*)&Qs[r * ROWP + co] = f;
    }
    const int rg0 = qbase + wid * 16 + g;
    const int rg1 = rg0 + 8;
    const int qd0 = docs[rg0], qd1 = docs[rg1];
    const int qdmin = docs[qbase];

    float o[16][4] = {};
    float m0 = NEG_INF_F, m1 = NEG_INF_F, l0 = 0.f, l1 = 0.f;
    __syncthreads();

    for (int kb = 0; kb <= qi; kb++) {
        const int kbase = kb * 64;
        if (docs[kbase + 63] < qdmin) continue;
        __syncthreads();
        #pragma unroll
        for (int i = 0; i < 16; i++) {
            int c = tid + i * 128;
            int r = c >> 5, co = (c & 31) * 4;
            float4 f = *(const float4*)&qkv[((size_t)(kbase + r) * 48 + 16 + h) * HD + co];
            *(float4*)&Ks[r * ROWP + co] = f;
            float4 v4 = *(const float4*)&qkv[((size_t)(kbase + r) * 48 + 32 + h) * HD + co];
            *(float4*)&Vs[r * ROWP + co] = v4;
        }
        if (tid < 64) kd[tid] = docs[kbase + tid];
        __syncthreads();

        float s[8][4] = {};
        #pragma unroll
        for (int ks = 0; ks < 16; ks++) {
            const int k0 = ks * 8;
            uint32_t a0 = __float_as_uint(Qs[(wid * 16 + g) * ROWP + k0 + tig]);
            uint32_t a1 = __float_as_uint(Qs[(wid * 16 + g + 8) * ROWP + k0 + tig]);
            uint32_t a2 = __float_as_uint(Qs[(wid * 16 + g) * ROWP + k0 + tig + 4]);
            uint32_t a3 = __float_as_uint(Qs[(wid * 16 + g + 8) * ROWP + k0 + tig + 4]);
            #pragma unroll
            for (int nt = 0; nt < 8; nt++) {
                uint32_t b0 = __float_as_uint(Ks[(nt * 8 + g) * ROWP + k0 + tig]);
                uint32_t b1 = __float_as_uint(Ks[(nt * 8 + g) * ROWP + k0 + tig + 4]);
                mma_tf32(s[nt][0], s[nt][1], s[nt][2], s[nt][3], a0, a1, a2, a3, b0, b1);
            }
        }

        float mx0 = m0, mx1 = m1;
        #pragma unroll
        for (int nt = 0; nt < 8; nt++) {
            int c0i = kbase + nt * 8 + 2 * tig;
            int d0 = kd[nt * 8 + 2 * tig], d1 = kd[nt * 8 + 2 * tig + 1];
            float v00 = (c0i     <= rg0 && d0 == qd0) ? s[nt][0] * scale : NEG_INF_F;
            float v01 = (c0i + 1 <= rg0 && d1 == qd0) ? s[nt][1] * scale : NEG_INF_F;
            float v10 = (c0i     <= rg1 && d0 == qd1) ? s[nt][2] * scale : NEG_INF_F;
            float v11 = (c0i + 1 <= rg1 && d1 == qd1) ? s[nt][3] * scale : NEG_INF_F;
            s[nt][0] = v00; s[nt][1] = v01; s[nt][2] = v10; s[nt][3] = v11;
            mx0 = fmaxf(mx0, fmaxf(v00, v01));
            mx1 = fmaxf(mx1, fmaxf(v10, v11));
        }
        mx0 = fmaxf(mx0, __shfl_xor_sync(0xffffffffu, mx0, 1));
        mx0 = fmaxf(mx0, __shfl_xor_sync(0xffffffffu, mx0, 2));
        mx1 = fmaxf(mx1, __shfl_xor_sync(0xffffffffu, mx1, 1));
        mx1 = fmaxf(mx1, __shfl_xor_sync(0xffffffffu, mx1, 2));
        float al0 = __expf(m0 - mx0), al1 = __expf(m1 - mx1);
        m0 = mx0; m1 = mx1;

        float sum0 = 0.f, sum1 = 0.f;
        #pragma unroll
        for (int nt = 0; nt < 8; nt++) {
            float p00 = __expf(s[nt][0] - m0);
            float p01 = __expf(s[nt][1] - m0);
            float p10 = __expf(s[nt][2] - m1);
            float p11 = __expf(s[nt][3] - m1);
            sum0 += p00 + p01; sum1 += p10 + p11;
            s[nt][0] = to_tf32(p00); s[nt][1] = to_tf32(p01);
            s[nt][2] = to_tf32(p10); s[nt][3] = to_tf32(p11);
        }
        sum0 += __shfl_xor_sync(0xffffffffu, sum0, 1);
        sum0 += __shfl_xor_sync(0xffffffffu, sum0, 2);
        sum1 += __shfl_xor_sync(0xffffffffu, sum1, 1);
        sum1 += __shfl_xor_sync(0xffffffffu, sum1, 2);
        l0 = l0 * al0 + sum0;
        l1 = l1 * al1 + sum1;
        #pragma unroll
        for (int nt = 0; nt < 16; nt++) {
            o[nt][0] *= al0; o[nt][1] *= al0;
            o[nt][2] *= al1; o[nt][3] *= al1;
        }

        #pragma unroll
        for (int kc = 0; kc < 8; kc++) {
            int src = (g << 2) | (tig >> 1);
            float x0 = __shfl_sync(0xffffffffu, s[kc][0], src);
            float x1 = __shfl_sync(0xffffffffu, s[kc][1], src);
            float x2 = __shfl_sync(0xffffffffu, s[kc][2], src);
            float x3 = __shfl_sync(0xffffffffu, s[kc][3], src);
            float z0 = __shfl_sync(0xffffffffu, s[kc][0], src + 2);
            float z1 = __shfl_sync(0xffffffffu, s[kc][1], src + 2);
            float z2 = __shfl_sync(0xffffffffu, s[kc][2], src + 2);
            float z3 = __shfl_sync(0xffffffffu, s[kc][3], src + 2);
            bool odd = (tig & 1) != 0;
            uint32_t a0 = __float_as_uint(odd ? x1 : x0);
            uint32_t a1 = __float_as_uint(odd ? x3 : x2);
            uint32_t a2 = __float_as_uint(odd ? z1 : z0);
            uint32_t a3 = __float_as_uint(odd ? z3 : z2);
            #pragma unroll
            for (int nt = 0; nt < 16; nt++) {
                uint32_t b0 = __float_as_uint(Vs[(kc * 8 + tig) * ROWP + nt * 8 + g]);
                uint32_t b1 = __float_as_uint(Vs[(kc * 8 + tig + 4) * ROWP + nt * 8 + g]);
                mma_tf32(o[nt][0], o[nt][1], o[nt][2], o[nt][3], a0, a1, a2, a3, b0, b1);
            }
        }
    }

    float f0 = (1.f / l0) * agate[rg0 * NH + h];
    float f1 = (1.f / l1) * agate[rg1 * NH + h];
    #pragma unroll
    for (int nt = 0; nt < 16; nt++) {
        *(__half2*)&y[(size_t)rg0 * DIM + h * HD + nt * 8 + 2 * tig] =
            __floats2half2_rn(o[nt][0] * f0, o[nt][1] * f0);
        *(__half2*)&y[(size_t)rg1 * DIM + h * HD + nt * 8 + 2 * tig] =
            __floats2half2_rn(o[nt][2] * f1, o[nt][3] * f1);
    }
}

// ---------------- launch ----------------
extern "C" void kernel_launch(void* const* d_in, const int* in_sizes, int n_in,
                              void* d_out, int out_size) {
    const float* x           = (const float*)d_in[0];
    const float* ve          = (const float*)d_in[1];
    const float* qkvo_w      = (const float*)d_in[2];
    const float* attn_gate_w = (const float*)d_in[3];
    const float* ve_gate_w   = (const float*)d_in[4];
    const float* c_fc        = (const float*)d_in[5];
    const float* c_proj      = (const float*)d_in[6];
    const float* sa_lambdas  = (const float*)d_in[7];
    const float* cosb        = (const float*)d_in[8];
    const float* sinb        = (const float*)d_in[9];
    const float* attn_scale  = (const float*)d_in[10];
    const int*   docs        = (const int*)d_in[11];
    const int*   key_offset  = (const int*)d_in[12];
    float*       out         = (float*)d_out;

    __half *xn, *y, *hbuf, *wqkv, *wfc, *wpT;
    float *qkv, *krot, *x1, *agate, *vgate;
    cudaGetSymbolAddress((void**)&xn,    g_xn);
    cudaGetSymbolAddress((void**)&qkv,   g_qkv);
    cudaGetSymbolAddress((void**)&krot,  g_krot);
    cudaGetSymbolAddress((void**)&y,     g_y);
    cudaGetSymbolAddress((void**)&x1,    g_x1);
    cudaGetSymbolAddress((void**)&hbuf,  g_h);
    cudaGetSymbolAddress((void**)&agate, g_agate);
    cudaGetSymbolAddress((void**)&vgate, g_vgate);
    cudaGetSymbolAddress((void**)&wqkv,  g_wqkv);
    cudaGetSymbolAddress((void**)&wfc,   g_wfc);
    cudaGetSymbolAddress((void**)&wpT,   g_wpT);

    cudaFuncSetAttribute(flash_mma_kernel, cudaFuncAttributeMaxDynamicSharedMemorySize,
                         FL_SMEM);
    cudaFuncSetAttribute(f16_gemm_kernel<0>, cudaFuncAttributeMaxDynamicSharedMemorySize,
                         GEMM_SMEM);
    cudaFuncSetAttribute(f16_gemm_kernel<1>, cudaFuncAttributeMaxDynamicSharedMemorySize,
                         GEMM_SMEM);
    cudaFuncSetAttribute(f16_gemm_kernel<2>, cudaFuncAttributeMaxDynamicSharedMemorySize,
                         GEMM_SMEM);

    // weight conversions (fp16 copies; c_proj also transposed to [N,K])
    round_f16_kernel<<<(4 * DIM * DIM / 8 + 255) / 256, 256>>>(qkvo_w, wqkv, 4 * DIM * DIM / 8);
    round_f16_kernel<<<((size_t)FFN * DIM / 8 + 255) / 256, 256>>>(c_fc, wfc, FFN * DIM / 8);
    transpose_f16_kernel<<<dim3(DIM / 32, FFN / 32), dim3(32, 8)>>>(c_proj, wpT);

    // 1. xn = fp16(rmsnorm(x))
    rmsnorm_kernel<<<T_SEQ, 256>>>(x, xn);
    // 2. qkv = lam0 * xn @ Wqkv^T   (fp32 out)
    f16_gemm_kernel<0><<<dim3(3 * DIM / GBN, T_SEQ / GBM), 512, GEMM_SMEM>>>(
        xn, wqkv, qkv, nullptr, sa_lambdas, 0, 3 * DIM, DIM);
    // 3. per-head rmsnorm + rotary
    qkrot_kernel<<<dim3(32, T_SEQ), 128>>>(qkv, krot, cosb, sinb);
    // 4. gates
    gates_kernel<<<T_SEQ, 256>>>(xn, attn_gate_w, ve_gate_w, agate, vgate);
    // 5. fused key-offset shift + v update
    kv_post_kernel<<<(2 * T_SEQ * NH * HD) / 256, 256>>>(krot, qkv, ve, vgate, key_offset);
    // 6. MMA flash attention (fp16 y out)
    flash_mma_kernel<<<dim3(T_SEQ / 64, NH), 128, FL_SMEM>>>(
        qkv, docs, attn_scale, agate, y);
    // 7. x1 = x + lam1 * y @ Wo^T
    f16_gemm_kernel<2><<<dim3(DIM / GBN, T_SEQ / GBM), 512, GEMM_SMEM>>>(
        y, wqkv + (size_t)3 * DIM * DIM, x1, x, sa_lambdas, 1, DIM, DIM);
    // 8. xn = fp16(rmsnorm(x1))
    rmsnorm_kernel<<<T_SEQ, 256>>>(x1, xn);
    // 9. h = fp16(relu(xn @ c_fc^T)^2)
    f16_gemm_kernel<1><<<dim3(FFN / GBN, T_SEQ / GBM), 512, GEMM_SMEM>>>(
        xn, wfc, hbuf, nullptr, nullptr, 0, FFN, DIM);
    // 10. out = x1 + h @ c_proj   (via c_proj^T, K=8192)
    f16_gemm_kernel<2><<<dim3(DIM / GBN, T_SEQ / GBM), 512, GEMM_SMEM>>>(
        hbuf, wpT, out, x1, nullptr, 0, DIM, FFN);
}

// round 10
// speedup vs baseline: 7.7178x; 1.0122x over previous
#include <cuda_runtime.h>
#include <cuda_fp16.h>
#include <cstdint>
#include <cstddef>

// ---------------- problem constants ----------------
#define T_SEQ 2048
#define DIM   2048
#define NH    16
#define HD    128
#define FFN   8192
#define EPS_F 1.1920929e-07f
#define NEG_INF_F (-1e30f)

// ---------------- scratch (device globals; no runtime allocs) ----------------
__device__ __half g_xn  [(size_t)T_SEQ * DIM];     // fp16 rmsnorm output
__device__ float  g_qkv [(size_t)T_SEQ * 3 * DIM]; // [T, 48, 128] fp32
__device__ float  g_krot[(size_t)T_SEQ * NH * HD]; // rotated k pre-shift (fp32)
__device__ __half g_qh  [(size_t)T_SEQ * NH * HD]; // fp16 q for flash
__device__ __half g_kh  [(size_t)T_SEQ * NH * HD]; // fp16 shifted k for flash
__device__ __half g_vh  [(size_t)T_SEQ * NH * HD]; // fp16 v for flash
__device__ __half g_y   [(size_t)T_SEQ * DIM];     // fp16 attention output
__device__ float  g_x1  [(size_t)T_SEQ * DIM];
__device__ __half g_h   [(size_t)T_SEQ * FFN];     // fp16 MLP hidden
__device__ float  g_agate[(size_t)T_SEQ * NH];
__device__ float  g_vgate[(size_t)T_SEQ * NH];
__device__ __half g_wqkv[(size_t)4 * DIM * DIM];   // fp16 qkvo weights [N,K]
__device__ __half g_wfc [(size_t)FFN * DIM];       // fp16 c_fc [N,K]
__device__ __half g_wp  [(size_t)FFN * DIM];       // fp16 c_proj [K,N] (native layout)

// ---------------- helpers ----------------
__device__ __forceinline__ float to_tf32(float x) {
    asm("cvt.rna.tf32.f32 %0, %1;" : "=f"(x) : "f"(x));
    return x;
}
__device__ __forceinline__ uint32_t pack2h(float a, float b) {
    __half2 h = __floats2half2_rn(a, b);
    return *(uint32_t*)&h;
}
__device__ __forceinline__ void cp_async16(uint32_t dst, const void* src) {
    asm volatile("cp.async.cg.shared.global [%0], [%1], 16;" :: "r"(dst), "l"(src));
}
__device__ __forceinline__ void cp_async_commit() {
    asm volatile("cp.async.commit_group;" ::: "memory");
}
template<int N>
__device__ __forceinline__ void cp_async_wait() {
    asm volatile("cp.async.wait_group %0;" :: "n"(N) : "memory");
}
__device__ __forceinline__ uint32_t smem_u32(const void* p) {
    uint32_t a;
    asm("{ .reg .u64 t; cvta.to.shared.u64 t, %1; cvt.u32.u64 %0, t; }" : "=r"(a) : "l"(p));
    return a;
}
__device__ __forceinline__ void ldsm_x4(uint32_t& r0, uint32_t& r1, uint32_t& r2, uint32_t& r3,
                                        uint32_t addr) {
    asm volatile("ldmatrix.sync.aligned.m8n8.x4.shared.b16 {%0,%1,%2,%3}, [%4];"
                 : "=r"(r0), "=r"(r1), "=r"(r2), "=r"(r3) : "r"(addr));
}
__device__ __forceinline__ void ldsm_x4_t(uint32_t& r0, uint32_t& r1, uint32_t& r2, uint32_t& r3,
                                          uint32_t addr) {
    asm volatile("ldmatrix.sync.aligned.m8n8.x4.trans.shared.b16 {%0,%1,%2,%3}, [%4];"
                 : "=r"(r0), "=r"(r1), "=r"(r2), "=r"(r3) : "r"(addr));
}
__device__ __forceinline__ void mma_f16(float& c0, float& c1, float& c2, float& c3,
                                        uint32_t a0, uint32_t a1, uint32_t a2, uint32_t a3,
                                        uint32_t b0, uint32_t b1) {
    asm volatile("mma.sync.aligned.m16n8k16.row.col.f32.f16.f16.f32 "
                 "{%0,%1,%2,%3}, {%4,%5,%6,%7}, {%8,%9}, {%0,%1,%2,%3};"
                 : "+f"(c0), "+f"(c1), "+f"(c2), "+f"(c3)
                 : "r"(a0), "r"(a1), "r"(a2), "r"(a3), "r"(b0), "r"(b1));
}

// ================= fp16 warp-MMA GEMM =================
// C[M,N] = epi(alpha * A[M,K] @ op(B)), A/B fp16, accumulate fp32.
// BT=1: B [N,K] row-major (k-contiguous). BT=0: B [K,N] row-major (n-contiguous).
// BM=256 BN=128 BK=64, 512 threads (16 warps, 4x4 of 64x32 warp tiles), 4-stage cp.async.
#define GBM 256
#define GBN 128
#define GBK 64
#define GSTAGES 4
#define ROWH 72                               // BT=1 B/A row: 64 halfs + 8 pad (144 B)
#define BROWB 272                             // BT=0 B row: 128 halfs + 8 pad (272 B)
#define A_STAGE_B (GBM * ROWH * 2)            // 36864 bytes
#define B_STAGE_B (GBN * ROWH * 2)            // 18432 bytes (>= 64*272=17408)
#define STAGE_B   (A_STAGE_B + B_STAGE_B)     // 55296 bytes
#define GEMM_SMEM (GSTAGES * STAGE_B)         // 221184 bytes

// EPI: 0=none->float, 1=relu^2->half, 2=add residual->float
template<int EPI, int BT>
__global__ void __launch_bounds__(512, 1)
f16_gemm_kernel(const __half* __restrict__ A, const __half* __restrict__ B,
                void* __restrict__ Cv, const float* __restrict__ addsrc,
                const float* __restrict__ alpha_ptr, int alpha_idx,
                int N, int K)
{
    extern __shared__ char smc[];
    const int tid = threadIdx.x;
    const int wid = tid >> 5, lane = tid & 31;
    const int g = lane >> 2, tig = lane & 3;
    const int wm = (wid & 3) * 64, wn = (wid >> 2) * 32;
    const int bn = blockIdx.x, bm = blockIdx.y;
    const int nk = K / GBK;
    const uint32_t sb = smem_u32(smc);

    const __half* Agm = A + (size_t)bm * GBM * K;
    const __half* Bgm = BT ? (B + (size_t)bn * GBN * K) : B;

    auto load_tile = [&](int stage, int ktile) {
        uint32_t sa = sb + stage * STAGE_B;
        uint32_t sB = sa + A_STAGE_B;
        int kt = ktile * GBK;
        #pragma unroll
        for (int i = 0; i < 4; i++) {                 // A: 256 rows x 8 chunks
            int c = tid + i * 512;
            int row = c >> 3, ch = c & 7;
            cp_async16(sa + (uint32_t)row * 144 + ch * 16,
                       Agm + (size_t)row * K + kt + ch * 8);
        }
        if (BT) {
            #pragma unroll
            for (int i = 0; i < 2; i++) {             // B: 128 rows x 8 chunks (k-major)
                int c = tid + i * 512;
                int row = c >> 3, ch = c & 7;
                cp_async16(sB + (uint32_t)row * 144 + ch * 16,
                           Bgm + (size_t)row * K + kt + ch * 8);
            }
        } else {
            #pragma unroll
            for (int i = 0; i < 2; i++) {             // B: 64 k-rows x 16 chunks (n-major)
                int c = tid + i * 512;
                int row = c >> 4, ch = c & 15;
                cp_async16(sB + (uint32_t)row * BROWB + ch * 16,
                           Bgm + (size_t)(kt + row) * N + bn * GBN + ch * 8);
            }
        }
    };

    // per-thread ldmatrix byte offsets (within a stage)
    uint32_t aoff[4], boff[2];
    #pragma unroll
    for (int mt = 0; mt < 4; mt++)
        aoff[mt] = (uint32_t)(wm + mt * 16 + (lane & 7) + ((lane >> 3) & 1) * 8) * 144
                 + ((lane >> 4) & 1) * 16;
    if (BT) {
        #pragma unroll
        for (int nb = 0; nb < 2; nb++)
            boff[nb] = (uint32_t)(wn + nb * 16 + (lane & 7) + ((lane >> 4) & 1) * 8) * 144
                     + ((lane >> 3) & 1) * 16;
    } else {
        #pragma unroll
        for (int nb = 0; nb < 2; nb++)
            boff[nb] = (uint32_t)((lane & 7) + ((lane >> 3) & 1) * 8) * BROWB
                     + (wn + nb * 16) * 2 + ((lane >> 4) & 1) * 16;
    }

    float acc[4][4][4];
    #pragma unroll
    for (int mt = 0; mt < 4; mt++)
        #pragma unroll
        for (int nt = 0; nt < 4; nt++)
            #pragma unroll
            for (int q = 0; q < 4; q++) acc[mt][nt][q] = 0.f;

    #pragma unroll
    for (int s = 0; s < GSTAGES - 1; s++) { load_tile(s, s); cp_async_commit(); }

    for (int k = 0; k < nk; k++) {
        cp_async_wait<GSTAGES - 2>();
        __syncthreads();
        if (k + GSTAGES - 1 < nk) load_tile((k + GSTAGES - 1) & (GSTAGES - 1),
                                            k + GSTAGES - 1);
        cp_async_commit();

        uint32_t sa = sb + (k & (GSTAGES - 1)) * STAGE_B;
        uint32_t sB = sa + A_STAGE_B;

        #pragma unroll
        for (int ks = 0; ks < 4; ks++) {              // 4 x k16 = BK 64
            uint32_t a[4][4];
            #pragma unroll
            for (int mt = 0; mt < 4; mt++)
                ldsm_x4(a[mt][0], a[mt][1], a[mt][2], a[mt][3],
                        sa + aoff[mt] + ks * 32);
            #pragma unroll
            for (int nb = 0; nb < 2; nb++) {
                uint32_t b0, b1, b2, b3;
                if (BT) ldsm_x4(b0, b1, b2, b3, sB + boff[nb] + ks * 32);
                else    ldsm_x4_t(b0, b1, b2, b3, sB + boff[nb] + ks * 16 * BROWB);
                #pragma unroll
                for (int mt = 0; mt < 4; mt++) {
                    mma_f16(acc[mt][2 * nb][0], acc[mt][2 * nb][1],
                            acc[mt][2 * nb][2], acc[mt][2 * nb][3],
                            a[mt][0], a[mt][1], a[mt][2], a[mt][3], b0, b1);
                    mma_f16(acc[mt][2 * nb + 1][0], acc[mt][2 * nb + 1][1],
                            acc[mt][2 * nb + 1][2], acc[mt][2 * nb + 1][3],
                            a[mt][0], a[mt][1], a[mt][2], a[mt][3], b2, b3);
                }
            }
        }
    }

    float alpha = alpha_ptr ? alpha_ptr[alpha_idx] : 1.0f;
    #pragma unroll
    for (int mt = 0; mt < 4; mt++) {
        #pragma unroll
        for (int half_i = 0; half_i < 2; half_i++) {
            int row = bm * GBM + wm + mt * 16 + g + half_i * 8;
            #pragma unroll
            for (int nt = 0; nt < 4; nt++) {
                int col = bn * GBN + wn + nt * 8 + tig * 2;
                float vx = acc[mt][nt][half_i * 2 + 0] * alpha;
                float vy = acc[mt][nt][half_i * 2 + 1] * alpha;
                size_t idx = (size_t)row * N + col;
                if (EPI == 1) {
                    vx = fmaxf(vx, 0.f); vx = vx * vx;
                    vy = fmaxf(vy, 0.f); vy = vy * vy;
                    *(__half2*)((__half*)Cv + idx) = __floats2half2_rn(vx, vy);
                } else if (EPI == 2) {
                    float2 a2 = *(const float2*)&addsrc[idx];
                    float2 v; v.x = vx + a2.x; v.y = vy + a2.y;
                    *(float2*)((float*)Cv + idx) = v;
                } else {
                    float2 v; v.x = vx; v.y = vy;
                    *(float2*)((float*)Cv + idx) = v;
                }
            }
        }
    }
}

// ---------------- weight conversion ----------------
__global__ void __launch_bounds__(256) round_f16_kernel(const float* __restrict__ in,
                                                        __half* __restrict__ outp, int n8) {
    int i = blockIdx.x * 256 + threadIdx.x;
    if (i < n8) {
        float4 v0 = ((const float4*)in)[2 * i];
        float4 v1 = ((const float4*)in)[2 * i + 1];
        __half2 h0 = __floats2half2_rn(v0.x, v0.y);
        __half2 h1 = __floats2half2_rn(v0.z, v0.w);
        __half2 h2 = __floats2half2_rn(v1.x, v1.y);
        __half2 h3 = __floats2half2_rn(v1.z, v1.w);
        uint4 o;
        o.x = *(uint32_t*)&h0; o.y = *(uint32_t*)&h1;
        o.z = *(uint32_t*)&h2; o.w = *(uint32_t*)&h3;
        ((uint4*)outp)[i] = o;
    }
}

// ---------------- RMSNorm (fp16 output) ----------------
__global__ void __launch_bounds__(256) rmsnorm_kernel(const float* __restrict__ in,
                                                      __half* __restrict__ outp) {
    int t = blockIdx.x;
    const float* r = in + (size_t)t * DIM;
    float ss = 0.f;
    float vals[8];
    #pragma unroll
    for (int j = 0; j < 8; j++) {
        float v = r[threadIdx.x + j * 256];
        vals[j] = v; ss += v * v;
    }
    __shared__ float sred[8];
    for (int o = 16; o; o >>= 1) ss += __shfl_xor_sync(0xffffffffu, ss, o);
    if ((threadIdx.x & 31) == 0) sred[threadIdx.x >> 5] = ss;
    __syncthreads();
    float tot = 0.f;
    #pragma unroll
    for (int i = 0; i < 8; i++) tot += sred[i];
    float scale = rsqrtf(tot / (float)DIM + EPS_F);
    #pragma unroll
    for (int j = 0; j < 8; j++)
        outp[(size_t)t * DIM + threadIdx.x + j * 256] = __float2half_rn(vals[j] * scale);
}

// ---------------- gates v2: tiled, low weight traffic ----------------
// grid 128 blocks x 256 threads; block handles 16 t-rows, all 32 gate outputs.
__global__ void __launch_bounds__(256) gates2_kernel(
    const __half* __restrict__ xn, const float* __restrict__ agw,
    const float* __restrict__ vgw, float* __restrict__ agate,
    float* __restrict__ vgate)
{
    __shared__ __half xs[16][520];
    int t0 = blockIdx.x * 16;
    int t = threadIdx.x & 15, og = threadIdx.x >> 4;   // og 0..15 (head)
    float acc0 = 0.f, acc1 = 0.f;
    for (int kc = 0; kc < 4; kc++) {
        #pragma unroll
        for (int i = 0; i < 4; i++) {
            int c = threadIdx.x + i * 256;
            int r = c >> 6, co = c & 63;
            *(uint4*)&xs[r][co * 8] =
                *(const uint4*)&xn[(size_t)(t0 + r) * DIM + kc * 512 + co * 8];
        }
        __syncthreads();
        const float* wa = agw + (size_t)og * DIM + kc * 512;
        const float* wv = vgw + (size_t)og * DIM + kc * 512;
        #pragma unroll 8
        for (int kk = 0; kk < 512; kk++) {
            float xv = __half2float(xs[t][kk]);
            acc0 = fmaf(xv, wa[kk], acc0);
            acc1 = fmaf(xv, wv[kk], acc1);
        }
        __syncthreads();
    }
    agate[(t0 + t) * NH + og] = 1.f / (1.f + expf(-acc0));
    vgate[(t0 + t) * NH + og] = 1.f / (1.f + expf(-acc1));
}

// ---------------- per-(t, head-slot) QK rmsnorm + rotary ----------------
// hs 0..15 -> q (fp16 g_qh), hs 16..31 -> rotated k (fp32 g_krot)
__global__ void __launch_bounds__(128) qkrot_kernel(
    const float* __restrict__ qkv, __half* __restrict__ qh,
    float* __restrict__ krot,
    const float* __restrict__ cosb, const float* __restrict__ sinb)
{
    int hs = blockIdx.x;
    int t  = blockIdx.y;
    int d  = threadIdx.x;
    float v = qkv[((size_t)t * 48 + hs) * HD + d];
    __shared__ float sm[HD];
    __shared__ float red[4];
    float ss = v * v;
    for (int o = 16; o; o >>= 1) ss += __shfl_xor_sync(0xffffffffu, ss, o);
    if ((d & 31) == 0) red[d >> 5] = ss;
    __syncthreads();
    float tot = red[0] + red[1] + red[2] + red[3];
    float n = v * rsqrtf(tot / (float)HD + EPS_F);
    sm[d] = n;
    __syncthreads();
    float o;
    if (d < 64) {
        float c = cosb[t * 64 + d], s = sinb[t * 64 + d];
        o = sm[d] * c + sm[d + 64] * s;
    } else {
        float c = cosb[t * 64 + d - 64], s = sinb[t * 64 + d - 64];
        o = -sm[d - 64] * s + sm[d] * c;
    }
    if (hs < 16) qh[((size_t)t * NH + hs) * HD + d] = __float2half_rn(o);
    else         krot[((size_t)t * NH + (hs - 16)) * HD + d] = o;
}

// ---------------- fused key-offset shift + v update (fp16 outputs) ----------------
__global__ void __launch_bounds__(256) kv_post_kernel(
    const float* __restrict__ krot, const float* __restrict__ qkv,
    const float* __restrict__ ve, const float* __restrict__ vgate,
    const int* __restrict__ key_offset,
    __half* __restrict__ kh, __half* __restrict__ vh)
{
    int idx = blockIdx.x * 256 + threadIdx.x;
    int half_sel = idx >= T_SEQ * NH * HD;
    int id = idx - half_sel * (T_SEQ * NH * HD);
    int d = id & 127;
    int h = (id >> 7) & 15;
    int t = id >> 11;
    if (!half_sel) {
        int ko = key_offset[0];
        bool up = (d >= 32 && d < 64) || (d >= 96);
        int st = (ko && up && t > 0) ? (t - 1) : t;
        kh[id] = __float2half_rn(krot[((size_t)st * NH + h) * HD + d]);
    } else {
        float gv = vgate[t * NH + h];
        float v = qkv[((size_t)t * 48 + 32 + h) * HD + d] + gv * ve[id];
        vh[id] = __float2half_rn(v);
    }
}

// ================= fp16 MMA flash attention =================
// 64 q x 64 k tiles, 4 warps (16 q-rows each), doc-block skip.
// S via fp16 mma (Q,K fp16); P relayed C->A frags directly (no shuffles);
// PV via fp16 mma with V loaded through ldmatrix.trans.
#define FROW 136
#define FL_SMEM (3 * 64 * FROW * 2 + 256)

__global__ void __launch_bounds__(128) flash_mma_kernel(
    const __half* __restrict__ qh, const __half* __restrict__ kh,
    const __half* __restrict__ vh, const int* __restrict__ docs,
    const float* __restrict__ attn_scale, const float* __restrict__ agate,
    __half* __restrict__ y)
{
    extern __shared__ __half fh[];
    __half* Qs = fh;
    __half* Ks = fh + 64 * FROW;
    __half* Vs = fh + 2 * 64 * FROW;
    int*    kd = (int*)(fh + 3 * 64 * FROW);

    const int tid = threadIdx.x, wid = tid >> 5, lane = tid & 31;
    const int g = lane >> 2, tig = lane & 3;
    const int h = blockIdx.y;
    const int qi = (int)gridDim.x - 1 - (int)blockIdx.x;
    const int qbase = qi * 64;
    const float scale = attn_scale[0];

    #pragma unroll
    for (int i = 0; i < 8; i++) {
        int c = tid + i * 128;
        int r = c >> 4, co = c & 15;
        *(uint4*)&Qs[r * FROW + co * 8] =
            *(const uint4*)&qh[((size_t)(qbase + r) * NH + h) * HD + co * 8];
    }
    const int rg0 = qbase + wid * 16 + g;
    const int rg1 = rg0 + 8;
    const int qd0 = docs[rg0], qd1 = docs[rg1];
    const int qdmin = docs[qbase];

    const uint32_t sQ = smem_u32(Qs), sK = smem_u32(Ks), sV = smem_u32(Vs);
    const uint32_t qoff = (uint32_t)(wid * 16 + (lane & 7) + ((lane >> 3) & 1) * 8) * (FROW * 2)
                        + ((lane >> 4) & 1) * 16;
    uint32_t koff[4], voff[8];
    #pragma unroll
    for (int nb = 0; nb < 4; nb++)
        koff[nb] = (uint32_t)(nb * 16 + (lane & 7) + ((lane >> 4) & 1) * 8) * (FROW * 2)
                 + ((lane >> 3) & 1) * 16;
    #pragma unroll
    for (int nb = 0; nb < 8; nb++)
        voff[nb] = (uint32_t)((lane & 7) + ((lane >> 3) & 1) * 8) * (FROW * 2)
                 + nb * 32 + ((lane >> 4) & 1) * 16;

    float o[16][4] = {};
    float m0 = NEG_INF_F, m1 = NEG_INF_F, l0 = 0.f, l1 = 0.f;
    __syncthreads();

    for (int kb = 0; kb <= qi; kb++) {
        const int kbase = kb * 64;
        if (docs[kbase + 63] < qdmin) continue;
        __syncthreads();
        #pragma unroll
        for (int i = 0; i < 8; i++) {
            int c = tid + i * 128;
            int r = c >> 4, co = c & 15;
            *(uint4*)&Ks[r * FROW + co * 8] =
                *(const uint4*)&kh[((size_t)(kbase + r) * NH + h) * HD + co * 8];
            *(uint4*)&Vs[r * FROW + co * 8] =
                *(const uint4*)&vh[((size_t)(kbase + r) * NH + h) * HD + co * 8];
        }
        if (tid < 64) kd[tid] = docs[kbase + tid];
        __syncthreads();

        // S = Q @ K^T  (warp: 16 x 64), fp16 mma, 8 k16 steps
        float s[8][4] = {};
        #pragma unroll
        for (int ks = 0; ks < 8; ks++) {
            uint32_t a0, a1, a2, a3;
            ldsm_x4(a0, a1, a2, a3, sQ + qoff + ks * 32);
            #pragma unroll
            for (int nb = 0; nb < 4; nb++) {
                uint32_t b0, b1, b2, b3;
                ldsm_x4(b0, b1, b2, b3, sK + koff[nb] + ks * 32);
                mma_f16(s[2 * nb][0], s[2 * nb][1], s[2 * nb][2], s[2 * nb][3],
                        a0, a1, a2, a3, b0, b1);
                mma_f16(s[2 * nb + 1][0], s[2 * nb + 1][1], s[2 * nb + 1][2], s[2 * nb + 1][3],
                        a0, a1, a2, a3, b2, b3);
            }
        }

        // scale + mask + row max
        float mx0 = m0, mx1 = m1;
        #pragma unroll
        for (int nt = 0; nt < 8; nt++) {
            int c0i = kbase + nt * 8 + 2 * tig;
            int d0 = kd[nt * 8 + 2 * tig], d1 = kd[nt * 8 + 2 * tig + 1];
            float v00 = (c0i     <= rg0 && d0 == qd0) ? s[nt][0] * scale : NEG_INF_F;
            float v01 = (c0i + 1 <= rg0 && d1 == qd0) ? s[nt][1] * scale : NEG_INF_F;
            float v10 = (c0i     <= rg1 && d0 == qd1) ? s[nt][2] * scale : NEG_INF_F;
            float v11 = (c0i + 1 <= rg1 && d1 == qd1) ? s[nt][3] * scale : NEG_INF_F;
            s[nt][0] = v00; s[nt][1] = v01; s[nt][2] = v10; s[nt][3] = v11;
            mx0 = fmaxf(mx0, fmaxf(v00, v01));
            mx1 = fmaxf(mx1, fmaxf(v10, v11));
        }
        mx0 = fmaxf(mx0, __shfl_xor_sync(0xffffffffu, mx0, 1));
        mx0 = fmaxf(mx0, __shfl_xor_sync(0xffffffffu, mx0, 2));
        mx1 = fmaxf(mx1, __shfl_xor_sync(0xffffffffu, mx1, 1));
        mx1 = fmaxf(mx1, __shfl_xor_sync(0xffffffffu, mx1, 2));
        float al0 = __expf(m0 - mx0), al1 = __expf(m1 - mx1);
        m0 = mx0; m1 = mx1;

        float sum0 = 0.f, sum1 = 0.f;
        #pragma unroll
        for (int nt = 0; nt < 8; nt++) {
            s[nt][0] = __expf(s[nt][0] - m0);
            s[nt][1] = __expf(s[nt][1] - m0);
            s[nt][2] = __expf(s[nt][2] - m1);
            s[nt][3] = __expf(s[nt][3] - m1);
            sum0 += s[nt][0] + s[nt][1];
            sum1 += s[nt][2] + s[nt][3];
        }
        sum0 += __shfl_xor_sync(0xffffffffu, sum0, 1);
        sum0 += __shfl_xor_sync(0xffffffffu, sum0, 2);
        sum1 += __shfl_xor_sync(0xffffffffu, sum1, 1);
        sum1 += __shfl_xor_sync(0xffffffffu, sum1, 2);
        l0 = l0 * al0 + sum0;
        l1 = l1 * al1 + sum1;
        #pragma unroll
        for (int nt = 0; nt < 16; nt++) {
            o[nt][0] *= al0; o[nt][1] *= al0;
            o[nt][2] *= al1; o[nt][3] *= al1;
        }

        // P C-frags -> A-frags directly (fp16)
        uint32_t pa[4][4];
        #pragma unroll
        for (int kc = 0; kc < 4; kc++) {
            pa[kc][0] = pack2h(s[2 * kc][0], s[2 * kc][1]);
            pa[kc][1] = pack2h(s[2 * kc][2], s[2 * kc][3]);
            pa[kc][2] = pack2h(s[2 * kc + 1][0], s[2 * kc + 1][1]);
            pa[kc][3] = pack2h(s[2 * kc + 1][2], s[2 * kc + 1][3]);
        }
        // O += P @ V  (V via ldmatrix.trans)
        #pragma unroll
        for (int kc = 0; kc < 4; kc++) {
            #pragma unroll
            for (int nb = 0; nb < 8; nb++) {
                uint32_t b0, b1, b2, b3;
                ldsm_x4_t(b0, b1, b2, b3, sV + voff[nb] + kc * 16 * (FROW * 2));
                mma_f16(o[2 * nb][0], o[2 * nb][1], o[2 * nb][2], o[2 * nb][3],
                        pa[kc][0], pa[kc][1], pa[kc][2], pa[kc][3], b0, b1);
                mma_f16(o[2 * nb + 1][0], o[2 * nb + 1][1], o[2 * nb + 1][2], o[2 * nb + 1][3],
                        pa[kc][0], pa[kc][1], pa[kc][2], pa[kc][3], b2, b3);
            }
        }
    }

    float f0 = (1.f / l0) * agate[rg0 * NH + h];
    float f1 = (1.f / l1) * agate[rg1 * NH + h];
    #pragma unroll
    for (int nt = 0; nt < 16; nt++) {
        *(__half2*)&y[(size_t)rg0 * DIM + h * HD + nt * 8 + 2 * tig] =
            __floats2half2_rn(o[nt][0] * f0, o[nt][1] * f0);
        *(__half2*)&y[(size_t)rg1 * DIM + h * HD + nt * 8 + 2 * tig] =
            __floats2half2_rn(o[nt][2] * f1, o[nt][3] * f1);
    }
}

// ---------------- launch ----------------
extern "C" void kernel_launch(void* const* d_in, const int* in_sizes, int n_in,
                              void* d_out, int out_size) {
    const float* x           = (const float*)d_in[0];
    const float* ve          = (const float*)d_in[1];
    const float* qkvo_w      = (const float*)d_in[2];
    const float* attn_gate_w = (const float*)d_in[3];
    const float* ve_gate_w   = (const float*)d_in[4];
    const float* c_fc        = (const float*)d_in[5];
    const float* c_proj      = (const float*)d_in[6];
    const float* sa_lambdas  = (const float*)d_in[7];
    const float* cosb        = (const float*)d_in[8];
    const float* sinb        = (const float*)d_in[9];
    const float* attn_scale  = (const float*)d_in[10];
    const int*   docs        = (const int*)d_in[11];
    const int*   key_offset  = (const int*)d_in[12];
    float*       out         = (float*)d_out;

    __half *xn, *qhp, *khp, *vhp, *y, *hbuf, *wqkv, *wfc, *wp;
    float *qkv, *krot, *x1, *agate, *vgate;
    cudaGetSymbolAddress((void**)&xn,    g_xn);
    cudaGetSymbolAddress((void**)&qkv,   g_qkv);
    cudaGetSymbolAddress((void**)&krot,  g_krot);
    cudaGetSymbolAddress((void**)&qhp,   g_qh);
    cudaGetSymbolAddress((void**)&khp,   g_kh);
    cudaGetSymbolAddress((void**)&vhp,   g_vh);
    cudaGetSymbolAddress((void**)&y,     g_y);
    cudaGetSymbolAddress((void**)&x1,    g_x1);
    cudaGetSymbolAddress((void**)&hbuf,  g_h);
    cudaGetSymbolAddress((void**)&agate, g_agate);
    cudaGetSymbolAddress((void**)&vgate, g_vgate);
    cudaGetSymbolAddress((void**)&wqkv,  g_wqkv);
    cudaGetSymbolAddress((void**)&wfc,   g_wfc);
    cudaGetSymbolAddress((void**)&wp,    g_wp);

    cudaFuncSetAttribute(flash_mma_kernel, cudaFuncAttributeMaxDynamicSharedMemorySize,
                         FL_SMEM);
    cudaFuncSetAttribute((const void*)f16_gemm_kernel<0,1>,
                         cudaFuncAttributeMaxDynamicSharedMemorySize, GEMM_SMEM);
    cudaFuncSetAttribute((const void*)f16_gemm_kernel<1,1>,
                         cudaFuncAttributeMaxDynamicSharedMemorySize, GEMM_SMEM);
    cudaFuncSetAttribute((const void*)f16_gemm_kernel<2,1>,
                         cudaFuncAttributeMaxDynamicSharedMemorySize, GEMM_SMEM);
    cudaFuncSetAttribute((const void*)f16_gemm_kernel<2,0>,
                         cudaFuncAttributeMaxDynamicSharedMemorySize, GEMM_SMEM);

    // weight conversions (all coalesced; c_proj kept in native [K,N] layout)
    round_f16_kernel<<<(4 * DIM * DIM / 8 + 255) / 256, 256>>>(qkvo_w, wqkv, 4 * DIM * DIM / 8);
    round_f16_kernel<<<((size_t)FFN * DIM / 8 + 255) / 256, 256>>>(c_fc, wfc, FFN * DIM / 8);
    round_f16_kernel<<<((size_t)FFN * DIM / 8 + 255) / 256, 256>>>(c_proj, wp, FFN * DIM / 8);

    // 1. xn = fp16(rmsnorm(x))
    rmsnorm_kernel<<<T_SEQ, 256>>>(x, xn);
    // 2. gate logits (tiled, low weight traffic)
    gates2_kernel<<<T_SEQ / 16, 256>>>(xn, attn_gate_w, ve_gate_w, agate, vgate);
    // 3. qkv = lam0 * xn @ Wqkv^T  (fp32 out)
    f16_gemm_kernel<0,1><<<dim3(3 * DIM / GBN, T_SEQ / GBM), 512, GEMM_SMEM>>>(
        xn, wqkv, qkv, nullptr, sa_lambdas, 0, 3 * DIM, DIM);
    // 4. per-head rmsnorm + rotary -> qh (fp16), krot (fp32)
    qkrot_kernel<<<dim3(32, T_SEQ), 128>>>(qkv, qhp, krot, cosb, sinb);
    // 5. fused key-offset shift + v update -> kh, vh (fp16)
    kv_post_kernel<<<(2 * T_SEQ * NH * HD) / 256, 256>>>(
        krot, qkv, ve, vgate, key_offset, khp, vhp);
    // 6. fp16 MMA flash attention -> y (fp16)
    flash_mma_kernel<<<dim3(T_SEQ / 64, NH), 128, FL_SMEM>>>(
        qhp, khp, vhp, docs, attn_scale, agate, y);
    // 7. x1 = x + lam1 * y @ Wo^T
    f16_gemm_kernel<2,1><<<dim3(DIM / GBN, T_SEQ / GBM), 512, GEMM_SMEM>>>(
        y, wqkv + (size_t)3 * DIM * DIM, x1, x, sa_lambdas, 1, DIM, DIM);
    // 8. xn = fp16(rmsnorm(x1))
    rmsnorm_kernel<<<T_SEQ, 256>>>(x1, xn);
    // 9. h = fp16(relu(xn @ c_fc^T)^2)
    f16_gemm_kernel<1,1><<<dim3(FFN / GBN, T_SEQ / GBM), 512, GEMM_SMEM>>>(
        xn, wfc, hbuf, nullptr, nullptr, 0, FFN, DIM);
    // 10. out = x1 + h @ c_proj  (B native [K,N], trans-ldmatrix path)
    f16_gemm_kernel<2,0><<<dim3(DIM / GBN, T_SEQ / GBM), 512, GEMM_SMEM>>>(
        hbuf, wp, out, x1, nullptr, 0, DIM, FFN);
}

// round 11
// speedup vs baseline: 8.3432x; 1.0810x over previous
#include <cuda_runtime.h>
#include <cuda_fp16.h>
#include <cstdint>
#include <cstddef>

// ---------------- problem constants ----------------
#define T_SEQ 2048
#define DIM   2048
#define NH    16
#define HD    128
#define FFN   8192
#define EPS_F 1.1920929e-07f
#define NEG_INF_F (-1e30f)

// ---------------- scratch (device globals; no runtime allocs) ----------------
__device__ __half g_xn  [(size_t)T_SEQ * DIM];     // fp16 rmsnorm output
__device__ float  g_qkv [(size_t)T_SEQ * 3 * DIM]; // [T, 48, 128] fp32
__device__ float  g_krot[(size_t)T_SEQ * NH * HD]; // rotated k pre-shift (fp32)
__device__ __half g_qh  [(size_t)T_SEQ * NH * HD]; // fp16 q for flash
__device__ __half g_kh  [(size_t)T_SEQ * NH * HD]; // fp16 shifted k for flash
__device__ __half g_vh  [(size_t)T_SEQ * NH * HD]; // fp16 v for flash
__device__ __half g_y   [(size_t)T_SEQ * DIM];     // fp16 attention output
__device__ float  g_x1  [(size_t)T_SEQ * DIM];
__device__ __half g_h   [(size_t)T_SEQ * FFN];     // fp16 MLP hidden
__device__ float  g_agate[(size_t)T_SEQ * NH];
__device__ float  g_vgate[(size_t)T_SEQ * NH];

// ---------------- helpers ----------------
__device__ __forceinline__ uint32_t pack2h(float a, float b) {
    __half2 h = __floats2half2_rn(a, b);
    return *(uint32_t*)&h;
}
__device__ __forceinline__ void cp_async16(uint32_t dst, const void* src) {
    asm volatile("cp.async.cg.shared.global [%0], [%1], 16;" :: "r"(dst), "l"(src));
}
__device__ __forceinline__ void cp_async_commit() {
    asm volatile("cp.async.commit_group;" ::: "memory");
}
template<int N>
__device__ __forceinline__ void cp_async_wait() {
    asm volatile("cp.async.wait_group %0;" :: "n"(N) : "memory");
}
__device__ __forceinline__ uint32_t smem_u32(const void* p) {
    uint32_t a;
    asm("{ .reg .u64 t; cvta.to.shared.u64 t, %1; cvt.u32.u64 %0, t; }" : "=r"(a) : "l"(p));
    return a;
}
__device__ __forceinline__ void ldsm_x4(uint32_t& r0, uint32_t& r1, uint32_t& r2, uint32_t& r3,
                                        uint32_t addr) {
    asm volatile("ldmatrix.sync.aligned.m8n8.x4.shared.b16 {%0,%1,%2,%3}, [%4];"
                 : "=r"(r0), "=r"(r1), "=r"(r2), "=r"(r3) : "r"(addr));
}
__device__ __forceinline__ void ldsm_x4_t(uint32_t& r0, uint32_t& r1, uint32_t& r2, uint32_t& r3,
                                          uint32_t addr) {
    asm volatile("ldmatrix.sync.aligned.m8n8.x4.trans.shared.b16 {%0,%1,%2,%3}, [%4];"
                 : "=r"(r0), "=r"(r1), "=r"(r2), "=r"(r3) : "r"(addr));
}
__device__ __forceinline__ void mma_f16(float& c0, float& c1, float& c2, float& c3,
                                        uint32_t a0, uint32_t a1, uint32_t a2, uint32_t a3,
                                        uint32_t b0, uint32_t b1) {
    asm volatile("mma.sync.aligned.m16n8k16.row.col.f32.f16.f16.f32 "
                 "{%0,%1,%2,%3}, {%4,%5,%6,%7}, {%8,%9}, {%0,%1,%2,%3};"
                 : "+f"(c0), "+f"(c1), "+f"(c2), "+f"(c3)
                 : "r"(a0), "r"(a1), "r"(a2), "r"(a3), "r"(b0), "r"(b1));
}

// ================= fp16 warp-MMA GEMM with fused fp32->fp16 B conversion =================
// C[M,N] = epi(alpha * A[M,K] @ op(B)); A fp16, B fp32 (converted in-kernel).
// BT=1: B [N,K] row-major. BT=0: B [K,N] row-major.
// BM=256 BN=128 BK=64, 512 threads (16 warps, 4x4 of 64x32 warp tiles).
// A: 4-stage cp.async; B: LDG fp32 -> regs -> convert -> STS fp16, 2-stage ring.
#define GBM 256
#define GBN 128
#define GBK 64
#define GSTAGES 4
#define ROWH 72
#define BROWB 272
#define A_STAGE_B (GBM * ROWH * 2)            // 36864 bytes
#define B_STAGE_B 18432                       // fp16 B stage (128x144 or 64x272)
#define B_BASE (GSTAGES * A_STAGE_B)          // 147456
#define GEMM_SMEM (B_BASE + 2 * B_STAGE_B)    // 184320 bytes

// EPI: 0=none->float, 1=relu^2->half, 2=add residual->float
template<int EPI, int BT>
__global__ void __launch_bounds__(512, 1)
f16_gemm_kernel(const __half* __restrict__ A, const float* __restrict__ B,
                void* __restrict__ Cv, const float* __restrict__ addsrc,
                const float* __restrict__ alpha_ptr, int alpha_idx,
                int N, int K)
{
    extern __shared__ char smc[];
    const int tid = threadIdx.x;
    const int wid = tid >> 5, lane = tid & 31;
    const int g = lane >> 2, tig = lane & 3;
    const int wm = (wid & 3) * 64, wn = (wid >> 2) * 32;
    const int bn = blockIdx.x, bm = blockIdx.y;
    const int nk = K / GBK;
    const uint32_t sb = smem_u32(smc);

    const __half* Agm = A + (size_t)bm * GBM * K;
    const float*  Bgm = BT ? (B + (size_t)bn * GBN * K) : B;

    auto load_A = [&](int stage, int ktile) {
        uint32_t sa = sb + stage * A_STAGE_B;
        int kt = ktile * GBK;
        #pragma unroll
        for (int i = 0; i < 4; i++) {
            int c = tid + i * 512;
            int row = c >> 3, ch = c & 7;
            cp_async16(sa + (uint32_t)row * 144 + ch * 16,
                       Agm + (size_t)row * K + kt + ch * 8);
        }
    };

    float4 breg[2][2];
    auto ldg_B = [&](int ktile) {
        int kt = ktile * GBK;
        #pragma unroll
        for (int i = 0; i < 2; i++) {
            int c = tid + i * 512;
            const float* p;
            if (BT) {
                int row = c >> 3, ch = c & 7;
                p = Bgm + (size_t)row * K + kt + ch * 8;
            } else {
                int row = c >> 4, ch = c & 15;
                p = Bgm + (size_t)(kt + row) * N + bn * GBN + ch * 8;
            }
            breg[i][0] = *(const float4*)p;
            breg[i][1] = *(const float4*)(p + 4);
        }
    };
    auto sts_B = [&](int bstage) {
        #pragma unroll
        for (int i = 0; i < 2; i++) {
            int c = tid + i * 512;
            uint32_t off;
            if (BT) { int row = c >> 3, ch = c & 7;  off = (uint32_t)row * 144 + ch * 16; }
            else    { int row = c >> 4, ch = c & 15; off = (uint32_t)row * BROWB + ch * 16; }
            uint4 o;
            o.x = pack2h(breg[i][0].x, breg[i][0].y);
            o.y = pack2h(breg[i][0].z, breg[i][0].w);
            o.z = pack2h(breg[i][1].x, breg[i][1].y);
            o.w = pack2h(breg[i][1].z, breg[i][1].w);
            *(uint4*)&smc[B_BASE + bstage * B_STAGE_B + off] = o;
        }
    };

    // per-thread ldmatrix byte offsets
    uint32_t aoff[4], boff[2];
    #pragma unroll
    for (int mt = 0; mt < 4; mt++)
        aoff[mt] = (uint32_t)(wm + mt * 16 + (lane & 7) + ((lane >> 3) & 1) * 8) * 144
                 + ((lane >> 4) & 1) * 16;
    if (BT) {
        #pragma unroll
        for (int nb = 0; nb < 2; nb++)
            boff[nb] = (uint32_t)(wn + nb * 16 + (lane & 7) + ((lane >> 4) & 1) * 8) * 144
                     + ((lane >> 3) & 1) * 16;
    } else {
        #pragma unroll
        for (int nb = 0; nb < 2; nb++)
            boff[nb] = (uint32_t)((lane & 7) + ((lane >> 3) & 1) * 8) * BROWB
                     + (wn + nb * 16) * 2 + ((lane >> 4) & 1) * 16;
    }

    float acc[4][4][4];
    #pragma unroll
    for (int mt = 0; mt < 4; mt++)
        #pragma unroll
        for (int nt = 0; nt < 4; nt++)
            #pragma unroll
            for (int q = 0; q < 4; q++) acc[mt][nt][q] = 0.f;

    // prologue: B0 staged, B1 held in regs; A0..A2 via cp.async
    ldg_B(0); sts_B(0);
    ldg_B(1);
    #pragma unroll
    for (int s = 0; s < GSTAGES - 1; s++) { load_A(s, s); cp_async_commit(); }

    for (int k = 0; k < nk; k++) {
        cp_async_wait<GSTAGES - 2>();
        __syncthreads();
        if (k + 1 < nk) sts_B((k + 1) & 1);        // from regs loaded last iter
        if (k + 2 < nk) ldg_B(k + 2);
        if (k + GSTAGES - 1 < nk) load_A((k + GSTAGES - 1) & (GSTAGES - 1),
                                         k + GSTAGES - 1);
        cp_async_commit();

        uint32_t sa = sb + (k & (GSTAGES - 1)) * A_STAGE_B;
        uint32_t sB = sb + B_BASE + (k & 1) * B_STAGE_B;

        #pragma unroll
        for (int ks = 0; ks < 4; ks++) {
            uint32_t a[4][4];
            #pragma unroll
            for (int mt = 0; mt < 4; mt++)
                ldsm_x4(a[mt][0], a[mt][1], a[mt][2], a[mt][3],
                        sa + aoff[mt] + ks * 32);
            #pragma unroll
            for (int nb = 0; nb < 2; nb++) {
                uint32_t b0, b1, b2, b3;
                if (BT) ldsm_x4(b0, b1, b2, b3, sB + boff[nb] + ks * 32);
                else    ldsm_x4_t(b0, b1, b2, b3, sB + boff[nb] + ks * 16 * BROWB);
                #pragma unroll
                for (int mt = 0; mt < 4; mt++) {
                    mma_f16(acc[mt][2 * nb][0], acc[mt][2 * nb][1],
                            acc[mt][2 * nb][2], acc[mt][2 * nb][3],
                            a[mt][0], a[mt][1], a[mt][2], a[mt][3], b0, b1);
                    mma_f16(acc[mt][2 * nb + 1][0], acc[mt][2 * nb + 1][1],
                            acc[mt][2 * nb + 1][2], acc[mt][2 * nb + 1][3],
                            a[mt][0], a[mt][1], a[mt][2], a[mt][3], b2, b3);
                }
            }
        }
    }

    float alpha = alpha_ptr ? alpha_ptr[alpha_idx] : 1.0f;
    #pragma unroll
    for (int mt = 0; mt < 4; mt++) {
        #pragma unroll
        for (int half_i = 0; half_i < 2; half_i++) {
            int row = bm * GBM + wm + mt * 16 + g + half_i * 8;
            #pragma unroll
            for (int nt = 0; nt < 4; nt++) {
                int col = bn * GBN + wn + nt * 8 + tig * 2;
                float vx = acc[mt][nt][half_i * 2 + 0] * alpha;
                float vy = acc[mt][nt][half_i * 2 + 1] * alpha;
                size_t idx = (size_t)row * N + col;
                if (EPI == 1) {
                    vx = fmaxf(vx, 0.f); vx = vx * vx;
                    vy = fmaxf(vy, 0.f); vy = vy * vy;
                    *(__half2*)((__half*)Cv + idx) = __floats2half2_rn(vx, vy);
                } else if (EPI == 2) {
                    float2 a2 = *(const float2*)&addsrc[idx];
                    float2 v; v.x = vx + a2.x; v.y = vy + a2.y;
                    *(float2*)((float*)Cv + idx) = v;
                } else {
                    float2 v; v.x = vx; v.y = vy;
                    *(float2*)((float*)Cv + idx) = v;
                }
            }
        }
    }
}

// ---------------- RMSNorm (fp16 output) ----------------
__global__ void __launch_bounds__(256) rmsnorm_kernel(const float* __restrict__ in,
                                                      __half* __restrict__ outp) {
    int t = blockIdx.x;
    const float* r = in + (size_t)t * DIM;
    float ss = 0.f;
    float vals[8];
    #pragma unroll
    for (int j = 0; j < 8; j++) {
        float v = r[threadIdx.x + j * 256];
        vals[j] = v; ss += v * v;
    }
    __shared__ float sred[8];
    for (int o = 16; o; o >>= 1) ss += __shfl_xor_sync(0xffffffffu, ss, o);
    if ((threadIdx.x & 31) == 0) sred[threadIdx.x >> 5] = ss;
    __syncthreads();
    float tot = 0.f;
    #pragma unroll
    for (int i = 0; i < 8; i++) tot += sred[i];
    float scale = rsqrtf(tot / (float)DIM + EPS_F);
    #pragma unroll
    for (int j = 0; j < 8; j++)
        outp[(size_t)t * DIM + threadIdx.x + j * 256] = __float2half_rn(vals[j] * scale);
}

// ---------------- gates v2: tiled, low weight traffic ----------------
__global__ void __launch_bounds__(256) gates2_kernel(
    const __half* __restrict__ xn, const float* __restrict__ agw,
    const float* __restrict__ vgw, float* __restrict__ agate,
    float* __restrict__ vgate)
{
    __shared__ __half xs[16][520];
    int t0 = blockIdx.x * 16;
    int t = threadIdx.x & 15, og = threadIdx.x >> 4;
    float acc0 = 0.f, acc1 = 0.f;
    for (int kc = 0; kc < 4; kc++) {
        #pragma unroll
        for (int i = 0; i < 4; i++) {
            int c = threadIdx.x + i * 256;
            int r = c >> 6, co = c & 63;
            *(uint4*)&xs[r][co * 8] =
                *(const uint4*)&xn[(size_t)(t0 + r) * DIM + kc * 512 + co * 8];
        }
        __syncthreads();
        const float* wa = agw + (size_t)og * DIM + kc * 512;
        const float* wv = vgw + (size_t)og * DIM + kc * 512;
        #pragma unroll 8
        for (int kk = 0; kk < 512; kk++) {
            float xv = __half2float(xs[t][kk]);
            acc0 = fmaf(xv, wa[kk], acc0);
            acc1 = fmaf(xv, wv[kk], acc1);
        }
        __syncthreads();
    }
    agate[(t0 + t) * NH + og] = 1.f / (1.f + expf(-acc0));
    vgate[(t0 + t) * NH + og] = 1.f / (1.f + expf(-acc1));
}

// ---------------- per-(t, head-slot) QK rmsnorm + rotary ----------------
__global__ void __launch_bounds__(128) qkrot_kernel(
    const float* __restrict__ qkv, __half* __restrict__ qh,
    float* __restrict__ krot,
    const float* __restrict__ cosb, const float* __restrict__ sinb)
{
    int hs = blockIdx.x;
    int t  = blockIdx.y;
    int d  = threadIdx.x;
    float v = qkv[((size_t)t * 48 + hs) * HD + d];
    __shared__ float sm[HD];
    __shared__ float red[4];
    float ss = v * v;
    for (int o = 16; o; o >>= 1) ss += __shfl_xor_sync(0xffffffffu, ss, o);
    if ((d & 31) == 0) red[d >> 5] = ss;
    __syncthreads();
    float tot = red[0] + red[1] + red[2] + red[3];
    float n = v * rsqrtf(tot / (float)HD + EPS_F);
    sm[d] = n;
    __syncthreads();
    float o;
    if (d < 64) {
        float c = cosb[t * 64 + d], s = sinb[t * 64 + d];
        o = sm[d] * c + sm[d + 64] * s;
    } else {
        float c = cosb[t * 64 + d - 64], s = sinb[t * 64 + d - 64];
        o = -sm[d - 64] * s + sm[d] * c;
    }
    if (hs < 16) qh[((size_t)t * NH + hs) * HD + d] = __float2half_rn(o);
    else         krot[((size_t)t * NH + (hs - 16)) * HD + d] = o;
}

// ---------------- fused key-offset shift + v update (fp16 outputs) ----------------
__global__ void __launch_bounds__(256) kv_post_kernel(
    const float* __restrict__ krot, const float* __restrict__ qkv,
    const float* __restrict__ ve, const float* __restrict__ vgate,
    const int* __restrict__ key_offset,
    __half* __restrict__ kh, __half* __restrict__ vh)
{
    int idx = blockIdx.x * 256 + threadIdx.x;
    int half_sel = idx >= T_SEQ * NH * HD;
    int id = idx - half_sel * (T_SEQ * NH * HD);
    int d = id & 127;
    int h = (id >> 7) & 15;
    int t = id >> 11;
    if (!half_sel) {
        int ko = key_offset[0];
        bool up = (d >= 32 && d < 64) || (d >= 96);
        int st = (ko && up && t > 0) ? (t - 1) : t;
        kh[id] = __float2half_rn(krot[((size_t)st * NH + h) * HD + d]);
    } else {
        float gv = vgate[t * NH + h];
        float v = qkv[((size_t)t * 48 + 32 + h) * HD + d] + gv * ve[id];
        vh[id] = __float2half_rn(v);
    }
}

// ================= fp16 MMA flash attention =================
#define FROW 136
#define FL_SMEM (3 * 64 * FROW * 2 + 256)

__global__ void __launch_bounds__(128) flash_mma_kernel(
    const __half* __restrict__ qh, const __half* __restrict__ kh,
    const __half* __restrict__ vh, const int* __restrict__ docs,
    const float* __restrict__ attn_scale, const float* __restrict__ agate,
    __half* __restrict__ y)
{
    extern __shared__ __half fh[];
    __half* Qs = fh;
    __half* Ks = fh + 64 * FROW;
    __half* Vs = fh + 2 * 64 * FROW;
    int*    kd = (int*)(fh + 3 * 64 * FROW);

    const int tid = threadIdx.x, wid = tid >> 5, lane = tid & 31;
    const int g = lane >> 2, tig = lane & 3;
    const int h = blockIdx.y;
    const int qi = (int)gridDim.x - 1 - (int)blockIdx.x;
    const int qbase = qi * 64;
    const float scale = attn_scale[0];

    #pragma unroll
    for (int i = 0; i < 8; i++) {
        int c = tid + i * 128;
        int r = c >> 4, co = c & 15;
        *(uint4*)&Qs[r * FROW + co * 8] =
            *(const uint4*)&qh[((size_t)(qbase + r) * NH + h) * HD + co * 8];
    }
    const int rg0 = qbase + wid * 16 + g;
    const int rg1 = rg0 + 8;
    const int qd0 = docs[rg0], qd1 = docs[rg1];
    const int qdmin = docs[qbase];

    const uint32_t sQ = smem_u32(Qs), sK = smem_u32(Ks), sV = smem_u32(Vs);
    const uint32_t qoff = (uint32_t)(wid * 16 + (lane & 7) + ((lane >> 3) & 1) * 8) * (FROW * 2)
                        + ((lane >> 4) & 1) * 16;
    uint32_t koff[4], voff[8];
    #pragma unroll
    for (int nb = 0; nb < 4; nb++)
        koff[nb] = (uint32_t)(nb * 16 + (lane & 7) + ((lane >> 4) & 1) * 8) * (FROW * 2)
                 + ((lane >> 3) & 1) * 16;
    #pragma unroll
    for (int nb = 0; nb < 8; nb++)
        voff[nb] = (uint32_t)((lane & 7) + ((lane >> 3) & 1) * 8) * (FROW * 2)
                 + nb * 32 + ((lane >> 4) & 1) * 16;

    float o[16][4] = {};
    float m0 = NEG_INF_F, m1 = NEG_INF_F, l0 = 0.f, l1 = 0.f;
    __syncthreads();

    for (int kb = 0; kb <= qi; kb++) {
        const int kbase = kb * 64;
        if (docs[kbase + 63] < qdmin) continue;
        __syncthreads();
        #pragma unroll
        for (int i = 0; i < 8; i++) {
            int c = tid + i * 128;
            int r = c >> 4, co = c & 15;
            *(uint4*)&Ks[r * FROW + co * 8] =
                *(const uint4*)&kh[((size_t)(kbase + r) * NH + h) * HD + co * 8];
            *(uint4*)&Vs[r * FROW + co * 8] =
                *(const uint4*)&vh[((size_t)(kbase + r) * NH + h) * HD + co * 8];
        }
        if (tid < 64) kd[tid] = docs[kbase + tid];
        __syncthreads();

        float s[8][4] = {};
        #pragma unroll
        for (int ks = 0; ks < 8; ks++) {
            uint32_t a0, a1, a2, a3;
            ldsm_x4(a0, a1, a2, a3, sQ + qoff + ks * 32);
            #pragma unroll
            for (int nb = 0; nb < 4; nb++) {
                uint32_t b0, b1, b2, b3;
                ldsm_x4(b0, b1, b2, b3, sK + koff[nb] + ks * 32);
                mma_f16(s[2 * nb][0], s[2 * nb][1], s[2 * nb][2], s[2 * nb][3],
                        a0, a1, a2, a3, b0, b1);
                mma_f16(s[2 * nb + 1][0], s[2 * nb + 1][1], s[2 * nb + 1][2], s[2 * nb + 1][3],
                        a0, a1, a2, a3, b2, b3);
            }
        }

        float mx0 = m0, mx1 = m1;
        #pragma unroll
        for (int nt = 0; nt < 8; nt++) {
            int c0i = kbase + nt * 8 + 2 * tig;
            int d0 = kd[nt * 8 + 2 * tig], d1 = kd[nt * 8 + 2 * tig + 1];
            float v00 = (c0i     <= rg0 && d0 == qd0) ? s[nt][0] * scale : NEG_INF_F;
            float v01 = (c0i + 1 <= rg0 && d1 == qd0) ? s[nt][1] * scale : NEG_INF_F;
            float v10 = (c0i     <= rg1 && d0 == qd1) ? s[nt][2] * scale : NEG_INF_F;
            float v11 = (c0i + 1 <= rg1 && d1 == qd1) ? s[nt][3] * scale : NEG_INF_F;
            s[nt][0] = v00; s[nt][1] = v01; s[nt][2] = v10; s[nt][3] = v11;
            mx0 = fmaxf(mx0, fmaxf(v00, v01));
            mx1 = fmaxf(mx1, fmaxf(v10, v11));
        }
        mx0 = fmaxf(mx0, __shfl_xor_sync(0xffffffffu, mx0, 1));
        mx0 = fmaxf(mx0, __shfl_xor_sync(0xffffffffu, mx0, 2));
        mx1 = fmaxf(mx1, __shfl_xor_sync(0xffffffffu, mx1, 1));
        mx1 = fmaxf(mx1, __shfl_xor_sync(0xffffffffu, mx1, 2));
        float al0 = __expf(m0 - mx0), al1 = __expf(m1 - mx1);
        m0 = mx0; m1 = mx1;

        float sum0 = 0.f, sum1 = 0.f;
        #pragma unroll
        for (int nt = 0; nt < 8; nt++) {
            s[nt][0] = __expf(s[nt][0] - m0);
            s[nt][1] = __expf(s[nt][1] - m0);
            s[nt][2] = __expf(s[nt][2] - m1);
            s[nt][3] = __expf(s[nt][3] - m1);
            sum0 += s[nt][0] + s[nt][1];
            sum1 += s[nt][2] + s[nt][3];
        }
        sum0 += __shfl_xor_sync(0xffffffffu, sum0, 1);
        sum0 += __shfl_xor_sync(0xffffffffu, sum0, 2);
        sum1 += __shfl_xor_sync(0xffffffffu, sum1, 1);
        sum1 += __shfl_xor_sync(0xffffffffu, sum1, 2);
        l0 = l0 * al0 + sum0;
        l1 = l1 * al1 + sum1;
        #pragma unroll
        for (int nt = 0; nt < 16; nt++) {
            o[nt][0] *= al0; o[nt][1] *= al0;
            o[nt][2] *= al1; o[nt][3] *= al1;
        }

        uint32_t pa[4][4];
        #pragma unroll
        for (int kc = 0; kc < 4; kc++) {
            pa[kc][0] = pack2h(s[2 * kc][0], s[2 * kc][1]);
            pa[kc][1] = pack2h(s[2 * kc][2], s[2 * kc][3]);
            pa[kc][2] = pack2h(s[2 * kc + 1][0], s[2 * kc + 1][1]);
            pa[kc][3] = pack2h(s[2 * kc + 1][2], s[2 * kc + 1][3]);
        }
        #pragma unroll
        for (int kc = 0; kc < 4; kc++) {
            #pragma unroll
            for (int nb = 0; nb < 8; nb++) {
                uint32_t b0, b1, b2, b3;
                ldsm_x4_t(b0, b1, b2, b3, sV + voff[nb] + kc * 16 * (FROW * 2));
                mma_f16(o[2 * nb][0], o[2 * nb][1], o[2 * nb][2], o[2 * nb][3],
                        pa[kc][0], pa[kc][1], pa[kc][2], pa[kc][3], b0, b1);
                mma_f16(o[2 * nb + 1][0], o[2 * nb + 1][1], o[2 * nb + 1][2], o[2 * nb + 1][3],
                        pa[kc][0], pa[kc][1], pa[kc][2], pa[kc][3], b2, b3);
            }
        }
    }

    float f0 = (1.f / l0) * agate[rg0 * NH + h];
    float f1 = (1.f / l1) * agate[rg1 * NH + h];
    #pragma unroll
    for (int nt = 0; nt < 16; nt++) {
        *(__half2*)&y[(size_t)rg0 * DIM + h * HD + nt * 8 + 2 * tig] =
            __floats2half2_rn(o[nt][0] * f0, o[nt][1] * f0);
        *(__half2*)&y[(size_t)rg1 * DIM + h * HD + nt * 8 + 2 * tig] =
            __floats2half2_rn(o[nt][2] * f1, o[nt][3] * f1);
    }
}

// ---------------- launch ----------------
extern "C" void kernel_launch(void* const* d_in, const int* in_sizes, int n_in,
                              void* d_out, int out_size) {
    const float* x           = (const float*)d_in[0];
    const float* ve          = (const float*)d_in[1];
    const float* qkvo_w      = (const float*)d_in[2];
    const float* attn_gate_w = (const float*)d_in[3];
    const float* ve_gate_w   = (const float*)d_in[4];
    const float* c_fc        = (const float*)d_in[5];
    const float* c_proj      = (const float*)d_in[6];
    const float* sa_lambdas  = (const float*)d_in[7];
    const float* cosb        = (const float*)d_in[8];
    const float* sinb        = (const float*)d_in[9];
    const float* attn_scale  = (const float*)d_in[10];
    const int*   docs        = (const int*)d_in[11];
    const int*   key_offset  = (const int*)d_in[12];
    float*       out         = (float*)d_out;

    __half *xn, *qhp, *khp, *vhp, *y, *hbuf;
    float *qkv, *krot, *x1, *agate, *vgate;
    cudaGetSymbolAddress((void**)&xn,    g_xn);
    cudaGetSymbolAddress((void**)&qkv,   g_qkv);
    cudaGetSymbolAddress((void**)&krot,  g_krot);
    cudaGetSymbolAddress((void**)&qhp,   g_qh);
    cudaGetSymbolAddress((void**)&khp,   g_kh);
    cudaGetSymbolAddress((void**)&vhp,   g_vh);
    cudaGetSymbolAddress((void**)&y,     g_y);
    cudaGetSymbolAddress((void**)&x1,    g_x1);
    cudaGetSymbolAddress((void**)&hbuf,  g_h);
    cudaGetSymbolAddress((void**)&agate, g_agate);
    cudaGetSymbolAddress((void**)&vgate, g_vgate);

    cudaFuncSetAttribute(flash_mma_kernel, cudaFuncAttributeMaxDynamicSharedMemorySize,
                         FL_SMEM);
    cudaFuncSetAttribute((const void*)f16_gemm_kernel<0,1>,
                         cudaFuncAttributeMaxDynamicSharedMemorySize, GEMM_SMEM);
    cudaFuncSetAttribute((const void*)f16_gemm_kernel<1,1>,
                         cudaFuncAttributeMaxDynamicSharedMemorySize, GEMM_SMEM);
    cudaFuncSetAttribute((const void*)f16_gemm_kernel<2,1>,
                         cudaFuncAttributeMaxDynamicSharedMemorySize, GEMM_SMEM);
    cudaFuncSetAttribute((const void*)f16_gemm_kernel<2,0>,
                         cudaFuncAttributeMaxDynamicSharedMemorySize, GEMM_SMEM);

    // 1. xn = fp16(rmsnorm(x))
    rmsnorm_kernel<<<T_SEQ, 256>>>(x, xn);
    // 2. gate logits
    gates2_kernel<<<T_SEQ / 16, 256>>>(xn, attn_gate_w, ve_gate_w, agate, vgate);
    // 3. qkv = lam0 * xn @ Wqkv^T  (B fp32, converted in-kernel)
    f16_gemm_kernel<0,1><<<dim3(3 * DIM / GBN, T_SEQ / GBM), 512, GEMM_SMEM>>>(
        xn, qkvo_w, qkv, nullptr, sa_lambdas, 0, 3 * DIM, DIM);
    // 4. per-head rmsnorm + rotary -> qh (fp16), krot (fp32)
    qkrot_kernel<<<dim3(32, T_SEQ), 128>>>(qkv, qhp, krot, cosb, sinb);
    // 5. fused key-offset shift + v update -> kh, vh (fp16)
    kv_post_kernel<<<(2 * T_SEQ * NH * HD) / 256, 256>>>(
        krot, qkv, ve, vgate, key_offset, khp, vhp);
    // 6. fp16 MMA flash attention -> y (fp16)
    flash_mma_kernel<<<dim3(T_SEQ / 64, NH), 128, FL_SMEM>>>(
        qhp, khp, vhp, docs, attn_scale, agate, y);
    // 7. x1 = x + lam1 * y @ Wo^T
    f16_gemm_kernel<2,1><<<dim3(DIM / GBN, T_SEQ / GBM), 512, GEMM_SMEM>>>(
        y, qkvo_w + (size_t)3 * DIM * DIM, x1, x, sa_lambdas, 1, DIM, DIM);
    // 8. xn = fp16(rmsnorm(x1))
    rmsnorm_kernel<<<T_SEQ, 256>>>(x1, xn);
    // 9. h = fp16(relu(xn @ c_fc^T)^2)
    f16_gemm_kernel<1,1><<<dim3(FFN / GBN, T_SEQ / GBM), 512, GEMM_SMEM>>>(
        xn, c_fc, hbuf, nullptr, nullptr, 0, FFN, DIM);
    // 10. out = x1 + h @ c_proj  (B native [K,N] fp32, trans-ldmatrix path)
    f16_gemm_kernel<2,0><<<dim3(DIM / GBN, T_SEQ / GBM), 512, GEMM_SMEM>>>(
        hbuf, c_proj, out, x1, nullptr, 0, DIM, FFN);
}

// round 12
// speedup vs baseline: 8.5679x; 1.0269x over previous
#include <cuda_runtime.h>
#include <cuda_fp16.h>
#include <cstdint>
#include <cstddef>

// ---------------- problem constants ----------------
#define T_SEQ 2048
#define DIM   2048
#define NH    16
#define HD    128
#define FFN   8192
#define EPS_F 1.1920929e-07f
#define NEG_INF_F (-1e30f)

// ---------------- scratch (device globals; no runtime allocs) ----------------
__device__ __half g_xn  [(size_t)T_SEQ * DIM];     // fp16 rmsnorm output
__device__ float  g_qkv [(size_t)T_SEQ * 3 * DIM]; // [T, 48, 128] fp32
__device__ float  g_krot[(size_t)T_SEQ * NH * HD]; // rotated k pre-shift (fp32)
__device__ __half g_qh  [(size_t)T_SEQ * NH * HD]; // fp16 q for flash
__device__ __half g_kh  [(size_t)T_SEQ * NH * HD]; // fp16 shifted k for flash
__device__ __half g_vh  [(size_t)T_SEQ * NH * HD]; // fp16 v for flash
__device__ __half g_y   [(size_t)T_SEQ * DIM];     // fp16 attention output
__device__ float  g_x1  [(size_t)T_SEQ * DIM];
__device__ __half g_h   [(size_t)T_SEQ * FFN];     // fp16 MLP hidden
__device__ float  g_agate[(size_t)T_SEQ * NH];
__device__ float  g_vgate[(size_t)T_SEQ * NH];

// ---------------- helpers ----------------
__device__ __forceinline__ uint32_t pack2h(float a, float b) {
    __half2 h = __floats2half2_rn(a, b);
    return *(uint32_t*)&h;
}
__device__ __forceinline__ void cp_async16(uint32_t dst, const void* src) {
    asm volatile("cp.async.cg.shared.global [%0], [%1], 16;" :: "r"(dst), "l"(src));
}
__device__ __forceinline__ void cp_async_commit() {
    asm volatile("cp.async.commit_group;" ::: "memory");
}
template<int N>
__device__ __forceinline__ void cp_async_wait() {
    asm volatile("cp.async.wait_group %0;" :: "n"(N) : "memory");
}
__device__ __forceinline__ uint32_t smem_u32(const void* p) {
    uint32_t a;
    asm("{ .reg .u64 t; cvta.to.shared.u64 t, %1; cvt.u32.u64 %0, t; }" : "=r"(a) : "l"(p));
    return a;
}
__device__ __forceinline__ void ldsm_x4(uint32_t& r0, uint32_t& r1, uint32_t& r2, uint32_t& r3,
                                        uint32_t addr) {
    asm volatile("ldmatrix.sync.aligned.m8n8.x4.shared.b16 {%0,%1,%2,%3}, [%4];"
                 : "=r"(r0), "=r"(r1), "=r"(r2), "=r"(r3) : "r"(addr));
}
__device__ __forceinline__ void ldsm_x4_t(uint32_t& r0, uint32_t& r1, uint32_t& r2, uint32_t& r3,
                                          uint32_t addr) {
    asm volatile("ldmatrix.sync.aligned.m8n8.x4.trans.shared.b16 {%0,%1,%2,%3}, [%4];"
                 : "=r"(r0), "=r"(r1), "=r"(r2), "=r"(r3) : "r"(addr));
}
__device__ __forceinline__ void mma_f16(float& c0, float& c1, float& c2, float& c3,
                                        uint32_t a0, uint32_t a1, uint32_t a2, uint32_t a3,
                                        uint32_t b0, uint32_t b1) {
    asm volatile("mma.sync.aligned.m16n8k16.row.col.f32.f16.f16.f32 "
                 "{%0,%1,%2,%3}, {%4,%5,%6,%7}, {%8,%9}, {%0,%1,%2,%3};"
                 : "+f"(c0), "+f"(c1), "+f"(c2), "+f"(c3)
                 : "r"(a0), "r"(a1), "r"(a2), "r"(a3), "r"(b0), "r"(b1));
}

// ================= fp16 warp-MMA GEMM with fused fp32->fp16 B conversion =================
// C[M,N] = epi(alpha * A[M,K] @ op(B)); A fp16, B fp32 (converted in-kernel).
// BT=1: B [N,K] row-major. BT=0: B [K,N] row-major.
// BM=256 BN=128 BK=64, 512 threads (16 warps, 4x4 of 64x32 warp tiles).
// A: 4-stage cp.async; B: LDG fp32 -> regs -> convert -> STS fp16, 2-stage ring.
#define GBM 256
#define GBN 128
#define GBK 64
#define GSTAGES 4
#define ROWH 72
#define BROWB 272
#define A_STAGE_B (GBM * ROWH * 2)            // 36864 bytes
#define B_STAGE_B 18432                       // fp16 B stage (128x144 or 64x272)
#define B_BASE (GSTAGES * A_STAGE_B)          // 147456
#define GEMM_SMEM (B_BASE + 2 * B_STAGE_B)    // 184320 bytes

// EPI: 0=none->float, 1=relu^2->half, 2=add residual->float
template<int EPI, int BT>
__global__ void __launch_bounds__(512, 1)
f16_gemm_kernel(const __half* __restrict__ A, const float* __restrict__ B,
                void* __restrict__ Cv, const float* __restrict__ addsrc,
                const float* __restrict__ alpha_ptr, int alpha_idx,
                int N, int K)
{
    extern __shared__ char smc[];
    const int tid = threadIdx.x;
    const int wid = tid >> 5, lane = tid & 31;
    const int g = lane >> 2, tig = lane & 3;
    const int wm = (wid & 3) * 64, wn = (wid >> 2) * 32;
    const int bn = blockIdx.x, bm = blockIdx.y;
    const int nk = K / GBK;
    const uint32_t sb = smem_u32(smc);

    const __half* Agm = A + (size_t)bm * GBM * K;
    const float*  Bgm = BT ? (B + (size_t)bn * GBN * K) : B;

    auto load_A = [&](int stage, int ktile) {
        uint32_t sa = sb + stage * A_STAGE_B;
        int kt = ktile * GBK;
        #pragma unroll
        for (int i = 0; i < 4; i++) {
            int c = tid + i * 512;
            int row = c >> 3, ch = c & 7;
            cp_async16(sa + (uint32_t)row * 144 + ch * 16,
                       Agm + (size_t)row * K + kt + ch * 8);
        }
    };

    float4 breg[2][2];
    auto ldg_B = [&](int ktile) {
        int kt = ktile * GBK;
        #pragma unroll
        for (int i = 0; i < 2; i++) {
            int c = tid + i * 512;
            const float* p;
            if (BT) {
                int row = c >> 3, ch = c & 7;
                p = Bgm + (size_t)row * K + kt + ch * 8;
            } else {
                int row = c >> 4, ch = c & 15;
                p = Bgm + (size_t)(kt + row) * N + bn * GBN + ch * 8;
            }
            breg[i][0] = *(const float4*)p;
            breg[i][1] = *(const float4*)(p + 4);
        }
    };
    auto sts_B = [&](int bstage) {
        #pragma unroll
        for (int i = 0; i < 2; i++) {
            int c = tid + i * 512;
            uint32_t off;
            if (BT) { int row = c >> 3, ch = c & 7;  off = (uint32_t)row * 144 + ch * 16; }
            else    { int row = c >> 4, ch = c & 15; off = (uint32_t)row * BROWB + ch * 16; }
            uint4 o;
            o.x = pack2h(breg[i][0].x, breg[i][0].y);
            o.y = pack2h(breg[i][0].z, breg[i][0].w);
            o.z = pack2h(breg[i][1].x, breg[i][1].y);
            o.w = pack2h(breg[i][1].z, breg[i][1].w);
            *(uint4*)&smc[B_BASE + bstage * B_STAGE_B + off] = o;
        }
    };

    // per-thread ldmatrix byte offsets
    uint32_t aoff[4], boff[2];
    #pragma unroll
    for (int mt = 0; mt < 4; mt++)
        aoff[mt] = (uint32_t)(wm + mt * 16 + (lane & 7) + ((lane >> 3) & 1) * 8) * 144
                 + ((lane >> 4) & 1) * 16;
    if (BT) {
        #pragma unroll
        for (int nb = 0; nb < 2; nb++)
            boff[nb] = (uint32_t)(wn + nb * 16 + (lane & 7) + ((lane >> 4) & 1) * 8) * 144
                     + ((lane >> 3) & 1) * 16;
    } else {
        #pragma unroll
        for (int nb = 0; nb < 2; nb++)
            boff[nb] = (uint32_t)((lane & 7) + ((lane >> 3) & 1) * 8) * BROWB
                     + (wn + nb * 16) * 2 + ((lane >> 4) & 1) * 16;
    }

    float acc[4][4][4];
    #pragma unroll
    for (int mt = 0; mt < 4; mt++)
        #pragma unroll
        for (int nt = 0; nt < 4; nt++)
            #pragma unroll
            for (int q = 0; q < 4; q++) acc[mt][nt][q] = 0.f;

    // prologue: B0 staged, B1 held in regs; A0..A2 via cp.async
    ldg_B(0); sts_B(0);
    ldg_B(1);
    #pragma unroll
    for (int s = 0; s < GSTAGES - 1; s++) { load_A(s, s); cp_async_commit(); }

    for (int k = 0; k < nk; k++) {
        cp_async_wait<GSTAGES - 2>();
        __syncthreads();
        if (k + 1 < nk) sts_B((k + 1) & 1);        // from regs loaded last iter
        if (k + 2 < nk) ldg_B(k + 2);
        if (k + GSTAGES - 1 < nk) load_A((k + GSTAGES - 1) & (GSTAGES - 1),
                                         k + GSTAGES - 1);
        cp_async_commit();

        uint32_t sa = sb + (k & (GSTAGES - 1)) * A_STAGE_B;
        uint32_t sB = sb + B_BASE + (k & 1) * B_STAGE_B;

        #pragma unroll
        for (int ks = 0; ks < 4; ks++) {
            uint32_t a[4][4];
            #pragma unroll
            for (int mt = 0; mt < 4; mt++)
                ldsm_x4(a[mt][0], a[mt][1], a[mt][2], a[mt][3],
                        sa + aoff[mt] + ks * 32);
            #pragma unroll
            for (int nb = 0; nb < 2; nb++) {
                uint32_t b0, b1, b2, b3;
                if (BT) ldsm_x4(b0, b1, b2, b3, sB + boff[nb] + ks * 32);
                else    ldsm_x4_t(b0, b1, b2, b3, sB + boff[nb] + ks * 16 * BROWB);
                #pragma unroll
                for (int mt = 0; mt < 4; mt++) {
                    mma_f16(acc[mt][2 * nb][0], acc[mt][2 * nb][1],
                            acc[mt][2 * nb][2], acc[mt][2 * nb][3],
                            a[mt][0], a[mt][1], a[mt][2], a[mt][3], b0, b1);
                    mma_f16(acc[mt][2 * nb + 1][0], acc[mt][2 * nb + 1][1],
                            acc[mt][2 * nb + 1][2], acc[mt][2 * nb + 1][3],
                            a[mt][0], a[mt][1], a[mt][2], a[mt][3], b2, b3);
                }
            }
        }
    }

    float alpha = alpha_ptr ? alpha_ptr[alpha_idx] : 1.0f;
    #pragma unroll
    for (int mt = 0; mt < 4; mt++) {
        #pragma unroll
        for (int half_i = 0; half_i < 2; half_i++) {
            int row = bm * GBM + wm + mt * 16 + g + half_i * 8;
            #pragma unroll
            for (int nt = 0; nt < 4; nt++) {
                int col = bn * GBN + wn + nt * 8 + tig * 2;
                float vx = acc[mt][nt][half_i * 2 + 0] * alpha;
                float vy = acc[mt][nt][half_i * 2 + 1] * alpha;
                size_t idx = (size_t)row * N + col;
                if (EPI == 1) {
                    vx = fmaxf(vx, 0.f); vx = vx * vx;
                    vy = fmaxf(vy, 0.f); vy = vy * vy;
                    *(__half2*)((__half*)Cv + idx) = __floats2half2_rn(vx, vy);
                } else if (EPI == 2) {
                    float2 a2 = *(const float2*)&addsrc[idx];
                    float2 v; v.x = vx + a2.x; v.y = vy + a2.y;
                    *(float2*)((float*)Cv + idx) = v;
                } else {
                    float2 v; v.x = vx; v.y = vy;
                    *(float2*)((float*)Cv + idx) = v;
                }
            }
        }
    }
}

// ---------------- RMSNorm (fp16 output) ----------------
__global__ void __launch_bounds__(256) rmsnorm_kernel(const float* __restrict__ in,
                                                      __half* __restrict__ outp) {
    int t = blockIdx.x;
    const float* r = in + (size_t)t * DIM;
    float ss = 0.f;
    float vals[8];
    #pragma unroll
    for (int j = 0; j < 8; j++) {
        float v = r[threadIdx.x + j * 256];
        vals[j] = v; ss += v * v;
    }
    __shared__ float sred[8];
    for (int o = 16; o; o >>= 1) ss += __shfl_xor_sync(0xffffffffu, ss, o);
    if ((threadIdx.x & 31) == 0) sred[threadIdx.x >> 5] = ss;
    __syncthreads();
    float tot = 0.f;
    #pragma unroll
    for (int i = 0; i < 8; i++) tot += sred[i];
    float scale = rsqrtf(tot / (float)DIM + EPS_F);
    #pragma unroll
    for (int j = 0; j < 8; j++)
        outp[(size_t)t * DIM + threadIdx.x + j * 256] = __float2half_rn(vals[j] * scale);
}

// ---------------- gates v2: tiled, low weight traffic ----------------
__global__ void __launch_bounds__(256) gates2_kernel(
    const __half* __restrict__ xn, const float* __restrict__ agw,
    const float* __restrict__ vgw, float* __restrict__ agate,
    float* __restrict__ vgate)
{
    __shared__ __half xs[16][520];
    int t0 = blockIdx.x * 16;
    int t = threadIdx.x & 15, og = threadIdx.x >> 4;
    float acc0 = 0.f, acc1 = 0.f;
    for (int kc = 0; kc < 4; kc++) {
        #pragma unroll
        for (int i = 0; i < 4; i++) {
            int c = threadIdx.x + i * 256;
            int r = c >> 6, co = c & 63;
            *(uint4*)&xs[r][co * 8] =
                *(const uint4*)&xn[(size_t)(t0 + r) * DIM + kc * 512 + co * 8];
        }
        __syncthreads();
        const float* wa = agw + (size_t)og * DIM + kc * 512;
        const float* wv = vgw + (size_t)og * DIM + kc * 512;
        #pragma unroll 8
        for (int kk = 0; kk < 512; kk++) {
            float xv = __half2float(xs[t][kk]);
            acc0 = fmaf(xv, wa[kk], acc0);
            acc1 = fmaf(xv, wv[kk], acc1);
        }
        __syncthreads();
    }
    agate[(t0 + t) * NH + og] = 1.f / (1.f + expf(-acc0));
    vgate[(t0 + t) * NH + og] = 1.f / (1.f + expf(-acc1));
}

// ---------------- warp-per-row QK rmsnorm + rotary (no smem, no barriers) ----------------
// warp handles one (t, hs) row of 128; hs 0..15 -> qh (fp16), 16..31 -> krot (fp32)
__global__ void __launch_bounds__(256) qkrot_kernel(
    const float* __restrict__ qkv, __half* __restrict__ qh,
    float* __restrict__ krot,
    const float* __restrict__ cosb, const float* __restrict__ sinb)
{
    int gw = blockIdx.x * 8 + (threadIdx.x >> 5);
    int lane = threadIdx.x & 31;
    int hs = gw & 31;
    int t  = gw >> 5;
    int d0 = lane * 4;

    float4 v = *(const float4*)&qkv[((size_t)t * 48 + hs) * HD + d0];
    float ss = v.x * v.x + v.y * v.y + v.z * v.z + v.w * v.w;
    #pragma unroll
    for (int o = 16; o; o >>= 1) ss += __shfl_xor_sync(0xffffffffu, ss, o);
    float sc = rsqrtf(ss / (float)HD + EPS_F);
    v.x *= sc; v.y *= sc; v.z *= sc; v.w *= sc;

    // rotary partner (d <-> d+64) lives in lane ^ 16
    float px = __shfl_xor_sync(0xffffffffu, v.x, 16);
    float py = __shfl_xor_sync(0xffffffffu, v.y, 16);
    float pz = __shfl_xor_sync(0xffffffffu, v.z, 16);
    float pw = __shfl_xor_sync(0xffffffffu, v.w, 16);

    int ci = t * 64 + (d0 & 63);
    float4 c = *(const float4*)&cosb[ci];
    float4 s = *(const float4*)&sinb[ci];
    float4 o4;
    if (lane < 16) {
        o4.x = v.x * c.x + px * s.x;
        o4.y = v.y * c.y + py * s.y;
        o4.z = v.z * c.z + pz * s.z;
        o4.w = v.w * c.w + pw * s.w;
    } else {
        o4.x = -px * s.x + v.x * c.x;
        o4.y = -py * s.y + v.y * c.y;
        o4.z = -pz * s.z + v.z * c.z;
        o4.w = -pw * s.w + v.w * c.w;
    }

    if (hs < 16) {
        uint2 hv;
        hv.x = pack2h(o4.x, o4.y);
        hv.y = pack2h(o4.z, o4.w);
        *(uint2*)&qh[((size_t)t * NH + hs) * HD + d0] = hv;
    } else {
        *(float4*)&krot[((size_t)t * NH + (hs - 16)) * HD + d0] = o4;
    }
}

// ---------------- fused key-offset shift + v update (fp16 outputs) ----------------
__global__ void __launch_bounds__(256) kv_post_kernel(
    const float* __restrict__ krot, const float* __restrict__ qkv,
    const float* __restrict__ ve, const float* __restrict__ vgate,
    const int* __restrict__ key_offset,
    __half* __restrict__ kh, __half* __restrict__ vh)
{
    int idx = blockIdx.x * 256 + threadIdx.x;
    int half_sel = idx >= T_SEQ * NH * HD;
    int id = idx - half_sel * (T_SEQ * NH * HD);
    int d = id & 127;
    int h = (id >> 7) & 15;
    int t = id >> 11;
    if (!half_sel) {
        int ko = key_offset[0];
        bool up = (d >= 32 && d < 64) || (d >= 96);
        int st = (ko && up && t > 0) ? (t - 1) : t;
        kh[id] = __float2half_rn(krot[((size_t)st * NH + h) * HD + d]);
    } else {
        float gv = vgate[t * NH + h];
        float v = qkv[((size_t)t * 48 + 32 + h) * HD + d] + gv * ve[id];
        vh[id] = __float2half_rn(v);
    }
}

// ================= fp16 MMA flash attention =================
#define FROW 136
#define FL_SMEM (3 * 64 * FROW * 2 + 256)

__global__ void __launch_bounds__(128) flash_mma_kernel(
    const __half* __restrict__ qh, const __half* __restrict__ kh,
    const __half* __restrict__ vh, const int* __restrict__ docs,
    const float* __restrict__ attn_scale, const float* __restrict__ agate,
    __half* __restrict__ y)
{
    extern __shared__ __half fh[];
    __half* Qs = fh;
    __half* Ks = fh + 64 * FROW;
    __half* Vs = fh + 2 * 64 * FROW;
    int*    kd = (int*)(fh + 3 * 64 * FROW);

    const int tid = threadIdx.x, wid = tid >> 5, lane = tid & 31;
    const int g = lane >> 2, tig = lane & 3;
    const int h = blockIdx.y;
    const int qi = (int)gridDim.x - 1 - (int)blockIdx.x;
    const int qbase = qi * 64;
    const float scale = attn_scale[0];

    #pragma unroll
    for (int i = 0; i < 8; i++) {
        int c = tid + i * 128;
        int r = c >> 4, co = c & 15;
        *(uint4*)&Qs[r * FROW + co * 8] =
            *(const uint4*)&qh[((size_t)(qbase + r) * NH + h) * HD + co * 8];
    }
    const int rg0 = qbase + wid * 16 + g;
    const int rg1 = rg0 + 8;
    const int qd0 = docs[rg0], qd1 = docs[rg1];
    const int qdmin = docs[qbase];

    const uint32_t sQ = smem_u32(Qs), sK = smem_u32(Ks), sV = smem_u32(Vs);
    const uint32_t qoff = (uint32_t)(wid * 16 + (lane & 7) + ((lane >> 3) & 1) * 8) * (FROW * 2)
                        + ((lane >> 4) & 1) * 16;
    uint32_t koff[4], voff[8];
    #pragma unroll
    for (int nb = 0; nb < 4; nb++)
        koff[nb] = (uint32_t)(nb * 16 + (lane & 7) + ((lane >> 4) & 1) * 8) * (FROW * 2)
                 + ((lane >> 3) & 1) * 16;
    #pragma unroll
    for (int nb = 0; nb < 8; nb++)
        voff[nb] = (uint32_t)((lane & 7) + ((lane >> 3) & 1) * 8) * (FROW * 2)
                 + nb * 32 + ((lane >> 4) & 1) * 16;

    float o[16][4] = {};
    float m0 = NEG_INF_F, m1 = NEG_INF_F, l0 = 0.f, l1 = 0.f;
    __syncthreads();

    for (int kb = 0; kb <= qi; kb++) {
        const int kbase = kb * 64;
        if (docs[kbase + 63] < qdmin) continue;
        __syncthreads();
        #pragma unroll
        for (int i = 0; i < 8; i++) {
            int c = tid + i * 128;
            int r = c >> 4, co = c & 15;
            *(uint4*)&Ks[r * FROW + co * 8] =
                *(const uint4*)&kh[((size_t)(kbase + r) * NH + h) * HD + co * 8];
            *(uint4*)&Vs[r * FROW + co * 8] =
                *(const uint4*)&vh[((size_t)(kbase + r) * NH + h) * HD + co * 8];
        }
        if (tid < 64) kd[tid] = docs[kbase + tid];
        __syncthreads();

        float s[8][4] = {};
        #pragma unroll
        for (int ks = 0; ks < 8; ks++) {
            uint32_t a0, a1, a2, a3;
            ldsm_x4(a0, a1, a2, a3, sQ + qoff + ks * 32);
            #pragma unroll
            for (int nb = 0; nb < 4; nb++) {
                uint32_t b0, b1, b2, b3;
                ldsm_x4(b0, b1, b2, b3, sK + koff[nb] + ks * 32);
                mma_f16(s[2 * nb][0], s[2 * nb][1], s[2 * nb][2], s[2 * nb][3],
                        a0, a1, a2, a3, b0, b1);
                mma_f16(s[2 * nb + 1][0], s[2 * nb + 1][1], s[2 * nb + 1][2], s[2 * nb + 1][3],
                        a0, a1, a2, a3, b2, b3);
            }
        }

        float mx0 = m0, mx1 = m1;
        #pragma unroll
        for (int nt = 0; nt < 8; nt++) {
            int c0i = kbase + nt * 8 + 2 * tig;
            int d0 = kd[nt * 8 + 2 * tig], d1 = kd[nt * 8 + 2 * tig + 1];
            float v00 = (c0i     <= rg0 && d0 == qd0) ? s[nt][0] * scale : NEG_INF_F;
            float v01 = (c0i + 1 <= rg0 && d1 == qd0) ? s[nt][1] * scale : NEG_INF_F;
            float v10 = (c0i     <= rg1 && d0 == qd1) ? s[nt][2] * scale : NEG_INF_F;
            float v11 = (c0i + 1 <= rg1 && d1 == qd1) ? s[nt][3] * scale : NEG_INF_F;
            s[nt][0] = v00; s[nt][1] = v01; s[nt][2] = v10; s[nt][3] = v11;
            mx0 = fmaxf(mx0, fmaxf(v00, v01));
            mx1 = fmaxf(mx1, fmaxf(v10, v11));
        }
        mx0 = fmaxf(mx0, __shfl_xor_sync(0xffffffffu, mx0, 1));
        mx0 = fmaxf(mx0, __shfl_xor_sync(0xffffffffu, mx0, 2));
        mx1 = fmaxf(mx1, __shfl_xor_sync(0xffffffffu, mx1, 1));
        mx1 = fmaxf(mx1, __shfl_xor_sync(0xffffffffu, mx1, 2));
        float al0 = __expf(m0 - mx0), al1 = __expf(m1 - mx1);
        m0 = mx0; m1 = mx1;

        float sum0 = 0.f, sum1 = 0.f;
        #pragma unroll
        for (int nt = 0; nt < 8; nt++) {
            s[nt][0] = __expf(s[nt][0] - m0);
            s[nt][1] = __expf(s[nt][1] - m0);
            s[nt][2] = __expf(s[nt][2] - m1);
            s[nt][3] = __expf(s[nt][3] - m1);
            sum0 += s[nt][0] + s[nt][1];
            sum1 += s[nt][2] + s[nt][3];
        }
        sum0 += __shfl_xor_sync(0xffffffffu, sum0, 1);
        sum0 += __shfl_xor_sync(0xffffffffu, sum0, 2);
        sum1 += __shfl_xor_sync(0xffffffffu, sum1, 1);
        sum1 += __shfl_xor_sync(0xffffffffu, sum1, 2);
        l0 = l0 * al0 + sum0;
        l1 = l1 * al1 + sum1;
        #pragma unroll
        for (int nt = 0; nt < 16; nt++) {
            o[nt][0] *= al0; o[nt][1] *= al0;
            o[nt][2] *= al1; o[nt][3] *= al1;
        }

        uint32_t pa[4][4];
        #pragma unroll
        for (int kc = 0; kc < 4; kc++) {
            pa[kc][0] = pack2h(s[2 * kc][0], s[2 * kc][1]);
            pa[kc][1] = pack2h(s[2 * kc][2], s[2 * kc][3]);
            pa[kc][2] = pack2h(s[2 * kc + 1][0], s[2 * kc + 1][1]);
            pa[kc][3] = pack2h(s[2 * kc + 1][2], s[2 * kc + 1][3]);
        }
        #pragma unroll
        for (int kc = 0; kc < 4; kc++) {
            #pragma unroll
            for (int nb = 0; nb < 8; nb++) {
                uint32_t b0, b1, b2, b3;
                ldsm_x4_t(b0, b1, b2, b3, sV + voff[nb] + kc * 16 * (FROW * 2));
                mma_f16(o[2 * nb][0], o[2 * nb][1], o[2 * nb][2], o[2 * nb][3],
                        pa[kc][0], pa[kc][1], pa[kc][2], pa[kc][3], b0, b1);
                mma_f16(o[2 * nb + 1][0], o[2 * nb + 1][1], o[2 * nb + 1][2], o[2 * nb + 1][3],
                        pa[kc][0], pa[kc][1], pa[kc][2], pa[kc][3], b2, b3);
            }
        }
    }

    float f0 = (1.f / l0) * agate[rg0 * NH + h];
    float f1 = (1.f / l1) * agate[rg1 * NH + h];
    #pragma unroll
    for (int nt = 0; nt < 16; nt++) {
        *(__half2*)&y[(size_t)rg0 * DIM + h * HD + nt * 8 + 2 * tig] =
            __floats2half2_rn(o[nt][0] * f0, o[nt][1] * f0);
        *(__half2*)&y[(size_t)rg1 * DIM + h * HD + nt * 8 + 2 * tig] =
            __floats2half2_rn(o[nt][2] * f1, o[nt][3] * f1);
    }
}

// ---------------- launch ----------------
extern "C" void kernel_launch(void* const* d_in, const int* in_sizes, int n_in,
                              void* d_out, int out_size) {
    const float* x           = (const float*)d_in[0];
    const float* ve          = (const float*)d_in[1];
    const float* qkvo_w      = (const float*)d_in[2];
    const float* attn_gate_w = (const float*)d_in[3];
    const float* ve_gate_w   = (const float*)d_in[4];
    const float* c_fc        = (const float*)d_in[5];
    const float* c_proj      = (const float*)d_in[6];
    const float* sa_lambdas  = (const float*)d_in[7];
    const float* cosb        = (const float*)d_in[8];
    const float* sinb        = (const float*)d_in[9];
    const float* attn_scale  = (const float*)d_in[10];
    const int*   docs        = (const int*)d_in[11];
    const int*   key_offset  = (const int*)d_in[12];
    float*       out         = (float*)d_out;

    __half *xn, *qhp, *khp, *vhp, *y, *hbuf;
    float *qkv, *krot, *x1, *agate, *vgate;
    cudaGetSymbolAddress((void**)&xn,    g_xn);
    cudaGetSymbolAddress((void**)&qkv,   g_qkv);
    cudaGetSymbolAddress((void**)&krot,  g_krot);
    cudaGetSymbolAddress((void**)&qhp,   g_qh);
    cudaGetSymbolAddress((void**)&khp,   g_kh);
    cudaGetSymbolAddress((void**)&vhp,   g_vh);
    cudaGetSymbolAddress((void**)&y,     g_y);
    cudaGetSymbolAddress((void**)&x1,    g_x1);
    cudaGetSymbolAddress((void**)&hbuf,  g_h);
    cudaGetSymbolAddress((void**)&agate, g_agate);
    cudaGetSymbolAddress((void**)&vgate, g_vgate);

    cudaFuncSetAttribute(flash_mma_kernel, cudaFuncAttributeMaxDynamicSharedMemorySize,
                         FL_SMEM);
    cudaFuncSetAttribute((const void*)f16_gemm_kernel<0,1>,
                         cudaFuncAttributeMaxDynamicSharedMemorySize, GEMM_SMEM);
    cudaFuncSetAttribute((const void*)f16_gemm_kernel<1,1>,
                         cudaFuncAttributeMaxDynamicSharedMemorySize, GEMM_SMEM);
    cudaFuncSetAttribute((const void*)f16_gemm_kernel<2,1>,
                         cudaFuncAttributeMaxDynamicSharedMemorySize, GEMM_SMEM);
    cudaFuncSetAttribute((const void*)f16_gemm_kernel<2,0>,
                         cudaFuncAttributeMaxDynamicSharedMemorySize, GEMM_SMEM);

    // 1. xn = fp16(rmsnorm(x))
    rmsnorm_kernel<<<T_SEQ, 256>>>(x, xn);
    // 2. gate logits
    gates2_kernel<<<T_SEQ / 16, 256>>>(xn, attn_gate_w, ve_gate_w, agate, vgate);
    // 3. qkv = lam0 * xn @ Wqkv^T  (B fp32, converted in-kernel)
    f16_gemm_kernel<0,1><<<dim3(3 * DIM / GBN, T_SEQ / GBM), 512, GEMM_SMEM>>>(
        xn, qkvo_w, qkv, nullptr, sa_lambdas, 0, 3 * DIM, DIM);
    // 4. warp-per-row QK rmsnorm + rotary -> qh (fp16), krot (fp32)
    qkrot_kernel<<<(T_SEQ * 32) / 8, 256>>>(qkv, qhp, krot, cosb, sinb);
    // 5. fused key-offset shift + v update -> kh, vh (fp16)
    kv_post_kernel<<<(2 * T_SEQ * NH * HD) / 256, 256>>>(
        krot, qkv, ve, vgate, key_offset, khp, vhp);
    // 6. fp16 MMA flash attention -> y (fp16)
    flash_mma_kernel<<<dim3(T_SEQ / 64, NH), 128, FL_SMEM>>>(
        qhp, khp, vhp, docs, attn_scale, agate, y);
    // 7. x1 = x + lam1 * y @ Wo^T
    f16_gemm_kernel<2,1><<<dim3(DIM / GBN, T_SEQ / GBM), 512, GEMM_SMEM>>>(
        y, qkvo_w + (size_t)3 * DIM * DIM, x1, x, sa_lambdas, 1, DIM, DIM);
    // 8. xn = fp16(rmsnorm(x1))
    rmsnorm_kernel<<<T_SEQ, 256>>>(x1, xn);
    // 9. h = fp16(relu(xn @ c_fc^T)^2)
    f16_gemm_kernel<1,1><<<dim3(FFN / GBN, T_SEQ / GBM), 512, GEMM_SMEM>>>(
        xn, c_fc, hbuf, nullptr, nullptr, 0, FFN, DIM);
    // 10. out = x1 + h @ c_proj  (B native [K,N] fp32, trans-ldmatrix path)
    f16_gemm_kernel<2,0><<<dim3(DIM / GBN, T_SEQ / GBM), 512, GEMM_SMEM>>>(
        hbuf, c_proj, out, x1, nullptr, 0, DIM, FFN);
}

// round 13
// speedup vs baseline: 8.7557x; 1.0219x over previous
#include <cuda_runtime.h>
#include <cuda_fp16.h>
#include <cstdint>
#include <cstddef>

// ---------------- problem constants ----------------
#define T_SEQ 2048
#define DIM   2048
#define NH    16
#define HD    128
#define FFN   8192
#define EPS_F 1.1920929e-07f
#define NEG_INF_F (-1e30f)

// ---------------- scratch (device globals; no runtime allocs) ----------------
__device__ __half g_xn  [(size_t)T_SEQ * DIM];     // fp16 rmsnorm output
__device__ float  g_qkv [(size_t)T_SEQ * 3 * DIM]; // [T, 48, 128] fp32
__device__ __half g_qh  [(size_t)T_SEQ * NH * HD]; // fp16 q for flash
__device__ __half g_kh  [(size_t)T_SEQ * NH * HD]; // fp16 shifted k for flash
__device__ __half g_vh  [(size_t)T_SEQ * NH * HD]; // fp16 v for flash
__device__ __half g_y   [(size_t)T_SEQ * DIM];     // fp16 attention output
__device__ float  g_x1  [(size_t)T_SEQ * DIM];
__device__ __half g_h   [(size_t)T_SEQ * FFN];     // fp16 MLP hidden
__device__ float  g_agate[(size_t)T_SEQ * NH];
__device__ float  g_vgate[(size_t)T_SEQ * NH];

// ---------------- helpers ----------------
__device__ __forceinline__ uint32_t pack2h(float a, float b) {
    __half2 h = __floats2half2_rn(a, b);
    return *(uint32_t*)&h;
}
__device__ __forceinline__ void cp_async16(uint32_t dst, const void* src) {
    asm volatile("cp.async.cg.shared.global [%0], [%1], 16;" :: "r"(dst), "l"(src));
}
__device__ __forceinline__ void cp_async_commit() {
    asm volatile("cp.async.commit_group;" ::: "memory");
}
template<int N>
__device__ __forceinline__ void cp_async_wait() {
    asm volatile("cp.async.wait_group %0;" :: "n"(N) : "memory");
}
__device__ __forceinline__ uint32_t smem_u32(const void* p) {
    uint32_t a;
    asm("{ .reg .u64 t; cvta.to.shared.u64 t, %1; cvt.u32.u64 %0, t; }" : "=r"(a) : "l"(p));
    return a;
}
__device__ __forceinline__ void ldsm_x4(uint32_t& r0, uint32_t& r1, uint32_t& r2, uint32_t& r3,
                                        uint32_t addr) {
    asm volatile("ldmatrix.sync.aligned.m8n8.x4.shared.b16 {%0,%1,%2,%3}, [%4];"
                 : "=r"(r0), "=r"(r1), "=r"(r2), "=r"(r3) : "r"(addr));
}
__device__ __forceinline__ void ldsm_x4_t(uint32_t& r0, uint32_t& r1, uint32_t& r2, uint32_t& r3,
                                          uint32_t addr) {
    asm volatile("ldmatrix.sync.aligned.m8n8.x4.trans.shared.b16 {%0,%1,%2,%3}, [%4];"
                 : "=r"(r0), "=r"(r1), "=r"(r2), "=r"(r3) : "r"(addr));
}
__device__ __forceinline__ void mma_f16(float& c0, float& c1, float& c2, float& c3,
                                        uint32_t a0, uint32_t a1, uint32_t a2, uint32_t a3,
                                        uint32_t b0, uint32_t b1) {
    asm volatile("mma.sync.aligned.m16n8k16.row.col.f32.f16.f16.f32 "
                 "{%0,%1,%2,%3}, {%4,%5,%6,%7}, {%8,%9}, {%0,%1,%2,%3};"
                 : "+f"(c0), "+f"(c1), "+f"(c2), "+f"(c3)
                 : "r"(a0), "r"(a1), "r"(a2), "r"(a3), "r"(b0), "r"(b1));
}

// ================= fp16 warp-MMA GEMM with fused fp32->fp16 B conversion =================
// C[M,N] = epi(alpha * A[M,K] @ op(B)); A fp16, B fp32 (converted in-kernel).
// BT=1: B [N,K] row-major. BT=0: B [K,N] row-major.
// BM=256 BN=128 BK=64, 512 threads (16 warps, 4x4 of 64x32 warp tiles).
// A: 4-stage cp.async; B: LDG fp32 -> regs -> convert -> STS fp16, 2-stage ring.
#define GBM 256
#define GBN 128
#define GBK 64
#define GSTAGES 4
#define ROWH 72
#define BROWB 272
#define A_STAGE_B (GBM * ROWH * 2)            // 36864 bytes
#define B_STAGE_B 18432                       // fp16 B stage (128x144 or 64x272)
#define B_BASE (GSTAGES * A_STAGE_B)          // 147456
#define GEMM_SMEM (B_BASE + 2 * B_STAGE_B)    // 184320 bytes

// EPI: 0=none->float, 1=relu^2->half, 2=add residual->float
template<int EPI, int BT>
__global__ void __launch_bounds__(512, 1)
f16_gemm_kernel(const __half* __restrict__ A, const float* __restrict__ B,
                void* __restrict__ Cv, const float* __restrict__ addsrc,
                const float* __restrict__ alpha_ptr, int alpha_idx,
                int N, int K)
{
    extern __shared__ char smc[];
    const int tid = threadIdx.x;
    const int wid = tid >> 5, lane = tid & 31;
    const int g = lane >> 2, tig = lane & 3;
    const int wm = (wid & 3) * 64, wn = (wid >> 2) * 32;
    const int bn = blockIdx.x, bm = blockIdx.y;
    const int nk = K / GBK;
    const uint32_t sb = smem_u32(smc);

    const __half* Agm = A + (size_t)bm * GBM * K;
    const float*  Bgm = BT ? (B + (size_t)bn * GBN * K) : B;

    auto load_A = [&](int stage, int ktile) {
        uint32_t sa = sb + stage * A_STAGE_B;
        int kt = ktile * GBK;
        #pragma unroll
        for (int i = 0; i < 4; i++) {
            int c = tid + i * 512;
            int row = c >> 3, ch = c & 7;
            cp_async16(sa + (uint32_t)row * 144 + ch * 16,
                       Agm + (size_t)row * K + kt + ch * 8);
        }
    };

    float4 breg[2][2];
    auto ldg_B = [&](int ktile) {
        int kt = ktile * GBK;
        #pragma unroll
        for (int i = 0; i < 2; i++) {
            int c = tid + i * 512;
            const float* p;
            if (BT) {
                int row = c >> 3, ch = c & 7;
                p = Bgm + (size_t)row * K + kt + ch * 8;
            } else {
                int row = c >> 4, ch = c & 15;
                p = Bgm + (size_t)(kt + row) * N + bn * GBN + ch * 8;
            }
            breg[i][0] = *(const float4*)p;
            breg[i][1] = *(const float4*)(p + 4);
        }
    };
    auto sts_B = [&](int bstage) {
        #pragma unroll
        for (int i = 0; i < 2; i++) {
            int c = tid + i * 512;
            uint32_t off;
            if (BT) { int row = c >> 3, ch = c & 7;  off = (uint32_t)row * 144 + ch * 16; }
            else    { int row = c >> 4, ch = c & 15; off = (uint32_t)row * BROWB + ch * 16; }
            uint4 o;
            o.x = pack2h(breg[i][0].x, breg[i][0].y);
            o.y = pack2h(breg[i][0].z, breg[i][0].w);
            o.z = pack2h(breg[i][1].x, breg[i][1].y);
            o.w = pack2h(breg[i][1].z, breg[i][1].w);
            *(uint4*)&smc[B_BASE + bstage * B_STAGE_B + off] = o;
        }
    };

    // per-thread ldmatrix byte offsets
    uint32_t aoff[4], boff[2];
    #pragma unroll
    for (int mt = 0; mt < 4; mt++)
        aoff[mt] = (uint32_t)(wm + mt * 16 + (lane & 7) + ((lane >> 3) & 1) * 8) * 144
                 + ((lane >> 4) & 1) * 16;
    if (BT) {
        #pragma unroll
        for (int nb = 0; nb < 2; nb++)
            boff[nb] = (uint32_t)(wn + nb * 16 + (lane & 7) + ((lane >> 4) & 1) * 8) * 144
                     + ((lane >> 3) & 1) * 16;
    } else {
        #pragma unroll
        for (int nb = 0; nb < 2; nb++)
            boff[nb] = (uint32_t)((lane & 7) + ((lane >> 3) & 1) * 8) * BROWB
                     + (wn + nb * 16) * 2 + ((lane >> 4) & 1) * 16;
    }

    float acc[4][4][4];
    #pragma unroll
    for (int mt = 0; mt < 4; mt++)
        #pragma unroll
        for (int nt = 0; nt < 4; nt++)
            #pragma unroll
            for (int q = 0; q < 4; q++) acc[mt][nt][q] = 0.f;

    // prologue: B0 staged, B1 held in regs; A0..A2 via cp.async
    ldg_B(0); sts_B(0);
    ldg_B(1);
    #pragma unroll
    for (int s = 0; s < GSTAGES - 1; s++) { load_A(s, s); cp_async_commit(); }

    for (int k = 0; k < nk; k++) {
        cp_async_wait<GSTAGES - 2>();
        __syncthreads();
        if (k + 1 < nk) sts_B((k + 1) & 1);        // from regs loaded last iter
        if (k + 2 < nk) ldg_B(k + 2);
        if (k + GSTAGES - 1 < nk) load_A((k + GSTAGES - 1) & (GSTAGES - 1),
                                         k + GSTAGES - 1);
        cp_async_commit();

        uint32_t sa = sb + (k & (GSTAGES - 1)) * A_STAGE_B;
        uint32_t sB = sb + B_BASE + (k & 1) * B_STAGE_B;

        #pragma unroll
        for (int ks = 0; ks < 4; ks++) {
            uint32_t a[4][4];
            #pragma unroll
            for (int mt = 0; mt < 4; mt++)
                ldsm_x4(a[mt][0], a[mt][1], a[mt][2], a[mt][3],
                        sa + aoff[mt] + ks * 32);
            #pragma unroll
            for (int nb = 0; nb < 2; nb++) {
                uint32_t b0, b1, b2, b3;
                if (BT) ldsm_x4(b0, b1, b2, b3, sB + boff[nb] + ks * 32);
                else    ldsm_x4_t(b0, b1, b2, b3, sB + boff[nb] + ks * 16 * BROWB);
                #pragma unroll
                for (int mt = 0; mt < 4; mt++) {
                    mma_f16(acc[mt][2 * nb][0], acc[mt][2 * nb][1],
                            acc[mt][2 * nb][2], acc[mt][2 * nb][3],
                            a[mt][0], a[mt][1], a[mt][2], a[mt][3], b0, b1);
                    mma_f16(acc[mt][2 * nb + 1][0], acc[mt][2 * nb + 1][1],
                            acc[mt][2 * nb + 1][2], acc[mt][2 * nb + 1][3],
                            a[mt][0], a[mt][1], a[mt][2], a[mt][3], b2, b3);
                }
            }
        }
    }

    float alpha = alpha_ptr ? alpha_ptr[alpha_idx] : 1.0f;
    #pragma unroll
    for (int mt = 0; mt < 4; mt++) {
        #pragma unroll
        for (int half_i = 0; half_i < 2; half_i++) {
            int row = bm * GBM + wm + mt * 16 + g + half_i * 8;
            #pragma unroll
            for (int nt = 0; nt < 4; nt++) {
                int col = bn * GBN + wn + nt * 8 + tig * 2;
                float vx = acc[mt][nt][half_i * 2 + 0] * alpha;
                float vy = acc[mt][nt][half_i * 2 + 1] * alpha;
                size_t idx = (size_t)row * N + col;
                if (EPI == 1) {
                    vx = fmaxf(vx, 0.f); vx = vx * vx;
                    vy = fmaxf(vy, 0.f); vy = vy * vy;
                    *(__half2*)((__half*)Cv + idx) = __floats2half2_rn(vx, vy);
                } else if (EPI == 2) {
                    float2 a2 = *(const float2*)&addsrc[idx];
                    float2 v; v.x = vx + a2.x; v.y = vy + a2.y;
                    *(float2*)((float*)Cv + idx) = v;
                } else {
                    float2 v; v.x = vx; v.y = vy;
                    *(float2*)((float*)Cv + idx) = v;
                }
            }
        }
    }
}

// ---------------- RMSNorm (fp16 output) ----------------
__global__ void __launch_bounds__(256) rmsnorm_kernel(const float* __restrict__ in,
                                                      __half* __restrict__ outp) {
    int t = blockIdx.x;
    const float* r = in + (size_t)t * DIM;
    float ss = 0.f;
    float vals[8];
    #pragma unroll
    for (int j = 0; j < 8; j++) {
        float v = r[threadIdx.x + j * 256];
        vals[j] = v; ss += v * v;
    }
    __shared__ float sred[8];
    for (int o = 16; o; o >>= 1) ss += __shfl_xor_sync(0xffffffffu, ss, o);
    if ((threadIdx.x & 31) == 0) sred[threadIdx.x >> 5] = ss;
    __syncthreads();
    float tot = 0.f;
    #pragma unroll
    for (int i = 0; i < 8; i++) tot += sred[i];
    float scale = rsqrtf(tot / (float)DIM + EPS_F);
    #pragma unroll
    for (int j = 0; j < 8; j++)
        outp[(size_t)t * DIM + threadIdx.x + j * 256] = __float2half_rn(vals[j] * scale);
}

// ---------------- gates v2: tiled, low weight traffic ----------------
__global__ void __launch_bounds__(256) gates2_kernel(
    const __half* __restrict__ xn, const float* __restrict__ agw,
    const float* __restrict__ vgw, float* __restrict__ agate,
    float* __restrict__ vgate)
{
    __shared__ __half xs[16][520];
    int t0 = blockIdx.x * 16;
    int t = threadIdx.x & 15, og = threadIdx.x >> 4;
    float acc0 = 0.f, acc1 = 0.f;
    for (int kc = 0; kc < 4; kc++) {
        #pragma unroll
        for (int i = 0; i < 4; i++) {
            int c = threadIdx.x + i * 256;
            int r = c >> 6, co = c & 63;
            *(uint4*)&xs[r][co * 8] =
                *(const uint4*)&xn[(size_t)(t0 + r) * DIM + kc * 512 + co * 8];
        }
        __syncthreads();
        const float* wa = agw + (size_t)og * DIM + kc * 512;
        const float* wv = vgw + (size_t)og * DIM + kc * 512;
        #pragma unroll 8
        for (int kk = 0; kk < 512; kk++) {
            float xv = __half2float(xs[t][kk]);
            acc0 = fmaf(xv, wa[kk], acc0);
            acc1 = fmaf(xv, wv[kk], acc1);
        }
        __syncthreads();
    }
    agate[(t0 + t) * NH + og] = 1.f / (1.f + expf(-acc0));
    vgate[(t0 + t) * NH + og] = 1.f / (1.f + expf(-acc1));
}

// ---------------- fused QKV post-processing: one warp per (t, slot 0..47) ----------------
// slot 0..15:  q rmsnorm+rotary -> qh
// slot 16..31: k rmsnorm+rotary -> kh with SCATTER key-offset shift
//              (low quarters -> kh[t]; high quarters -> kh[t+1], and also kh[0] when t==0)
// slot 32..47: v + vgate*ve -> vh
__global__ void __launch_bounds__(256) qkvpost_kernel(
    const float* __restrict__ qkv, __half* __restrict__ qh,
    __half* __restrict__ kh, __half* __restrict__ vh,
    const float* __restrict__ ve, const float* __restrict__ vgate,
    const float* __restrict__ cosb, const float* __restrict__ sinb,
    const int* __restrict__ key_offset)
{
    int gw = blockIdx.x * 8 + (threadIdx.x >> 5);
    int lane = threadIdx.x & 31;
    int hs = gw % 48;
    int t  = gw / 48;
    int d0 = lane * 4;

    if (hs >= 32) {
        // ---- v update ----
        int h = hs - 32;
        float4 v = *(const float4*)&qkv[((size_t)t * 48 + hs) * HD + d0];
        float4 e = *(const float4*)&ve[((size_t)t * NH + h) * HD + d0];
        float gv = vgate[t * NH + h];
        uint2 hv;
        hv.x = pack2h(v.x + gv * e.x, v.y + gv * e.y);
        hv.y = pack2h(v.z + gv * e.z, v.w + gv * e.w);
        *(uint2*)&vh[((size_t)t * NH + h) * HD + d0] = hv;
        return;
    }

    // ---- q/k rmsnorm + rotary ----
    float4 v = *(const float4*)&qkv[((size_t)t * 48 + hs) * HD + d0];
    float ss = v.x * v.x + v.y * v.y + v.z * v.z + v.w * v.w;
    #pragma unroll
    for (int o = 16; o; o >>= 1) ss += __shfl_xor_sync(0xffffffffu, ss, o);
    float sc = rsqrtf(ss / (float)HD + EPS_F);
    v.x *= sc; v.y *= sc; v.z *= sc; v.w *= sc;

    float px = __shfl_xor_sync(0xffffffffu, v.x, 16);
    float py = __shfl_xor_sync(0xffffffffu, v.y, 16);
    float pz = __shfl_xor_sync(0xffffffffu, v.z, 16);
    float pw = __shfl_xor_sync(0xffffffffu, v.w, 16);

    int ci = t * 64 + (d0 & 63);
    float4 c = *(const float4*)&cosb[ci];
    float4 s = *(const float4*)&sinb[ci];
    float4 o4;
    if (lane < 16) {
        o4.x = v.x * c.x + px * s.x;
        o4.y = v.y * c.y + py * s.y;
        o4.z = v.z * c.z + pz * s.z;
        o4.w = v.w * c.w + pw * s.w;
    } else {
        o4.x = -px * s.x + v.x * c.x;
        o4.y = -py * s.y + v.y * c.y;
        o4.z = -pz * s.z + v.z * c.z;
        o4.w = -pw * s.w + v.w * c.w;
    }
    uint2 hv;
    hv.x = pack2h(o4.x, o4.y);
    hv.y = pack2h(o4.z, o4.w);

    if (hs < 16) {
        *(uint2*)&qh[((size_t)t * NH + hs) * HD + d0] = hv;
    } else {
        int h = hs - 16;
        int ko = key_offset[0];
        // "up" = channels [32,64) U [96,128)  (the shifted quarters)
        bool up = ((d0 & 64) ? (d0 & 32) : (d0 & 32));   // d in quarter 1 or 3
        up = ((d0 >> 5) & 1) != 0;                       // quarters 1 and 3 have bit5 set
        if (!ko) {
            *(uint2*)&kh[((size_t)t * NH + h) * HD + d0] = hv;
        } else if (!up) {
            *(uint2*)&kh[((size_t)t * NH + h) * HD + d0] = hv;
        } else {
            if (t + 1 < T_SEQ)
                *(uint2*)&kh[((size_t)(t + 1) * NH + h) * HD + d0] = hv;
            if (t == 0)
                *(uint2*)&kh[((size_t)0 * NH + h) * HD + d0] = hv;
        }
    }
}

// ================= fp16 MMA flash attention =================
#define FROW 136
#define FL_SMEM (3 * 64 * FROW * 2 + 256)

__global__ void __launch_bounds__(128) flash_mma_kernel(
    const __half* __restrict__ qh, const __half* __restrict__ kh,
    const __half* __restrict__ vh, const int* __restrict__ docs,
    const float* __restrict__ attn_scale, const float* __restrict__ agate,
    __half* __restrict__ y)
{
    extern __shared__ __half fh[];
    __half* Qs = fh;
    __half* Ks = fh + 64 * FROW;
    __half* Vs = fh + 2 * 64 * FROW;
    int*    kd = (int*)(fh + 3 * 64 * FROW);

    const int tid = threadIdx.x, wid = tid >> 5, lane = tid & 31;
    const int g = lane >> 2, tig = lane & 3;
    const int h = blockIdx.y;
    const int qi = (int)gridDim.x - 1 - (int)blockIdx.x;
    const int qbase = qi * 64;
    const float scale = attn_scale[0];

    #pragma unroll
    for (int i = 0; i < 8; i++) {
        int c = tid + i * 128;
        int r = c >> 4, co = c & 15;
        *(uint4*)&Qs[r * FROW + co * 8] =
            *(const uint4*)&qh[((size_t)(qbase + r) * NH + h) * HD + co * 8];
    }
    const int rg0 = qbase + wid * 16 + g;
    const int rg1 = rg0 + 8;
    const int qd0 = docs[rg0], qd1 = docs[rg1];
    const int qdmin = docs[qbase];

    const uint32_t sQ = smem_u32(Qs), sK = smem_u32(Ks), sV = smem_u32(Vs);
    const uint32_t qoff = (uint32_t)(wid * 16 + (lane & 7) + ((lane >> 3) & 1) * 8) * (FROW * 2)
                        + ((lane >> 4) & 1) * 16;
    uint32_t koff[4], voff[8];
    #pragma unroll
    for (int nb = 0; nb < 4; nb++)
        koff[nb] = (uint32_t)(nb * 16 + (lane & 7) + ((lane >> 4) & 1) * 8) * (FROW * 2)
                 + ((lane >> 3) & 1) * 16;
    #pragma unroll
    for (int nb = 0; nb < 8; nb++)
        voff[nb] = (uint32_t)((lane & 7) + ((lane >> 3) & 1) * 8) * (FROW * 2)
                 + nb * 32 + ((lane >> 4) & 1) * 16;

    float o[16][4] = {};
    float m0 = NEG_INF_F, m1 = NEG_INF_F, l0 = 0.f, l1 = 0.f;
    __syncthreads();

    for (int kb = 0; kb <= qi; kb++) {
        const int kbase = kb * 64;
        if (docs[kbase + 63] < qdmin) continue;
        __syncthreads();
        #pragma unroll
        for (int i = 0; i < 8; i++) {
            int c = tid + i * 128;
            int r = c >> 4, co = c & 15;
            *(uint4*)&Ks[r * FROW + co * 8] =
                *(const uint4*)&kh[((size_t)(kbase + r) * NH + h) * HD + co * 8];
            *(uint4*)&Vs[r * FROW + co * 8] =
                *(const uint4*)&vh[((size_t)(kbase + r) * NH + h) * HD + co * 8];
        }
        if (tid < 64) kd[tid] = docs[kbase + tid];
        __syncthreads();

        float s[8][4] = {};
        #pragma unroll
        for (int ks = 0; ks < 8; ks++) {
            uint32_t a0, a1, a2, a3;
            ldsm_x4(a0, a1, a2, a3, sQ + qoff + ks * 32);
            #pragma unroll
            for (int nb = 0; nb < 4; nb++) {
                uint32_t b0, b1, b2, b3;
                ldsm_x4(b0, b1, b2, b3, sK + koff[nb] + ks * 32);
                mma_f16(s[2 * nb][0], s[2 * nb][1], s[2 * nb][2], s[2 * nb][3],
                        a0, a1, a2, a3, b0, b1);
                mma_f16(s[2 * nb + 1][0], s[2 * nb + 1][1], s[2 * nb + 1][2], s[2 * nb + 1][3],
                        a0, a1, a2, a3, b2, b3);
            }
        }

        float mx0 = m0, mx1 = m1;
        #pragma unroll
        for (int nt = 0; nt < 8; nt++) {
            int c0i = kbase + nt * 8 + 2 * tig;
            int d0 = kd[nt * 8 + 2 * tig], d1 = kd[nt * 8 + 2 * tig + 1];
            float v00 = (c0i     <= rg0 && d0 == qd0) ? s[nt][0] * scale : NEG_INF_F;
            float v01 = (c0i + 1 <= rg0 && d1 == qd0) ? s[nt][1] * scale : NEG_INF_F;
            float v10 = (c0i     <= rg1 && d0 == qd1) ? s[nt][2] * scale : NEG_INF_F;
            float v11 = (c0i + 1 <= rg1 && d1 == qd1) ? s[nt][3] * scale : NEG_INF_F;
            s[nt][0] = v00; s[nt][1] = v01; s[nt][2] = v10; s[nt][3] = v11;
            mx0 = fmaxf(mx0, fmaxf(v00, v01));
            mx1 = fmaxf(mx1, fmaxf(v10, v11));
        }
        mx0 = fmaxf(mx0, __shfl_xor_sync(0xffffffffu, mx0, 1));
        mx0 = fmaxf(mx0, __shfl_xor_sync(0xffffffffu, mx0, 2));
        mx1 = fmaxf(mx1, __shfl_xor_sync(0xffffffffu, mx1, 1));
        mx1 = fmaxf(mx1, __shfl_xor_sync(0xffffffffu, mx1, 2));
        float al0 = __expf(m0 - mx0), al1 = __expf(m1 - mx1);
        m0 = mx0; m1 = mx1;

        float sum0 = 0.f, sum1 = 0.f;
        #pragma unroll
        for (int nt = 0; nt < 8; nt++) {
            s[nt][0] = __expf(s[nt][0] - m0);
            s[nt][1] = __expf(s[nt][1] - m0);
            s[nt][2] = __expf(s[nt][2] - m1);
            s[nt][3] = __expf(s[nt][3] - m1);
            sum0 += s[nt][0] + s[nt][1];
            sum1 += s[nt][2] + s[nt][3];
        }
        sum0 += __shfl_xor_sync(0xffffffffu, sum0, 1);
        sum0 += __shfl_xor_sync(0xffffffffu, sum0, 2);
        sum1 += __shfl_xor_sync(0xffffffffu, sum1, 1);
        sum1 += __shfl_xor_sync(0xffffffffu, sum1, 2);
        l0 = l0 * al0 + sum0;
        l1 = l1 * al1 + sum1;
        #pragma unroll
        for (int nt = 0; nt < 16; nt++) {
            o[nt][0] *= al0; o[nt][1] *= al0;
            o[nt][2] *= al1; o[nt][3] *= al1;
        }

        uint32_t pa[4][4];
        #pragma unroll
        for (int kc = 0; kc < 4; kc++) {
            pa[kc][0] = pack2h(s[2 * kc][0], s[2 * kc][1]);
            pa[kc][1] = pack2h(s[2 * kc][2], s[2 * kc][3]);
            pa[kc][2] = pack2h(s[2 * kc + 1][0], s[2 * kc + 1][1]);
            pa[kc][3] = pack2h(s[2 * kc + 1][2], s[2 * kc + 1][3]);
        }
        #pragma unroll
        for (int kc = 0; kc < 4; kc++) {
            #pragma unroll
            for (int nb = 0; nb < 8; nb++) {
                uint32_t b0, b1, b2, b3;
                ldsm_x4_t(b0, b1, b2, b3, sV + voff[nb] + kc * 16 * (FROW * 2));
                mma_f16(o[2 * nb][0], o[2 * nb][1], o[2 * nb][2], o[2 * nb][3],
                        pa[kc][0], pa[kc][1], pa[kc][2], pa[kc][3], b0, b1);
                mma_f16(o[2 * nb + 1][0], o[2 * nb + 1][1], o[2 * nb + 1][2], o[2 * nb + 1][3],
                        pa[kc][0], pa[kc][1], pa[kc][2], pa[kc][3], b2, b3);
            }
        }
    }

    float f0 = (1.f / l0) * agate[rg0 * NH + h];
    float f1 = (1.f / l1) * agate[rg1 * NH + h];
    #pragma unroll
    for (int nt = 0; nt < 16; nt++) {
        *(__half2*)&y[(size_t)rg0 * DIM + h * HD + nt * 8 + 2 * tig] =
            __floats2half2_rn(o[nt][0] * f0, o[nt][1] * f0);
        *(__half2*)&y[(size_t)rg1 * DIM + h * HD + nt * 8 + 2 * tig] =
            __floats2half2_rn(o[nt][2] * f1, o[nt][3] * f1);
    }
}

// ---------------- launch ----------------
extern "C" void kernel_launch(void* const* d_in, const int* in_sizes, int n_in,
                              void* d_out, int out_size) {
    const float* x           = (const float*)d_in[0];
    const float* ve          = (const float*)d_in[1];
    const float* qkvo_w      = (const float*)d_in[2];
    const float* attn_gate_w = (const float*)d_in[3];
    const float* ve_gate_w   = (const float*)d_in[4];
    const float* c_fc        = (const float*)d_in[5];
    const float* c_proj      = (const float*)d_in[6];
    const float* sa_lambdas  = (const float*)d_in[7];
    const float* cosb        = (const float*)d_in[8];
    const float* sinb        = (const float*)d_in[9];
    const float* attn_scale  = (const float*)d_in[10];
    const int*   docs        = (const int*)d_in[11];
    const int*   key_offset  = (const int*)d_in[12];
    float*       out         = (float*)d_out;

    __half *xn, *qhp, *khp, *vhp, *y, *hbuf;
    float *qkv, *x1, *agate, *vgate;
    cudaGetSymbolAddress((void**)&xn,    g_xn);
    cudaGetSymbolAddress((void**)&qkv,   g_qkv);
    cudaGetSymbolAddress((void**)&qhp,   g_qh);
    cudaGetSymbolAddress((void**)&khp,   g_kh);
    cudaGetSymbolAddress((void**)&vhp,   g_vh);
    cudaGetSymbolAddress((void**)&y,     g_y);
    cudaGetSymbolAddress((void**)&x1,    g_x1);
    cudaGetSymbolAddress((void**)&hbuf,  g_h);
    cudaGetSymbolAddress((void**)&agate, g_agate);
    cudaGetSymbolAddress((void**)&vgate, g_vgate);

    cudaFuncSetAttribute(flash_mma_kernel, cudaFuncAttributeMaxDynamicSharedMemorySize,
                         FL_SMEM);
    cudaFuncSetAttribute((const void*)f16_gemm_kernel<0,1>,
                         cudaFuncAttributeMaxDynamicSharedMemorySize, GEMM_SMEM);
    cudaFuncSetAttribute((const void*)f16_gemm_kernel<1,1>,
                         cudaFuncAttributeMaxDynamicSharedMemorySize, GEMM_SMEM);
    cudaFuncSetAttribute((const void*)f16_gemm_kernel<2,1>,
                         cudaFuncAttributeMaxDynamicSharedMemorySize, GEMM_SMEM);
    cudaFuncSetAttribute((const void*)f16_gemm_kernel<2,0>,
                         cudaFuncAttributeMaxDynamicSharedMemorySize, GEMM_SMEM);

    // 1. xn = fp16(rmsnorm(x))
    rmsnorm_kernel<<<T_SEQ, 256>>>(x, xn);
    // 2. gate logits
    gates2_kernel<<<T_SEQ / 16, 256>>>(xn, attn_gate_w, ve_gate_w, agate, vgate);
    // 3. qkv = lam0 * xn @ Wqkv^T  (B fp32, converted in-kernel)
    f16_gemm_kernel<0,1><<<dim3(3 * DIM / GBN, T_SEQ / GBM), 512, GEMM_SMEM>>>(
        xn, qkvo_w, qkv, nullptr, sa_lambdas, 0, 3 * DIM, DIM);
    // 4. fused QKV post (q/k rmsnorm+rotary with scatter shift, v update)
    qkvpost_kernel<<<(T_SEQ * 48) / 8, 256>>>(
        qkv, qhp, khp, vhp, ve, vgate, cosb, sinb, key_offset);
    // 5. fp16 MMA flash attention -> y (fp16)
    flash_mma_kernel<<<dim3(T_SEQ / 64, NH), 128, FL_SMEM>>>(
        qhp, khp, vhp, docs, attn_scale, agate, y);
    // 6. x1 = x + lam1 * y @ Wo^T
    f16_gemm_kernel<2,1><<<dim3(DIM / GBN, T_SEQ / GBM), 512, GEMM_SMEM>>>(
        y, qkvo_w + (size_t)3 * DIM * DIM, x1, x, sa_lambdas, 1, DIM, DIM);
    // 7. xn = fp16(rmsnorm(x1))
    rmsnorm_kernel<<<T_SEQ, 256>>>(x1, xn);
    // 8. h = fp16(relu(xn @ c_fc^T)^2)
    f16_gemm_kernel<1,1><<<dim3(FFN / GBN, T_SEQ / GBM), 512, GEMM_SMEM>>>(
        xn, c_fc, hbuf, nullptr, nullptr, 0, FFN, DIM);
    // 9. out = x1 + h @ c_proj  (B native [K,N] fp32, trans-ldmatrix path)
    f16_gemm_kernel<2,0><<<dim3(DIM / GBN, T_SEQ / GBM), 512, GEMM_SMEM>>>(
        hbuf, c_proj, out, x1, nullptr, 0, DIM, FFN);
}